// round 3
// baseline (speedup 1.0000x reference)
#include <cuda_runtime.h>
#include <math.h>

// Problem dims
#define Bn 1024
#define Tn 64
#define Dn 256
#define Pn 2048
#define Hn 512

#define THRESHOLD 0.3f
#define STRENGTH 0.1f
#define MIN_S 0.0f
#define MAX_S 0.5f
#define EPS_COS 1e-8f
#define EPS_LN 1e-5f

// ---------------- scratch (static device globals; no allocations) -------------
__device__ float g_centers[Pn * Dn];       // proto centers [P,D]
__device__ float g_ncT[Dn * Pn];           // normalized centers, transposed [D,P]
__device__ float g_nf[Bn * Dn];            // normalized feat rows [B,D]
__device__ float g_fcent[Bn * Dn];         // feat_flat (unnormalized) [B,D]
__device__ float g_gm[Dn];                 // global mean [D]
__device__ float g_drift[Bn * Pn];         // fallback drift buffer
__device__ float g_flag[Pn];               // is_drifted as 0/1 float
__device__ float g_concat[Pn * 2 * Dn];    // [P, 2D]
__device__ float g_z1[Pn * Hn];
__device__ float g_a1[Pn * Hn];
__device__ float g_h2[Pn * (Hn / 2)];
__device__ float g_conf[Pn];
__device__ float g_z2[Pn * Hn];
__device__ float g_a2[Pn * Hn];
__device__ float g_c2[Pn * Hn];
__device__ float g_delta[Pn * Dn];
__device__ float g_newc[Pn * Dn];

// ---------------- kernels ----------------------------------------------------

// One block per prototype p: centers[p][d] = mean_t proto[p][t][d],
// also compute ||center|| and write normalized transposed copy for the sim GEMM.
__global__ void __launch_bounds__(Dn) proto_centers_kernel(const float* __restrict__ proto) {
    int p = blockIdx.x;
    int d = threadIdx.x;
    const float* base = proto + (size_t)p * Tn * Dn + d;
    float s = 0.f;
#pragma unroll 16
    for (int t = 0; t < Tn; t++) s += base[t * Dn];
    float c = s * (1.0f / Tn);

    __shared__ float red[Dn];
    red[d] = c * c;
    __syncthreads();
    for (int o = Dn / 2; o > 0; o >>= 1) {
        if (d < o) red[d] += red[d + o];
        __syncthreads();
    }
    float pnrm = fmaxf(sqrtf(red[0]), EPS_COS);
    g_centers[p * Dn + d] = c;
    g_ncT[(size_t)d * Pn + p] = c / pnrm;
}

// One block per batch row b: feat_flat + normalized copy.
__global__ void __launch_bounds__(Dn) feat_kernel(const float* __restrict__ feat) {
    int b = blockIdx.x;
    int d = threadIdx.x;
    const float* base = feat + (size_t)b * Tn * Dn + d;
    float s = 0.f;
#pragma unroll 16
    for (int t = 0; t < Tn; t++) s += base[t * Dn];
    float c = s * (1.0f / Tn);

    __shared__ float red[Dn];
    red[d] = c * c;
    __syncthreads();
    for (int o = Dn / 2; o > 0; o >>= 1) {
        if (d < o) red[d] += red[d + o];
        __syncthreads();
    }
    float fnrm = fmaxf(sqrtf(red[0]), EPS_COS);
    g_fcent[b * Dn + d] = c;
    g_nf[b * Dn + d] = c / fnrm;
}

// global_mean over B (deterministic, single block, coalesced across threads)
__global__ void __launch_bounds__(Dn) gm_kernel() {
    int d = threadIdx.x;
    float s = 0.f;
#pragma unroll 8
    for (int b = 0; b < Bn; b++) s += g_fcent[b * Dn + d];
    g_gm[d] = s * (1.0f / Bn);
}

// ---- generic SGEMM: C[M,N] = act(A[M,K] @ W[K,N] + bias)
// act: 0 = bias only, 1 = relu(bias), 2 = (1 - acc), no bias  (drift score)
#define BM 64
#define BN 64
#define BKx 16
__global__ void __launch_bounds__(256) gemm_kernel(
    const float* __restrict__ A, const float* __restrict__ W,
    const float* __restrict__ bias, float* __restrict__ C,
    int M, int N, int K, int act)
{
    __shared__ __align__(16) float As[BKx][BM + 4];   // transposed A tile, padded
    __shared__ __align__(16) float Ws[BKx][BN];

    int t = threadIdx.x;
    int tx = t & 15, ty = t >> 4;
    int m0 = blockIdx.y * BM, n0 = blockIdx.x * BN;

    int rowA = t >> 2;            // 0..63
    int cgA  = (t & 3) * 4;       // 0,4,8,12
    int rowW = t >> 4;            // 0..15
    int cgW  = (t & 15) * 4;      // 0..60

    const float* Ap = A + (size_t)(m0 + rowA) * K + cgA;
    const float* Wp = W + (size_t)rowW * N + n0 + cgW;

    float acc[4][4] = {};

    float4 av = *(const float4*)Ap;
    float4 wv = *(const float4*)Wp;

    for (int k0 = 0; k0 < K; k0 += BKx) {
        __syncthreads();
        As[cgA + 0][rowA] = av.x;
        As[cgA + 1][rowA] = av.y;
        As[cgA + 2][rowA] = av.z;
        As[cgA + 3][rowA] = av.w;
        *(float4*)&Ws[rowW][cgW] = wv;
        __syncthreads();

        if (k0 + BKx < K) {
            av = *(const float4*)(Ap + k0 + BKx);
            wv = *(const float4*)(Wp + (size_t)(k0 + BKx) * N);
        }

#pragma unroll
        for (int k = 0; k < BKx; k++) {
            float4 a = *(const float4*)&As[k][ty * 4];
            float4 b = *(const float4*)&Ws[k][tx * 4];
            acc[0][0] += a.x * b.x; acc[0][1] += a.x * b.y; acc[0][2] += a.x * b.z; acc[0][3] += a.x * b.w;
            acc[1][0] += a.y * b.x; acc[1][1] += a.y * b.y; acc[1][2] += a.y * b.z; acc[1][3] += a.y * b.w;
            acc[2][0] += a.z * b.x; acc[2][1] += a.z * b.y; acc[2][2] += a.z * b.z; acc[2][3] += a.z * b.w;
            acc[3][0] += a.w * b.x; acc[3][1] += a.w * b.y; acc[3][2] += a.w * b.z; acc[3][3] += a.w * b.w;
        }
    }

    int m = m0 + ty * 4, n = n0 + tx * 4;
    float4 bv = make_float4(0.f, 0.f, 0.f, 0.f);
    if (act != 2) bv = *(const float4*)&bias[n];

#pragma unroll
    for (int i = 0; i < 4; i++) {
        float4 v;
        if (act == 2) {
            v.x = 1.0f - acc[i][0]; v.y = 1.0f - acc[i][1];
            v.z = 1.0f - acc[i][2]; v.w = 1.0f - acc[i][3];
        } else {
            v.x = acc[i][0] + bv.x; v.y = acc[i][1] + bv.y;
            v.z = acc[i][2] + bv.z; v.w = acc[i][3] + bv.w;
            if (act == 1) {
                v.x = fmaxf(v.x, 0.f); v.y = fmaxf(v.y, 0.f);
                v.z = fmaxf(v.z, 0.f); v.w = fmaxf(v.w, 0.f);
            }
        }
        *(float4*)&C[(size_t)(m + i) * N + n] = v;
    }
}

// mean over B of drift column p, threshold -> flag
__global__ void __launch_bounds__(256) colmean_kernel(const float* __restrict__ drift,
                                                      float* __restrict__ out_flag) {
    int p = blockIdx.x * 256 + threadIdx.x;
    if (p >= Pn) return;
    float s = 0.f;
#pragma unroll 8
    for (int b = 0; b < Bn; b++) s += drift[(size_t)b * Pn + p];
    float fl = (s * (1.0f / Bn) > THRESHOLD) ? 1.0f : 0.0f;
    g_flag[p] = fl;
    if (out_flag) out_flag[p] = fl;
}

// build [centers | global_mean] concat
__global__ void __launch_bounds__(256) concat_kernel() {
    int i = blockIdx.x * 256 + threadIdx.x;   // P * 2D
    int p = i >> 9;
    int j = i & 511;
    g_concat[i] = (j < Dn) ? g_centers[(p << 8) + j] : g_gm[j - Dn];
}

// layernorm + relu over rows of width H=512 (256 threads, 2 elems/thread)
__global__ void __launch_bounds__(256) ln_relu_kernel(const float* __restrict__ z,
                                                      const float* __restrict__ g,
                                                      const float* __restrict__ be,
                                                      float* __restrict__ out) {
    int r = blockIdx.x;
    int d = threadIdx.x;
    const float* row = z + (size_t)r * Hn;
    float v0 = row[d], v1 = row[d + 256];

    __shared__ float red[256];
    red[d] = v0 + v1;
    __syncthreads();
    for (int o = 128; o > 0; o >>= 1) {
        if (d < o) red[d] += red[d + o];
        __syncthreads();
    }
    float mu = red[0] * (1.0f / Hn);
    __syncthreads();

    float d0 = v0 - mu, d1 = v1 - mu;
    red[d] = d0 * d0 + d1 * d1;
    __syncthreads();
    for (int o = 128; o > 0; o >>= 1) {
        if (d < o) red[d] += red[d + o];
        __syncthreads();
    }
    float var = red[0] * (1.0f / Hn);
    float rs = rsqrtf(var + EPS_LN);

    float* orow = out + (size_t)r * Hn;
    orow[d]       = fmaxf(d0 * rs * g[d] + be[d], 0.f);
    orow[d + 256] = fmaxf(d1 * rs * g[d + 256] + be[d + 256], 0.f);
}

// conf[p] = sigmoid(dot(h2[p], w3) + b3)
__global__ void __launch_bounds__(256) gemv_sig_kernel(const float* __restrict__ w3,
                                                       const float* __restrict__ b3) {
    int p = blockIdx.x;
    int d = threadIdx.x;
    float s = g_h2[(size_t)p * (Hn / 2) + d] * w3[d];
    __shared__ float red[256];
    red[d] = s;
    __syncthreads();
    for (int o = 128; o > 0; o >>= 1) {
        if (d < o) red[d] += red[d + o];
        __syncthreads();
    }
    if (d == 0) {
        float x = red[0] + b3[0];
        g_conf[p] = 1.0f / (1.0f + expf(-x));
    }
}

// new_center = centers + clip(0.1*conf,0,0.5)*delta
__global__ void __launch_bounds__(256) newc_kernel() {
    int i = blockIdx.x * 256 + threadIdx.x;   // P*D
    int p = i >> 8;
    float s = fminf(fmaxf(STRENGTH * g_conf[p], MIN_S), MAX_S);
    g_newc[i] = g_centers[i] + s * g_delta[i];
}

// calibrated[p][t][d] = flag[p] ? new_center[p][d] : prototype[p][t][d]  (float4)
__global__ void __launch_bounds__(256) scatter_kernel(const float* __restrict__ proto,
                                                      float* __restrict__ out) {
    int i = blockIdx.x * 256 + threadIdx.x;   // in float4 units; total P*T*D/4
    int p = i >> 12;            // T*D/4 = 4096
    int r = i & 4095;
    int d4 = r & 63;            // D/4 = 64
    float4 v;
    if (g_flag[p] > 0.5f) {
        v = ((const float4*)g_newc)[(p << 6) + d4];
    } else {
        v = ((const float4*)proto)[i];
    }
    ((float4*)out)[i] = v;
}

// ---------------- launch ------------------------------------------------------
extern "C" void kernel_launch(void* const* d_in, const int* in_sizes, int n_in,
                              void* d_out, int out_size) {
    (void)in_sizes; (void)n_in;
    const float* feat   = (const float*)d_in[0];
    const float* proto  = (const float*)d_in[1];
    const float* dd_w1  = (const float*)d_in[2];
    const float* dd_b1  = (const float*)d_in[3];
    const float* dd_g1  = (const float*)d_in[4];
    const float* dd_be1 = (const float*)d_in[5];
    const float* dd_w2  = (const float*)d_in[6];
    const float* dd_b2  = (const float*)d_in[7];
    const float* dd_w3  = (const float*)d_in[8];
    const float* dd_b3  = (const float*)d_in[9];
    const float* cal_w1 = (const float*)d_in[10];
    const float* cal_b1 = (const float*)d_in[11];
    const float* cal_g1 = (const float*)d_in[12];
    const float* cal_be1= (const float*)d_in[13];
    const float* cal_w2 = (const float*)d_in[14];
    const float* cal_b2 = (const float*)d_in[15];
    const float* cal_w3 = (const float*)d_in[16];
    const float* cal_b3 = (const float*)d_in[17];

    float* out = (float*)d_out;
    const long long PTD = (long long)Pn * Tn * Dn;       // 33,554,432
    const long long BP  = (long long)Bn * Pn;            //  2,097,152

    bool has_drift = (long long)out_size >= PTD + BP;
    bool has_flag  = (long long)out_size >= PTD + BP + Pn;

    float* drift_ptr = nullptr;
    if (has_drift) {
        drift_ptr = out + PTD;
    } else {
        cudaGetSymbolAddress((void**)&drift_ptr, g_drift);
    }
    float* flag_ptr = has_flag ? (out + PTD + BP) : nullptr;

    // symbol addresses for GEMM operands
    float *p_centers, *p_ncT, *p_nf, *p_concat, *p_z1, *p_a1, *p_h2, *p_z2, *p_a2, *p_c2, *p_delta;
    cudaGetSymbolAddress((void**)&p_centers, g_centers);
    cudaGetSymbolAddress((void**)&p_ncT,     g_ncT);
    cudaGetSymbolAddress((void**)&p_nf,      g_nf);
    cudaGetSymbolAddress((void**)&p_concat,  g_concat);
    cudaGetSymbolAddress((void**)&p_z1,      g_z1);
    cudaGetSymbolAddress((void**)&p_a1,      g_a1);
    cudaGetSymbolAddress((void**)&p_h2,      g_h2);
    cudaGetSymbolAddress((void**)&p_z2,      g_z2);
    cudaGetSymbolAddress((void**)&p_a2,      g_a2);
    cudaGetSymbolAddress((void**)&p_c2,      g_c2);
    cudaGetSymbolAddress((void**)&p_delta,   g_delta);

    // 1-2: reductions
    proto_centers_kernel<<<Pn, Dn>>>(proto);
    feat_kernel<<<Bn, Dn>>>(feat);
    gm_kernel<<<1, Dn>>>();

    // 3: drift score GEMM  [B,P] = 1 - nf @ ncT
    gemm_kernel<<<dim3(Pn / BN, Bn / BM), 256>>>(p_nf, p_ncT, nullptr, drift_ptr,
                                                 Bn, Pn, Dn, 2);

    // 4: column mean -> is_drifted
    colmean_kernel<<<Pn / 256, 256>>>(drift_ptr, flag_ptr);

    // 5: concat [centers | gm]
    concat_kernel<<<(Pn * 2 * Dn) / 256, 256>>>();

    // 6-8: drift-detector MLP
    gemm_kernel<<<dim3(Hn / BN, Pn / BM), 256>>>(p_concat, dd_w1, dd_b1, p_z1,
                                                 Pn, Hn, 2 * Dn, 0);
    ln_relu_kernel<<<Pn, 256>>>(p_z1, dd_g1, dd_be1, p_a1);
    gemm_kernel<<<dim3((Hn / 2) / BN, Pn / BM), 256>>>(p_a1, dd_w2, dd_b2, p_h2,
                                                       Pn, Hn / 2, Hn, 1);
    gemv_sig_kernel<<<Pn, 256>>>(dd_w3, dd_b3);

    // 9-11: calibration MLP
    gemm_kernel<<<dim3(Hn / BN, Pn / BM), 256>>>(p_centers, cal_w1, cal_b1, p_z2,
                                                 Pn, Hn, Dn, 0);
    ln_relu_kernel<<<Pn, 256>>>(p_z2, cal_g1, cal_be1, p_a2);
    gemm_kernel<<<dim3(Hn / BN, Pn / BM), 256>>>(p_a2, cal_w2, cal_b2, p_c2,
                                                 Pn, Hn, Hn, 1);
    gemm_kernel<<<dim3(Dn / BN, Pn / BM), 256>>>(p_c2, cal_w3, cal_b3, p_delta,
                                                 Pn, Dn, Hn, 0);

    // 12: new centers
    newc_kernel<<<(Pn * Dn) / 256, 256>>>();

    // 13: scatter calibrated output
    scatter_kernel<<<(int)(PTD / 4 / 256), 256>>>(proto, out);
}

// round 5
// speedup vs baseline: 1.1096x; 1.1096x over previous
#include <cuda_runtime.h>
#include <math.h>

// Problem dims
#define Bn 1024
#define Tn 64
#define Dn 256
#define Pn 2048
#define Hn 512

#define THRESHOLD 0.3f
#define STRENGTH 0.1f
#define MIN_S 0.0f
#define MAX_S 0.5f
#define EPS_COS 1e-8f
#define EPS_LN 1e-5f

// ---------------- scratch (static device globals; no allocations) -------------
__device__ float g_centers[Pn * Dn];       // proto centers [P,D]
__device__ float g_ncT[Dn * Pn];           // normalized centers, transposed [D,P]
__device__ float g_nf[Bn * Dn];            // normalized feat rows [B,D]
__device__ float g_fcent[Bn * Dn];         // feat_flat (unnormalized) [B,D]
__device__ float g_gmp[8][Dn];             // partial global mean
__device__ float g_drift[Bn * Pn];         // fallback drift buffer
__device__ float g_flag[Pn];               // is_drifted as 0/1 float
__device__ float g_concat[Pn * 2 * Dn];    // [P, 2D]
__device__ float g_z1[Pn * Hn];
__device__ float g_a1[Pn * Hn];
__device__ float g_h2[Pn * (Hn / 2)];
__device__ float g_conf[Pn];
__device__ float g_z2[Pn * Hn];
__device__ float g_a2[Pn * Hn];
__device__ float g_c2[Pn * Hn];
__device__ float g_delta[Pn * Dn];
__device__ float g_newc[Pn * Dn];

// ---------------- fused T-mean reductions (proto + feat in one launch) --------
__global__ void __launch_bounds__(Dn) reduce_centers_kernel(
    const float* __restrict__ proto, const float* __restrict__ feat)
{
    int blk = blockIdx.x;
    int d = threadIdx.x;
    bool isP = blk < Pn;
    int row = isP ? blk : (blk - Pn);
    const float* base = (isP ? proto : feat) + (size_t)row * Tn * Dn + d;
    float s = 0.f;
#pragma unroll 16
    for (int t = 0; t < Tn; t++) s += base[t * Dn];
    float c = s * (1.0f / Tn);

    __shared__ float red[Dn];
    red[d] = c * c;
    __syncthreads();
    for (int o = Dn / 2; o > 0; o >>= 1) {
        if (d < o) red[d] += red[d + o];
        __syncthreads();
    }
    float nrm = fmaxf(sqrtf(red[0]), EPS_COS);
    if (isP) {
        g_centers[row * Dn + d] = c;
        g_ncT[(size_t)d * Pn + row] = c / nrm;
    } else {
        g_fcent[row * Dn + d] = c;
        g_nf[row * Dn + d] = c / nrm;
    }
}

// partial global_mean over B: 8 blocks, each sums 128 rows
__global__ void __launch_bounds__(Dn) gm_partial_kernel() {
    int i = blockIdx.x;
    int d = threadIdx.x;
    float s = 0.f;
    int b0 = i * (Bn / 8);
#pragma unroll 8
    for (int b = 0; b < Bn / 8; b++) s += g_fcent[(b0 + b) * Dn + d];
    g_gmp[i][d] = s;
}

// ---- templated double-buffered SGEMM: C[M,N] = act(A[M,K] @ W[K,N] + bias)
// ACT: 0 = bias, 1 = relu(bias), 2 = (1 - acc), no bias
template<int BM, int BN, int TM, int TN, int ACT, int NT>
__global__ void __launch_bounds__(NT) gemm_t(
    const float* __restrict__ A, const float* __restrict__ W,
    const float* __restrict__ bias, float* __restrict__ C,
    int M, int N, int K)
{
    constexpr int BK = 16;
    constexpr int PAD = 4;
    __shared__ __align__(16) float As[2][BK][BM + PAD];
    __shared__ __align__(16) float Ws[2][BK][BN];

    const int t = threadIdx.x;
    constexpr int TX = BN / TN;          // thread columns (groups of 4)
    const int tx = t % TX;
    const int ty = t / TX;

    const int m0 = blockIdx.y * BM;
    const int n0 = blockIdx.x * BN;

    constexpr int LA = (BM * BK) / (4 * NT);
    constexpr int LW = (BK * BN) / (4 * NT);
    constexpr int AR = NT / (BK / 4);    // A rows covered per load iter
    constexpr int WR = NT / (BN / 4);    // W rows covered per load iter
    const int rowA = t / (BK / 4);
    const int col4A = (t % (BK / 4)) * 4;
    const int rowW = t / (BN / 4);
    const int colW = (t % (BN / 4)) * 4;

    const float* Abase = A + (size_t)m0 * K;
    const float* Wbase = W + n0;

    float4 ra[LA], rw[LW];

    // prologue: load k-block 0
#pragma unroll
    for (int i = 0; i < LA; i++)
        ra[i] = *(const float4*)(Abase + (size_t)(rowA + i * AR) * K + col4A);
#pragma unroll
    for (int i = 0; i < LW; i++)
        rw[i] = *(const float4*)(Wbase + (size_t)(rowW + i * WR) * N + colW);

#pragma unroll
    for (int i = 0; i < LA; i++) {
        int r = rowA + i * AR;
        As[0][col4A + 0][r] = ra[i].x;
        As[0][col4A + 1][r] = ra[i].y;
        As[0][col4A + 2][r] = ra[i].z;
        As[0][col4A + 3][r] = ra[i].w;
    }
#pragma unroll
    for (int i = 0; i < LW; i++)
        *(float4*)&Ws[0][rowW + i * WR][colW] = rw[i];
    __syncthreads();

    float acc[TM][TN] = {};
    constexpr int MG = TM / 4;
    constexpr int NG = TN / 4;

    int s = 0;
    for (int k0 = 0; k0 < K; k0 += BK) {
        bool more = (k0 + BK) < K;
        if (more) {
            const float* An = Abase + k0 + BK;
#pragma unroll
            for (int i = 0; i < LA; i++)
                ra[i] = *(const float4*)(An + (size_t)(rowA + i * AR) * K + col4A);
            const float* Wn = Wbase + (size_t)(k0 + BK) * N;
#pragma unroll
            for (int i = 0; i < LW; i++)
                rw[i] = *(const float4*)(Wn + (size_t)(rowW + i * WR) * N + colW);
        }

#pragma unroll
        for (int k = 0; k < BK; k++) {
            float a[TM], b[TN];
            float4 av0 = *(const float4*)&As[s][k][ty * 4];
            a[0] = av0.x; a[1] = av0.y; a[2] = av0.z; a[3] = av0.w;
            if (MG > 1) {
                float4 av1 = *(const float4*)&As[s][k][BM / 2 + ty * 4];
                a[4] = av1.x; a[5] = av1.y; a[6] = av1.z; a[7] = av1.w;
            }
            float4 bv0 = *(const float4*)&Ws[s][k][tx * 4];
            b[0] = bv0.x; b[1] = bv0.y; b[2] = bv0.z; b[3] = bv0.w;
            if (NG > 1) {
                float4 bv1 = *(const float4*)&Ws[s][k][BN / 2 + tx * 4];
                b[4] = bv1.x; b[5] = bv1.y; b[6] = bv1.z; b[7] = bv1.w;
            }
#pragma unroll
            for (int i = 0; i < TM; i++)
#pragma unroll
                for (int j = 0; j < TN; j++)
                    acc[i][j] += a[i] * b[j];
        }

        if (more) {
            s ^= 1;
#pragma unroll
            for (int i = 0; i < LA; i++) {
                int r = rowA + i * AR;
                As[s][col4A + 0][r] = ra[i].x;
                As[s][col4A + 1][r] = ra[i].y;
                As[s][col4A + 2][r] = ra[i].z;
                As[s][col4A + 3][r] = ra[i].w;
            }
#pragma unroll
            for (int i = 0; i < LW; i++)
                *(float4*)&Ws[s][rowW + i * WR][colW] = rw[i];
            __syncthreads();
        }
    }

    // epilogue
#pragma unroll
    for (int mg = 0; mg < MG; mg++) {
#pragma unroll
        for (int i = 0; i < 4; i++) {
            int m = m0 + mg * (BM / 2) + ty * 4 + i;
#pragma unroll
            for (int ng = 0; ng < NG; ng++) {
                int n = n0 + ng * (BN / 2) + tx * 4;
                float4 v;
                float* vr = (float*)&v;
#pragma unroll
                for (int j = 0; j < 4; j++) {
                    float x = acc[mg * 4 + i][ng * 4 + j];
                    if (ACT == 2) {
                        x = 1.0f - x;
                    } else {
                        x += bias[n + j];
                        if (ACT == 1) x = fmaxf(x, 0.f);
                    }
                    vr[j] = x;
                }
                *(float4*)&C[(size_t)m * N + n] = v;
            }
        }
    }
}

// mean over B of drift column p, threshold -> flag
__global__ void __launch_bounds__(256) colmean_kernel(const float* __restrict__ drift,
                                                      float* __restrict__ out_flag) {
    int p = blockIdx.x * 256 + threadIdx.x;
    if (p >= Pn) return;
    float s = 0.f;
#pragma unroll 8
    for (int b = 0; b < Bn; b++) s += drift[(size_t)b * Pn + p];
    float fl = (s * (1.0f / Bn) > THRESHOLD) ? 1.0f : 0.0f;
    g_flag[p] = fl;
    if (out_flag) out_flag[p] = fl;
}

// build [centers | global_mean] concat; finalizes gm from partials (cached reads)
__global__ void __launch_bounds__(256) concat_kernel() {
    int i = blockIdx.x * 256 + threadIdx.x;   // P * 2D
    int p = i >> 9;
    int j = i & 511;
    float v;
    if (j < Dn) {
        v = g_centers[(p << 8) + j];
    } else {
        int d = j - Dn;
        float s = 0.f;
#pragma unroll
        for (int q = 0; q < 8; q++) s += g_gmp[q][d];
        v = s * (1.0f / Bn);
    }
    g_concat[i] = v;
}

// layernorm + relu over rows of width H=512
__global__ void __launch_bounds__(256) ln_relu_kernel(const float* __restrict__ z,
                                                      const float* __restrict__ g,
                                                      const float* __restrict__ be,
                                                      float* __restrict__ out) {
    int r = blockIdx.x;
    int d = threadIdx.x;
    const float* row = z + (size_t)r * Hn;
    float v0 = row[d], v1 = row[d + 256];

    __shared__ float red[256];
    red[d] = v0 + v1;
    __syncthreads();
    for (int o = 128; o > 0; o >>= 1) {
        if (d < o) red[d] += red[d + o];
        __syncthreads();
    }
    float mu = red[0] * (1.0f / Hn);
    __syncthreads();

    float d0 = v0 - mu, d1 = v1 - mu;
    red[d] = d0 * d0 + d1 * d1;
    __syncthreads();
    for (int o = 128; o > 0; o >>= 1) {
        if (d < o) red[d] += red[d + o];
        __syncthreads();
    }
    float var = red[0] * (1.0f / Hn);
    float rs = rsqrtf(var + EPS_LN);

    float* orow = out + (size_t)r * Hn;
    orow[d]       = fmaxf(d0 * rs * g[d] + be[d], 0.f);
    orow[d + 256] = fmaxf(d1 * rs * g[d + 256] + be[d + 256], 0.f);
}

// conf[p] = sigmoid(dot(h2[p], w3) + b3)
__global__ void __launch_bounds__(256) gemv_sig_kernel(const float* __restrict__ w3,
                                                       const float* __restrict__ b3) {
    int p = blockIdx.x;
    int d = threadIdx.x;
    float s = g_h2[(size_t)p * (Hn / 2) + d] * w3[d];
    __shared__ float red[256];
    red[d] = s;
    __syncthreads();
    for (int o = 128; o > 0; o >>= 1) {
        if (d < o) red[d] += red[d + o];
        __syncthreads();
    }
    if (d == 0) {
        float x = red[0] + b3[0];
        g_conf[p] = 1.0f / (1.0f + expf(-x));
    }
}

// new_center = centers + clip(0.1*conf,0,0.5)*delta
__global__ void __launch_bounds__(256) newc_kernel() {
    int i = blockIdx.x * 256 + threadIdx.x;   // P*D
    int p = i >> 8;
    float s = fminf(fmaxf(STRENGTH * g_conf[p], MIN_S), MAX_S);
    g_newc[i] = g_centers[i] + s * g_delta[i];
}

// calibrated[p][t][d] = flag[p] ? new_center[p][d] : prototype[p][t][d]  (float4)
__global__ void __launch_bounds__(256) scatter_kernel(const float* __restrict__ proto,
                                                      float* __restrict__ out) {
    int i = blockIdx.x * 256 + threadIdx.x;   // float4 units; total P*T*D/4
    int p = i >> 12;            // T*D/4 = 4096
    int r = i & 4095;
    int d4 = r & 63;            // D/4 = 64
    float4 v;
    if (g_flag[p] > 0.5f) {
        v = ((const float4*)g_newc)[(p << 6) + d4];
    } else {
        v = ((const float4*)proto)[i];
    }
    ((float4*)out)[i] = v;
}

// ---------------- launch ------------------------------------------------------
extern "C" void kernel_launch(void* const* d_in, const int* in_sizes, int n_in,
                              void* d_out, int out_size) {
    (void)in_sizes; (void)n_in;
    const float* feat   = (const float*)d_in[0];
    const float* proto  = (const float*)d_in[1];
    const float* dd_w1  = (const float*)d_in[2];
    const float* dd_b1  = (const float*)d_in[3];
    const float* dd_g1  = (const float*)d_in[4];
    const float* dd_be1 = (const float*)d_in[5];
    const float* dd_w2  = (const float*)d_in[6];
    const float* dd_b2  = (const float*)d_in[7];
    const float* dd_w3  = (const float*)d_in[8];
    const float* dd_b3  = (const float*)d_in[9];
    const float* cal_w1 = (const float*)d_in[10];
    const float* cal_b1 = (const float*)d_in[11];
    const float* cal_g1 = (const float*)d_in[12];
    const float* cal_be1= (const float*)d_in[13];
    const float* cal_w2 = (const float*)d_in[14];
    const float* cal_b2 = (const float*)d_in[15];
    const float* cal_w3 = (const float*)d_in[16];
    const float* cal_b3 = (const float*)d_in[17];

    float* out = (float*)d_out;
    const long long PTD = (long long)Pn * Tn * Dn;       // 33,554,432
    const long long BP  = (long long)Bn * Pn;            //  2,097,152

    bool has_drift = (long long)out_size >= PTD + BP;
    bool has_flag  = (long long)out_size >= PTD + BP + Pn;

    float* drift_ptr = nullptr;
    if (has_drift) {
        drift_ptr = out + PTD;
    } else {
        cudaGetSymbolAddress((void**)&drift_ptr, g_drift);
    }
    float* flag_ptr = has_flag ? (out + PTD + BP) : nullptr;

    float *p_centers, *p_ncT, *p_nf, *p_concat, *p_z1, *p_a1, *p_h2, *p_z2, *p_a2, *p_c2, *p_delta;
    cudaGetSymbolAddress((void**)&p_centers, g_centers);
    cudaGetSymbolAddress((void**)&p_ncT,     g_ncT);
    cudaGetSymbolAddress((void**)&p_nf,      g_nf);
    cudaGetSymbolAddress((void**)&p_concat,  g_concat);
    cudaGetSymbolAddress((void**)&p_z1,      g_z1);
    cudaGetSymbolAddress((void**)&p_a1,      g_a1);
    cudaGetSymbolAddress((void**)&p_h2,      g_h2);
    cudaGetSymbolAddress((void**)&p_z2,      g_z2);
    cudaGetSymbolAddress((void**)&p_a2,      g_a2);
    cudaGetSymbolAddress((void**)&p_c2,      g_c2);
    cudaGetSymbolAddress((void**)&p_delta,   g_delta);

    // 1: fused T-mean reductions (proto centers + feat rows)
    reduce_centers_kernel<<<Pn + Bn, Dn>>>(proto, feat);
    // 2: partial global mean
    gm_partial_kernel<<<8, Dn>>>();
    // 3: concat [centers | gm] (finalizes gm inline)
    concat_kernel<<<(Pn * 2 * Dn) / 256, 256>>>();

    // 4: drift score GEMM  [B,P] = 1 - nf @ ncT   (128x128 tile, 128 blocks)
    gemm_t<128, 128, 8, 8, 2, 256><<<dim3(Pn / 128, Bn / 128), 256>>>(
        p_nf, p_ncT, nullptr, drift_ptr, Bn, Pn, Dn);
    // 5: column mean -> is_drifted
    colmean_kernel<<<Pn / 256, 256>>>(drift_ptr, flag_ptr);

    // 6-8: drift-detector MLP
    gemm_t<128, 64, 8, 4, 0, 256><<<dim3(Hn / 64, Pn / 128), 256>>>(
        p_concat, dd_w1, dd_b1, p_z1, Pn, Hn, 2 * Dn);
    ln_relu_kernel<<<Pn, 256>>>(p_z1, dd_g1, dd_be1, p_a1);
    gemm_t<64, 64, 8, 4, 1, 128><<<dim3((Hn / 2) / 64, Pn / 64), 128>>>(
        p_a1, dd_w2, dd_b2, p_h2, Pn, Hn / 2, Hn);
    gemv_sig_kernel<<<Pn, 256>>>(dd_w3, dd_b3);

    // 9-12: calibration MLP
    gemm_t<128, 64, 8, 4, 0, 256><<<dim3(Hn / 64, Pn / 128), 256>>>(
        p_centers, cal_w1, cal_b1, p_z2, Pn, Hn, Dn);
    ln_relu_kernel<<<Pn, 256>>>(p_z2, cal_g1, cal_be1, p_a2);
    gemm_t<128, 64, 8, 4, 1, 256><<<dim3(Hn / 64, Pn / 128), 256>>>(
        p_a2, cal_w2, cal_b2, p_c2, Pn, Hn, Hn);
    gemm_t<64, 64, 8, 4, 0, 128><<<dim3(Dn / 64, Pn / 64), 128>>>(
        p_c2, cal_w3, cal_b3, p_delta, Pn, Dn, Hn);

    // 13: new centers
    newc_kernel<<<(Pn * Dn) / 256, 256>>>();
    // 14: scatter calibrated output
    scatter_kernel<<<(int)(PTD / 4 / 256), 256>>>(proto, out);
}

// round 6
// speedup vs baseline: 1.2420x; 1.1194x over previous
#include <cuda_runtime.h>
#include <math.h>
#include <stdint.h>

// Problem dims
#define Bn 1024
#define Tn 64
#define Dn 256
#define Pn 2048
#define Hn 512

#define THRESHOLD 0.3f
#define STRENGTH 0.1f
#define MIN_S 0.0f
#define MAX_S 0.5f
#define EPS_COS 1e-8f
#define EPS_LN 1e-5f

// ---------------- scratch (static device globals; no allocations) -------------
__device__ float g_centers[Pn * Dn];
__device__ float g_ncT[Dn * Pn];
__device__ float g_nf[Bn * Dn];
__device__ float g_fcent[Bn * Dn];
__device__ float g_gmp[8][Dn];
__device__ float g_drift[Bn * Pn];
__device__ float g_flag[Pn];
__device__ float g_concat[Pn * 2 * Dn];
__device__ float g_z1[Pn * Hn];
__device__ float g_a1[Pn * Hn];
__device__ float g_h2[Pn * (Hn / 2)];
__device__ float g_conf[Pn];
__device__ float g_z2[Pn * Hn];
__device__ float g_a2[Pn * Hn];
__device__ float g_c2[Pn * Hn];
__device__ float g_delta[Pn * Dn];
__device__ float g_newc[Pn * Dn];

// ---------------- fused T-mean reductions (proto + feat in one launch) --------
__global__ void __launch_bounds__(Dn) reduce_centers_kernel(
    const float* __restrict__ proto, const float* __restrict__ feat)
{
    int blk = blockIdx.x;
    int d = threadIdx.x;
    bool isP = blk < Pn;
    int row = isP ? blk : (blk - Pn);
    const float* base = (isP ? proto : feat) + (size_t)row * Tn * Dn + d;
    float s = 0.f;
#pragma unroll 16
    for (int t = 0; t < Tn; t++) s += base[t * Dn];
    float c = s * (1.0f / Tn);

    __shared__ float red[Dn];
    red[d] = c * c;
    __syncthreads();
    for (int o = Dn / 2; o > 0; o >>= 1) {
        if (d < o) red[d] += red[d + o];
        __syncthreads();
    }
    float nrm = fmaxf(sqrtf(red[0]), EPS_COS);
    if (isP) {
        g_centers[row * Dn + d] = c;
        g_ncT[(size_t)d * Pn + row] = c / nrm;
    } else {
        g_fcent[row * Dn + d] = c;
        g_nf[row * Dn + d] = c / nrm;
    }
}

// partial global_mean over B: 8 blocks, each sums 128 rows
__global__ void __launch_bounds__(Dn) gm_partial_kernel() {
    int i = blockIdx.x;
    int d = threadIdx.x;
    float s = 0.f;
    int b0 = i * (Bn / 8);
#pragma unroll 8
    for (int b = 0; b < Bn / 8; b++) s += g_fcent[(b0 + b) * Dn + d];
    g_gmp[i][d] = s;
}

// ---------------- tf32 helpers -----------------------------------------------
__device__ __forceinline__ float tf32f(float x) {
    uint32_t r;
    asm("cvt.rna.tf32.f32 %0, %1;" : "=r"(r) : "f"(x));
    return __uint_as_float(r);
}

__device__ __forceinline__ void mma_tf32(float* c,
                                         uint32_t a0, uint32_t a1, uint32_t a2, uint32_t a3,
                                         uint32_t b0, uint32_t b1) {
    asm volatile(
        "mma.sync.aligned.m16n8k8.row.col.f32.tf32.tf32.f32 "
        "{%0,%1,%2,%3}, {%4,%5,%6,%7}, {%8,%9}, {%0,%1,%2,%3};\n"
        : "+f"(c[0]), "+f"(c[1]), "+f"(c[2]), "+f"(c[3])
        : "r"(a0), "r"(a1), "r"(a2), "r"(a3), "r"(b0), "r"(b1));
}

// ---- tf32 tensor-core GEMM: C[M,N] = act(A[M,K] @ W[K,N] + bias)
// ACT: 0 = bias, 1 = relu(bias), 2 = (1 - acc), no bias
// Block: NT threads (NT/32 warps arranged WM x WN). Warp tile: (BM/WM) x (BN/WN).
// BK = 16 (two k=8 mma steps), double buffered smem. Pads chosen so the k-row
// stride is 8 banks -> fragment loads are conflict-free (4 k x 8 m lanes span
// all 32 banks).
template<int BM, int BN, int WM, int WN, int ACT, int NT>
__global__ void __launch_bounds__(NT) gemm_tc(
    const float* __restrict__ A, const float* __restrict__ W,
    const float* __restrict__ bias, float* __restrict__ C,
    int M, int N, int K)
{
    constexpr int BK = 16;
    constexpr int WTM = BM / WM;     // warp tile M
    constexpr int WTN = BN / WN;     // warp tile N
    constexpr int MI = WTM / 16;     // mma tiles per warp in M
    constexpr int NI = WTN / 8;      // mma tiles per warp in N
    constexpr int PA = 8;            // pad -> row stride % 32 == 8 banks

    __shared__ __align__(16) float As[2][BK][BM + PA];
    __shared__ __align__(16) float Bs[2][BK][BN + PA];

    const int t = threadIdx.x;
    const int warp = t >> 5;
    const int lane = t & 31;
    const int g  = lane >> 2;        // group id 0..7
    const int tg = lane & 3;         // thread in group 0..3
    const int wm = warp / WN;
    const int wn = warp % WN;

    const int m0 = blockIdx.y * BM;
    const int n0 = blockIdx.x * BN;

    // staging: A tile BM x BK (row-major), W tile BK x BN (row-major)
    constexpr int LA = (BM * BK) / (4 * NT);
    constexpr int LB = (BK * BN) / (4 * NT);
    constexpr int AR = NT / (BK / 4);       // A rows per load pass
    constexpr int WR = NT / (BN / 4);       // W rows per load pass
    const int rowA  = t / (BK / 4);
    const int col4A = (t % (BK / 4)) * 4;
    const int rowW  = t / (BN / 4);
    const int colW  = (t % (BN / 4)) * 4;

    const float* Abase = A + (size_t)m0 * K;
    const float* Wbase = W + n0;

    float4 ra[LA], rw[LB];

    // prologue: k-block 0
#pragma unroll
    for (int i = 0; i < LA; i++)
        ra[i] = *(const float4*)(Abase + (size_t)(rowA + i * AR) * K + col4A);
#pragma unroll
    for (int i = 0; i < LB; i++)
        rw[i] = *(const float4*)(Wbase + (size_t)(rowW + i * WR) * N + colW);

#pragma unroll
    for (int i = 0; i < LA; i++) {
        int r = rowA + i * AR;
        As[0][col4A + 0][r] = tf32f(ra[i].x);
        As[0][col4A + 1][r] = tf32f(ra[i].y);
        As[0][col4A + 2][r] = tf32f(ra[i].z);
        As[0][col4A + 3][r] = tf32f(ra[i].w);
    }
#pragma unroll
    for (int i = 0; i < LB; i++) {
        float4 cv;
        cv.x = tf32f(rw[i].x); cv.y = tf32f(rw[i].y);
        cv.z = tf32f(rw[i].z); cv.w = tf32f(rw[i].w);
        *(float4*)&Bs[0][rowW + i * WR][colW] = cv;
    }
    __syncthreads();

    float acc[MI][NI][4];
#pragma unroll
    for (int mi = 0; mi < MI; mi++)
#pragma unroll
        for (int ni = 0; ni < NI; ni++)
#pragma unroll
            for (int q = 0; q < 4; q++) acc[mi][ni][q] = 0.f;

    int s = 0;
    for (int k0 = 0; k0 < K; k0 += BK) {
        bool more = (k0 + BK) < K;
        if (more) {
            const float* An = Abase + k0 + BK;
#pragma unroll
            for (int i = 0; i < LA; i++)
                ra[i] = *(const float4*)(An + (size_t)(rowA + i * AR) * K + col4A);
            const float* Wn = Wbase + (size_t)(k0 + BK) * N;
#pragma unroll
            for (int i = 0; i < LB; i++)
                rw[i] = *(const float4*)(Wn + (size_t)(rowW + i * WR) * N + colW);
        }

#pragma unroll
        for (int ks = 0; ks < BK; ks += 8) {
            uint32_t af[MI][4], bf[NI][2];
#pragma unroll
            for (int mi = 0; mi < MI; mi++) {
                int m = wm * WTM + mi * 16 + g;
                af[mi][0] = __float_as_uint(As[s][ks + tg][m]);
                af[mi][1] = __float_as_uint(As[s][ks + tg][m + 8]);
                af[mi][2] = __float_as_uint(As[s][ks + tg + 4][m]);
                af[mi][3] = __float_as_uint(As[s][ks + tg + 4][m + 8]);
            }
#pragma unroll
            for (int ni = 0; ni < NI; ni++) {
                int n = wn * WTN + ni * 8 + g;
                bf[ni][0] = __float_as_uint(Bs[s][ks + tg][n]);
                bf[ni][1] = __float_as_uint(Bs[s][ks + tg + 4][n]);
            }
#pragma unroll
            for (int mi = 0; mi < MI; mi++)
#pragma unroll
                for (int ni = 0; ni < NI; ni++)
                    mma_tf32(acc[mi][ni],
                             af[mi][0], af[mi][1], af[mi][2], af[mi][3],
                             bf[ni][0], bf[ni][1]);
        }

        if (more) {
            s ^= 1;
#pragma unroll
            for (int i = 0; i < LA; i++) {
                int r = rowA + i * AR;
                As[s][col4A + 0][r] = tf32f(ra[i].x);
                As[s][col4A + 1][r] = tf32f(ra[i].y);
                As[s][col4A + 2][r] = tf32f(ra[i].z);
                As[s][col4A + 3][r] = tf32f(ra[i].w);
            }
#pragma unroll
            for (int i = 0; i < LB; i++) {
                float4 cv;
                cv.x = tf32f(rw[i].x); cv.y = tf32f(rw[i].y);
                cv.z = tf32f(rw[i].z); cv.w = tf32f(rw[i].w);
                *(float4*)&Bs[s][rowW + i * WR][colW] = cv;
            }
            __syncthreads();
        }
    }

    // epilogue: each mma frag holds rows {g, g+8}, cols {tg*2, tg*2+1}
#pragma unroll
    for (int mi = 0; mi < MI; mi++) {
#pragma unroll
        for (int ni = 0; ni < NI; ni++) {
            int m = m0 + wm * WTM + mi * 16 + g;
            int n = n0 + wn * WTN + ni * 8 + tg * 2;
            float b0 = 0.f, b1 = 0.f;
            if (ACT != 2) { b0 = bias[n]; b1 = bias[n + 1]; }
            float2 v0, v1;
            if (ACT == 2) {
                v0.x = 1.0f - acc[mi][ni][0]; v0.y = 1.0f - acc[mi][ni][1];
                v1.x = 1.0f - acc[mi][ni][2]; v1.y = 1.0f - acc[mi][ni][3];
            } else {
                v0.x = acc[mi][ni][0] + b0;   v0.y = acc[mi][ni][1] + b1;
                v1.x = acc[mi][ni][2] + b0;   v1.y = acc[mi][ni][3] + b1;
                if (ACT == 1) {
                    v0.x = fmaxf(v0.x, 0.f); v0.y = fmaxf(v0.y, 0.f);
                    v1.x = fmaxf(v1.x, 0.f); v1.y = fmaxf(v1.y, 0.f);
                }
            }
            *(float2*)&C[(size_t)m * N + n]       = v0;
            *(float2*)&C[(size_t)(m + 8) * N + n] = v1;
        }
    }
}

// mean over B of drift column p, threshold -> flag
__global__ void __launch_bounds__(256) colmean_kernel(const float* __restrict__ drift,
                                                      float* __restrict__ out_flag) {
    int p = blockIdx.x * 256 + threadIdx.x;
    if (p >= Pn) return;
    float s = 0.f;
#pragma unroll 8
    for (int b = 0; b < Bn; b++) s += drift[(size_t)b * Pn + p];
    float fl = (s * (1.0f / Bn) > THRESHOLD) ? 1.0f : 0.0f;
    g_flag[p] = fl;
    if (out_flag) out_flag[p] = fl;
}

// build [centers | global_mean] concat; finalizes gm from partials
__global__ void __launch_bounds__(256) concat_kernel() {
    int i = blockIdx.x * 256 + threadIdx.x;
    int p = i >> 9;
    int j = i & 511;
    float v;
    if (j < Dn) {
        v = g_centers[(p << 8) + j];
    } else {
        int d = j - Dn;
        float s = 0.f;
#pragma unroll
        for (int q = 0; q < 8; q++) s += g_gmp[q][d];
        v = s * (1.0f / Bn);
    }
    g_concat[i] = v;
}

// layernorm + relu over rows of width H=512
__global__ void __launch_bounds__(256) ln_relu_kernel(const float* __restrict__ z,
                                                      const float* __restrict__ g,
                                                      const float* __restrict__ be,
                                                      float* __restrict__ out) {
    int r = blockIdx.x;
    int d = threadIdx.x;
    const float* row = z + (size_t)r * Hn;
    float v0 = row[d], v1 = row[d + 256];

    __shared__ float red[256];
    red[d] = v0 + v1;
    __syncthreads();
    for (int o = 128; o > 0; o >>= 1) {
        if (d < o) red[d] += red[d + o];
        __syncthreads();
    }
    float mu = red[0] * (1.0f / Hn);
    __syncthreads();

    float d0 = v0 - mu, d1 = v1 - mu;
    red[d] = d0 * d0 + d1 * d1;
    __syncthreads();
    for (int o = 128; o > 0; o >>= 1) {
        if (d < o) red[d] += red[d + o];
        __syncthreads();
    }
    float var = red[0] * (1.0f / Hn);
    float rs = rsqrtf(var + EPS_LN);

    float* orow = out + (size_t)r * Hn;
    orow[d]       = fmaxf(d0 * rs * g[d] + be[d], 0.f);
    orow[d + 256] = fmaxf(d1 * rs * g[d + 256] + be[d + 256], 0.f);
}

// conf[p] = sigmoid(dot(h2[p], w3) + b3)
__global__ void __launch_bounds__(256) gemv_sig_kernel(const float* __restrict__ w3,
                                                       const float* __restrict__ b3) {
    int p = blockIdx.x;
    int d = threadIdx.x;
    float s = g_h2[(size_t)p * (Hn / 2) + d] * w3[d];
    __shared__ float red[256];
    red[d] = s;
    __syncthreads();
    for (int o = 128; o > 0; o >>= 1) {
        if (d < o) red[d] += red[d + o];
        __syncthreads();
    }
    if (d == 0) {
        float x = red[0] + b3[0];
        g_conf[p] = 1.0f / (1.0f + expf(-x));
    }
}

// new_center = centers + clip(0.1*conf,0,0.5)*delta
__global__ void __launch_bounds__(256) newc_kernel() {
    int i = blockIdx.x * 256 + threadIdx.x;
    int p = i >> 8;
    float s = fminf(fmaxf(STRENGTH * g_conf[p], MIN_S), MAX_S);
    g_newc[i] = g_centers[i] + s * g_delta[i];
}

// calibrated[p][t][d] = flag[p] ? new_center[p][d] : prototype[p][t][d]
__global__ void __launch_bounds__(256) scatter_kernel(const float* __restrict__ proto,
                                                      float* __restrict__ out) {
    int i = blockIdx.x * 256 + threadIdx.x;
    int p = i >> 12;
    int r = i & 4095;
    int d4 = r & 63;
    float4 v;
    if (g_flag[p] > 0.5f) {
        v = ((const float4*)g_newc)[(p << 6) + d4];
    } else {
        v = ((const float4*)proto)[i];
    }
    ((float4*)out)[i] = v;
}

// ---------------- launch ------------------------------------------------------
extern "C" void kernel_launch(void* const* d_in, const int* in_sizes, int n_in,
                              void* d_out, int out_size) {
    (void)in_sizes; (void)n_in;
    const float* feat   = (const float*)d_in[0];
    const float* proto  = (const float*)d_in[1];
    const float* dd_w1  = (const float*)d_in[2];
    const float* dd_b1  = (const float*)d_in[3];
    const float* dd_g1  = (const float*)d_in[4];
    const float* dd_be1 = (const float*)d_in[5];
    const float* dd_w2  = (const float*)d_in[6];
    const float* dd_b2  = (const float*)d_in[7];
    const float* dd_w3  = (const float*)d_in[8];
    const float* dd_b3  = (const float*)d_in[9];
    const float* cal_w1 = (const float*)d_in[10];
    const float* cal_b1 = (const float*)d_in[11];
    const float* cal_g1 = (const float*)d_in[12];
    const float* cal_be1= (const float*)d_in[13];
    const float* cal_w2 = (const float*)d_in[14];
    const float* cal_b2 = (const float*)d_in[15];
    const float* cal_w3 = (const float*)d_in[16];
    const float* cal_b3 = (const float*)d_in[17];

    float* out = (float*)d_out;
    const long long PTD = (long long)Pn * Tn * Dn;
    const long long BP  = (long long)Bn * Pn;

    bool has_drift = (long long)out_size >= PTD + BP;
    bool has_flag  = (long long)out_size >= PTD + BP + Pn;

    float* drift_ptr = nullptr;
    if (has_drift) {
        drift_ptr = out + PTD;
    } else {
        cudaGetSymbolAddress((void**)&drift_ptr, g_drift);
    }
    float* flag_ptr = has_flag ? (out + PTD + BP) : nullptr;

    float *p_centers, *p_ncT, *p_nf, *p_concat, *p_z1, *p_a1, *p_h2, *p_z2, *p_a2, *p_c2, *p_delta;
    cudaGetSymbolAddress((void**)&p_centers, g_centers);
    cudaGetSymbolAddress((void**)&p_ncT,     g_ncT);
    cudaGetSymbolAddress((void**)&p_nf,      g_nf);
    cudaGetSymbolAddress((void**)&p_concat,  g_concat);
    cudaGetSymbolAddress((void**)&p_z1,      g_z1);
    cudaGetSymbolAddress((void**)&p_a1,      g_a1);
    cudaGetSymbolAddress((void**)&p_h2,      g_h2);
    cudaGetSymbolAddress((void**)&p_z2,      g_z2);
    cudaGetSymbolAddress((void**)&p_a2,      g_a2);
    cudaGetSymbolAddress((void**)&p_c2,      g_c2);
    cudaGetSymbolAddress((void**)&p_delta,   g_delta);

    // 1: fused T-mean reductions
    reduce_centers_kernel<<<Pn + Bn, Dn>>>(proto, feat);
    // 2: partial global mean
    gm_partial_kernel<<<8, Dn>>>();
    // 3: concat [centers | gm]
    concat_kernel<<<(Pn * 2 * Dn) / 256, 256>>>();

    // 4: drift score GEMM  [B,P] = 1 - nf @ ncT   (tf32 tensor cores)
    gemm_tc<128, 128, 2, 4, 2, 256><<<dim3(Pn / 128, Bn / 128), 256>>>(
        p_nf, p_ncT, nullptr, drift_ptr, Bn, Pn, Dn);
    // 5: column mean -> is_drifted
    colmean_kernel<<<Pn / 256, 256>>>(drift_ptr, flag_ptr);

    // 6-8: drift-detector MLP
    gemm_tc<128, 64, 4, 2, 0, 256><<<dim3(Hn / 64, Pn / 128), 256>>>(
        p_concat, dd_w1, dd_b1, p_z1, Pn, Hn, 2 * Dn);
    ln_relu_kernel<<<Pn, 256>>>(p_z1, dd_g1, dd_be1, p_a1);
    gemm_tc<64, 64, 2, 2, 1, 128><<<dim3((Hn / 2) / 64, Pn / 64), 128>>>(
        p_a1, dd_w2, dd_b2, p_h2, Pn, Hn / 2, Hn);
    gemv_sig_kernel<<<Pn, 256>>>(dd_w3, dd_b3);

    // 9-12: calibration MLP
    gemm_tc<128, 64, 4, 2, 0, 256><<<dim3(Hn / 64, Pn / 128), 256>>>(
        p_centers, cal_w1, cal_b1, p_z2, Pn, Hn, Dn);
    ln_relu_kernel<<<Pn, 256>>>(p_z2, cal_g1, cal_be1, p_a2);
    gemm_tc<128, 64, 4, 2, 1, 256><<<dim3(Hn / 64, Pn / 128), 256>>>(
        p_a2, cal_w2, cal_b2, p_c2, Pn, Hn, Hn);
    gemm_tc<64, 64, 2, 2, 0, 128><<<dim3(Dn / 64, Pn / 64), 128>>>(
        p_c2, cal_w3, cal_b3, p_delta, Pn, Dn, Hn);

    // 13: new centers
    newc_kernel<<<(Pn * Dn) / 256, 256>>>();
    // 14: scatter calibrated output
    scatter_kernel<<<(int)(PTD / 4 / 256), 256>>>(proto, out);
}

// round 7
// speedup vs baseline: 1.4310x; 1.1521x over previous
#include <cuda_runtime.h>
#include <math.h>
#include <stdint.h>

// Problem dims
#define Bn 1024
#define Tn 64
#define Dn 256
#define Pn 2048
#define Hn 512

#define THRESHOLD 0.3f
#define STRENGTH 0.1f
#define MIN_S 0.0f
#define MAX_S 0.5f
#define EPS_COS 1e-8f
#define EPS_LN 1e-5f

// ---------------- scratch (static device globals; no allocations) -------------
__device__ float g_centers[Pn * Dn];
__device__ float g_ncT[Dn * Pn];
__device__ float g_nf[Bn * Dn];
__device__ float g_fcent[Bn * Dn];
__device__ float g_gmp[8][Dn];
__device__ float g_bias2[Hn];
__device__ float g_drift[Bn * Pn];
__device__ float g_flag[Pn];
__device__ float g_z1[Pn * Hn];
__device__ float g_a1[Pn * Hn];
__device__ float g_h2[Pn * (Hn / 2)];
__device__ float g_conf[Pn];
__device__ float g_z2[Pn * Hn];
__device__ float g_a2[Pn * Hn];
__device__ float g_c2[Pn * Hn];
__device__ float g_delta[Pn * Dn];
__device__ float g_newc[Pn * Dn];

// ---------------- fused T-mean reductions (proto + feat in one launch) --------
__global__ void __launch_bounds__(Dn) reduce_centers_kernel(
    const float* __restrict__ proto, const float* __restrict__ feat)
{
    int blk = blockIdx.x;
    int d = threadIdx.x;
    bool isP = blk < Pn;
    int row = isP ? blk : (blk - Pn);
    const float* base = (isP ? proto : feat) + (size_t)row * Tn * Dn + d;
    float s = 0.f;
#pragma unroll 16
    for (int t = 0; t < Tn; t++) s += base[t * Dn];
    float c = s * (1.0f / Tn);

    __shared__ float red[Dn];
    red[d] = c * c;
    __syncthreads();
    for (int o = Dn / 2; o > 0; o >>= 1) {
        if (d < o) red[d] += red[d + o];
        __syncthreads();
    }
    float nrm = fmaxf(sqrtf(red[0]), EPS_COS);
    if (isP) {
        g_centers[row * Dn + d] = c;
        g_ncT[(size_t)d * Pn + row] = c / nrm;
    } else {
        g_fcent[row * Dn + d] = c;
        g_nf[row * Dn + d] = c / nrm;
    }
}

// partial global_mean over B: 8 blocks, each sums 128 rows
__global__ void __launch_bounds__(Dn) gm_partial_kernel() {
    int i = blockIdx.x;
    int d = threadIdx.x;
    float s = 0.f;
    int b0 = i * (Bn / 8);
#pragma unroll 8
    for (int b = 0; b < Bn / 8; b++) s += g_fcent[(b0 + b) * Dn + d];
    g_gmp[i][d] = s;
}

// bias2[h] = dd_b1[h] + sum_d gm[d] * dd_w1[D + d][h]
// grid 8 blocks x 512 threads; threads = (64 h) x (8 d-groups)
__global__ void __launch_bounds__(512) bias2_kernel(const float* __restrict__ dd_w1,
                                                    const float* __restrict__ dd_b1) {
    int hx = threadIdx.x & 63;
    int dg = threadIdx.x >> 6;
    int h = blockIdx.x * 64 + hx;
    float s = 0.f;
#pragma unroll 8
    for (int j = 0; j < 32; j++) {
        int d = dg * 32 + j;
        float gm = 0.f;
#pragma unroll
        for (int q = 0; q < 8; q++) gm += g_gmp[q][d];
        gm *= (1.0f / Bn);
        s += gm * dd_w1[(size_t)(Dn + d) * Hn + h];
    }
    __shared__ float red[8][64];
    red[dg][hx] = s;
    __syncthreads();
    if (dg == 0) {
        float t = 0.f;
#pragma unroll
        for (int q = 0; q < 8; q++) t += red[q][hx];
        g_bias2[h] = dd_b1[h] + t;
    }
}

// ---------------- tf32 helpers -----------------------------------------------
__device__ __forceinline__ float tf32f(float x) {
    uint32_t r;
    asm("cvt.rna.tf32.f32 %0, %1;" : "=r"(r) : "f"(x));
    return __uint_as_float(r);
}

__device__ __forceinline__ void mma_tf32(float* c,
                                         uint32_t a0, uint32_t a1, uint32_t a2, uint32_t a3,
                                         uint32_t b0, uint32_t b1) {
    asm volatile(
        "mma.sync.aligned.m16n8k8.row.col.f32.tf32.tf32.f32 "
        "{%0,%1,%2,%3}, {%4,%5,%6,%7}, {%8,%9}, {%0,%1,%2,%3};\n"
        : "+f"(c[0]), "+f"(c[1]), "+f"(c[2]), "+f"(c[3])
        : "r"(a0), "r"(a1), "r"(a2), "r"(a3), "r"(b0), "r"(b1));
}

// ---- tf32 tensor-core GEMM: C[M,N] = act(A[M,K] @ W[K,N] + bias)
// ACT: 0 = bias, 1 = relu(bias), 2 = (1 - acc), no bias
template<int BM, int BN, int WM, int WN, int ACT, int NT>
__global__ void __launch_bounds__(NT) gemm_tc(
    const float* __restrict__ A, const float* __restrict__ W,
    const float* __restrict__ bias, float* __restrict__ C,
    int M, int N, int K)
{
    constexpr int BK = 16;
    constexpr int WTM = BM / WM;
    constexpr int WTN = BN / WN;
    constexpr int MI = WTM / 16;
    constexpr int NI = WTN / 8;
    constexpr int PA = 8;

    __shared__ __align__(16) float As[2][BK][BM + PA];
    __shared__ __align__(16) float Bs[2][BK][BN + PA];

    const int t = threadIdx.x;
    const int warp = t >> 5;
    const int lane = t & 31;
    const int g  = lane >> 2;
    const int tg = lane & 3;
    const int wm = warp / WN;
    const int wn = warp % WN;

    const int m0 = blockIdx.y * BM;
    const int n0 = blockIdx.x * BN;

    constexpr int LA = (BM * BK) / (4 * NT);
    constexpr int LB = (BK * BN) / (4 * NT);
    constexpr int AR = NT / (BK / 4);
    constexpr int WR = NT / (BN / 4);
    const int rowA  = t / (BK / 4);
    const int col4A = (t % (BK / 4)) * 4;
    const int rowW  = t / (BN / 4);
    const int colW  = (t % (BN / 4)) * 4;

    const float* Abase = A + (size_t)m0 * K;
    const float* Wbase = W + n0;

    float4 ra[LA], rw[LB];

#pragma unroll
    for (int i = 0; i < LA; i++)
        ra[i] = *(const float4*)(Abase + (size_t)(rowA + i * AR) * K + col4A);
#pragma unroll
    for (int i = 0; i < LB; i++)
        rw[i] = *(const float4*)(Wbase + (size_t)(rowW + i * WR) * N + colW);

#pragma unroll
    for (int i = 0; i < LA; i++) {
        int r = rowA + i * AR;
        As[0][col4A + 0][r] = tf32f(ra[i].x);
        As[0][col4A + 1][r] = tf32f(ra[i].y);
        As[0][col4A + 2][r] = tf32f(ra[i].z);
        As[0][col4A + 3][r] = tf32f(ra[i].w);
    }
#pragma unroll
    for (int i = 0; i < LB; i++) {
        float4 cv;
        cv.x = tf32f(rw[i].x); cv.y = tf32f(rw[i].y);
        cv.z = tf32f(rw[i].z); cv.w = tf32f(rw[i].w);
        *(float4*)&Bs[0][rowW + i * WR][colW] = cv;
    }
    __syncthreads();

    float acc[MI][NI][4];
#pragma unroll
    for (int mi = 0; mi < MI; mi++)
#pragma unroll
        for (int ni = 0; ni < NI; ni++)
#pragma unroll
            for (int q = 0; q < 4; q++) acc[mi][ni][q] = 0.f;

    int s = 0;
    for (int k0 = 0; k0 < K; k0 += BK) {
        bool more = (k0 + BK) < K;
        if (more) {
            const float* An = Abase + k0 + BK;
#pragma unroll
            for (int i = 0; i < LA; i++)
                ra[i] = *(const float4*)(An + (size_t)(rowA + i * AR) * K + col4A);
            const float* Wn = Wbase + (size_t)(k0 + BK) * N;
#pragma unroll
            for (int i = 0; i < LB; i++)
                rw[i] = *(const float4*)(Wn + (size_t)(rowW + i * WR) * N + colW);
        }

#pragma unroll
        for (int ks = 0; ks < BK; ks += 8) {
            uint32_t af[MI][4], bf[NI][2];
#pragma unroll
            for (int mi = 0; mi < MI; mi++) {
                int m = wm * WTM + mi * 16 + g;
                af[mi][0] = __float_as_uint(As[s][ks + tg][m]);
                af[mi][1] = __float_as_uint(As[s][ks + tg][m + 8]);
                af[mi][2] = __float_as_uint(As[s][ks + tg + 4][m]);
                af[mi][3] = __float_as_uint(As[s][ks + tg + 4][m + 8]);
            }
#pragma unroll
            for (int ni = 0; ni < NI; ni++) {
                int n = wn * WTN + ni * 8 + g;
                bf[ni][0] = __float_as_uint(Bs[s][ks + tg][n]);
                bf[ni][1] = __float_as_uint(Bs[s][ks + tg + 4][n]);
            }
#pragma unroll
            for (int mi = 0; mi < MI; mi++)
#pragma unroll
                for (int ni = 0; ni < NI; ni++)
                    mma_tf32(acc[mi][ni],
                             af[mi][0], af[mi][1], af[mi][2], af[mi][3],
                             bf[ni][0], bf[ni][1]);
        }

        if (more) {
            s ^= 1;
#pragma unroll
            for (int i = 0; i < LA; i++) {
                int r = rowA + i * AR;
                As[s][col4A + 0][r] = tf32f(ra[i].x);
                As[s][col4A + 1][r] = tf32f(ra[i].y);
                As[s][col4A + 2][r] = tf32f(ra[i].z);
                As[s][col4A + 3][r] = tf32f(ra[i].w);
            }
#pragma unroll
            for (int i = 0; i < LB; i++) {
                float4 cv;
                cv.x = tf32f(rw[i].x); cv.y = tf32f(rw[i].y);
                cv.z = tf32f(rw[i].z); cv.w = tf32f(rw[i].w);
                *(float4*)&Bs[s][rowW + i * WR][colW] = cv;
            }
            __syncthreads();
        }
    }

#pragma unroll
    for (int mi = 0; mi < MI; mi++) {
#pragma unroll
        for (int ni = 0; ni < NI; ni++) {
            int m = m0 + wm * WTM + mi * 16 + g;
            int n = n0 + wn * WTN + ni * 8 + tg * 2;
            float b0 = 0.f, b1 = 0.f;
            if (ACT != 2) { b0 = bias[n]; b1 = bias[n + 1]; }
            float2 v0, v1;
            if (ACT == 2) {
                v0.x = 1.0f - acc[mi][ni][0]; v0.y = 1.0f - acc[mi][ni][1];
                v1.x = 1.0f - acc[mi][ni][2]; v1.y = 1.0f - acc[mi][ni][3];
            } else {
                v0.x = acc[mi][ni][0] + b0;   v0.y = acc[mi][ni][1] + b1;
                v1.x = acc[mi][ni][2] + b0;   v1.y = acc[mi][ni][3] + b1;
                if (ACT == 1) {
                    v0.x = fmaxf(v0.x, 0.f); v0.y = fmaxf(v0.y, 0.f);
                    v1.x = fmaxf(v1.x, 0.f); v1.y = fmaxf(v1.y, 0.f);
                }
            }
            *(float2*)&C[(size_t)m * N + n]       = v0;
            *(float2*)&C[(size_t)(m + 8) * N + n] = v1;
        }
    }
}

// mean over B of drift column p -> flag. 64 blocks x (32 p, 8 b-slices)
__global__ void __launch_bounds__(256) colmean_kernel(const float* __restrict__ drift,
                                                      float* __restrict__ out_flag) {
    int tx = threadIdx.x & 31;
    int ty = threadIdx.x >> 5;
    int p = blockIdx.x * 32 + tx;
    float s = 0.f;
#pragma unroll 8
    for (int b = ty; b < Bn; b += 8)
        s += drift[(size_t)b * Pn + p];
    __shared__ float red[8][33];
    red[ty][tx] = s;
    __syncthreads();
    if (ty == 0) {
        float t = red[0][tx];
#pragma unroll
        for (int q = 1; q < 8; q++) t += red[q][tx];
        float fl = (t * (1.0f / Bn) > THRESHOLD) ? 1.0f : 0.0f;
        g_flag[p] = fl;
        if (out_flag) out_flag[p] = fl;
    }
}

// layernorm + relu over rows of width H=512
__global__ void __launch_bounds__(256) ln_relu_kernel(const float* __restrict__ z,
                                                      const float* __restrict__ g,
                                                      const float* __restrict__ be,
                                                      float* __restrict__ out) {
    int r = blockIdx.x;
    int d = threadIdx.x;
    const float* row = z + (size_t)r * Hn;
    float v0 = row[d], v1 = row[d + 256];

    __shared__ float red[256];
    red[d] = v0 + v1;
    __syncthreads();
    for (int o = 128; o > 0; o >>= 1) {
        if (d < o) red[d] += red[d + o];
        __syncthreads();
    }
    float mu = red[0] * (1.0f / Hn);
    __syncthreads();

    float d0 = v0 - mu, d1 = v1 - mu;
    red[d] = d0 * d0 + d1 * d1;
    __syncthreads();
    for (int o = 128; o > 0; o >>= 1) {
        if (d < o) red[d] += red[d + o];
        __syncthreads();
    }
    float var = red[0] * (1.0f / Hn);
    float rs = rsqrtf(var + EPS_LN);

    float* orow = out + (size_t)r * Hn;
    orow[d]       = fmaxf(d0 * rs * g[d] + be[d], 0.f);
    orow[d + 256] = fmaxf(d1 * rs * g[d + 256] + be[d + 256], 0.f);
}

// conf[p] = sigmoid(dot(h2[p], w3) + b3)
__global__ void __launch_bounds__(256) gemv_sig_kernel(const float* __restrict__ w3,
                                                       const float* __restrict__ b3) {
    int p = blockIdx.x;
    int d = threadIdx.x;
    float s = g_h2[(size_t)p * (Hn / 2) + d] * w3[d];
    __shared__ float red[256];
    red[d] = s;
    __syncthreads();
    for (int o = 128; o > 0; o >>= 1) {
        if (d < o) red[d] += red[d + o];
        __syncthreads();
    }
    if (d == 0) {
        float x = red[0] + b3[0];
        g_conf[p] = 1.0f / (1.0f + expf(-x));
    }
}

// new_center = centers + clip(0.1*conf,0,0.5)*delta
__global__ void __launch_bounds__(256) newc_kernel() {
    int i = blockIdx.x * 256 + threadIdx.x;
    int p = i >> 8;
    float s = fminf(fmaxf(STRENGTH * g_conf[p], MIN_S), MAX_S);
    g_newc[i] = g_centers[i] + s * g_delta[i];
}

// calibrated[p][t][d] = flag[p] ? new_center[p][d] : prototype[p][t][d]
__global__ void __launch_bounds__(256) scatter_kernel(const float* __restrict__ proto,
                                                      float* __restrict__ out) {
    int i = blockIdx.x * 256 + threadIdx.x;
    int p = i >> 12;
    int r = i & 4095;
    int d4 = r & 63;
    float4 v;
    if (g_flag[p] > 0.5f) {
        v = ((const float4*)g_newc)[(p << 6) + d4];
    } else {
        v = ((const float4*)proto)[i];
    }
    ((float4*)out)[i] = v;
}

// ---------------- launch ------------------------------------------------------
extern "C" void kernel_launch(void* const* d_in, const int* in_sizes, int n_in,
                              void* d_out, int out_size) {
    (void)in_sizes; (void)n_in;
    const float* feat   = (const float*)d_in[0];
    const float* proto  = (const float*)d_in[1];
    const float* dd_w1  = (const float*)d_in[2];
    const float* dd_b1  = (const float*)d_in[3];
    const float* dd_g1  = (const float*)d_in[4];
    const float* dd_be1 = (const float*)d_in[5];
    const float* dd_w2  = (const float*)d_in[6];
    const float* dd_b2  = (const float*)d_in[7];
    const float* dd_w3  = (const float*)d_in[8];
    const float* dd_b3  = (const float*)d_in[9];
    const float* cal_w1 = (const float*)d_in[10];
    const float* cal_b1 = (const float*)d_in[11];
    const float* cal_g1 = (const float*)d_in[12];
    const float* cal_be1= (const float*)d_in[13];
    const float* cal_w2 = (const float*)d_in[14];
    const float* cal_b2 = (const float*)d_in[15];
    const float* cal_w3 = (const float*)d_in[16];
    const float* cal_b3 = (const float*)d_in[17];

    float* out = (float*)d_out;
    const long long PTD = (long long)Pn * Tn * Dn;
    const long long BP  = (long long)Bn * Pn;

    bool has_drift = (long long)out_size >= PTD + BP;
    bool has_flag  = (long long)out_size >= PTD + BP + Pn;

    float* drift_ptr = nullptr;
    if (has_drift) {
        drift_ptr = out + PTD;
    } else {
        cudaGetSymbolAddress((void**)&drift_ptr, g_drift);
    }
    float* flag_ptr = has_flag ? (out + PTD + BP) : nullptr;

    float *p_centers, *p_ncT, *p_nf, *p_bias2, *p_z1, *p_a1, *p_h2, *p_z2, *p_a2, *p_c2, *p_delta;
    cudaGetSymbolAddress((void**)&p_centers, g_centers);
    cudaGetSymbolAddress((void**)&p_ncT,     g_ncT);
    cudaGetSymbolAddress((void**)&p_nf,      g_nf);
    cudaGetSymbolAddress((void**)&p_bias2,   g_bias2);
    cudaGetSymbolAddress((void**)&p_z1,      g_z1);
    cudaGetSymbolAddress((void**)&p_a1,      g_a1);
    cudaGetSymbolAddress((void**)&p_h2,      g_h2);
    cudaGetSymbolAddress((void**)&p_z2,      g_z2);
    cudaGetSymbolAddress((void**)&p_a2,      g_a2);
    cudaGetSymbolAddress((void**)&p_c2,      g_c2);
    cudaGetSymbolAddress((void**)&p_delta,   g_delta);

    // 1: fused T-mean reductions
    reduce_centers_kernel<<<Pn + Bn, Dn>>>(proto, feat);
    // 2: partial global mean + fold gm @ dd_w1[D:2D] into bias2
    gm_partial_kernel<<<8, Dn>>>();
    bias2_kernel<<<8, 512>>>(dd_w1, dd_b1);

    // 3: drift score GEMM  [B,P] = 1 - nf @ ncT  (256 blocks, 128 thr)
    gemm_tc<128, 64, 2, 2, 2, 128><<<dim3(Pn / 64, Bn / 128), 128>>>(
        p_nf, p_ncT, nullptr, drift_ptr, Bn, Pn, Dn);
    // 4: column mean -> is_drifted
    colmean_kernel<<<Pn / 32, 256>>>(drift_ptr, flag_ptr);

    // 5-7: drift-detector MLP (K halved: gm half folded into bias2)
    gemm_tc<128, 64, 2, 2, 0, 128><<<dim3(Hn / 64, Pn / 128), 128>>>(
        p_centers, dd_w1, p_bias2, p_z1, Pn, Hn, Dn);
    ln_relu_kernel<<<Pn, 256>>>(p_z1, dd_g1, dd_be1, p_a1);
    gemm_tc<64, 64, 1, 2, 1, 64><<<dim3((Hn / 2) / 64, Pn / 64), 64>>>(
        p_a1, dd_w2, dd_b2, p_h2, Pn, Hn / 2, Hn);
    gemv_sig_kernel<<<Pn, 256>>>(dd_w3, dd_b3);

    // 8-11: calibration MLP
    gemm_tc<128, 64, 2, 2, 0, 128><<<dim3(Hn / 64, Pn / 128), 128>>>(
        p_centers, cal_w1, cal_b1, p_z2, Pn, Hn, Dn);
    ln_relu_kernel<<<Pn, 256>>>(p_z2, cal_g1, cal_be1, p_a2);
    gemm_tc<128, 64, 2, 2, 1, 128><<<dim3(Hn / 64, Pn / 128), 128>>>(
        p_a2, cal_w2, cal_b2, p_c2, Pn, Hn, Hn);
    gemm_tc<64, 64, 1, 2, 0, 64><<<dim3(Dn / 64, Pn / 64), 64>>>(
        p_c2, cal_w3, cal_b3, p_delta, Pn, Dn, Hn);

    // 12: new centers
    newc_kernel<<<(Pn * Dn) / 256, 256>>>();
    // 13: scatter calibrated output
    scatter_kernel<<<(int)(PTD / 4 / 256), 256>>>(proto, out);
}

// round 8
// speedup vs baseline: 1.8560x; 1.2970x over previous
#include <cuda_runtime.h>
#include <math.h>
#include <stdint.h>

// Problem dims
#define Bn 1024
#define Tn 64
#define Dn 256
#define Pn 2048
#define Hn 512

#define THRESHOLD 0.3f
#define STRENGTH 0.1f
#define MIN_S 0.0f
#define MAX_S 0.5f
#define EPS_COS 1e-8f
#define EPS_LN 1e-5f

// ---------------- scratch (static device globals; no allocations) -------------
__device__ float g_centers[Pn * Dn];
__device__ float g_ncT[Dn * Pn];
__device__ float g_nf[Bn * Dn];
__device__ float g_fcent[Bn * Dn];
__device__ float g_gmp[8][Dn];
__device__ float g_bias2[Hn];
__device__ float g_drift[Bn * Pn];
__device__ float g_flag[Pn];
__device__ float g_z1[Pn * Hn];
__device__ float g_a1[Pn * Hn];
__device__ float g_h2[Pn * (Hn / 2)];
__device__ float g_conf[Pn];
__device__ float g_z2[Pn * Hn];
__device__ float g_a2[Pn * Hn];
__device__ float g_c2[Pn * Hn];
__device__ float g_newc[Pn * Dn];

// ---------------- fused T-mean reductions (proto + feat in one launch) --------
__global__ void __launch_bounds__(Dn) reduce_centers_kernel(
    const float* __restrict__ proto, const float* __restrict__ feat)
{
    int blk = blockIdx.x;
    int d = threadIdx.x;
    bool isP = blk < Pn;
    int row = isP ? blk : (blk - Pn);
    const float* base = (isP ? proto : feat) + (size_t)row * Tn * Dn + d;
    float s = 0.f;
#pragma unroll 16
    for (int t = 0; t < Tn; t++) s += base[t * Dn];
    float c = s * (1.0f / Tn);

    __shared__ float red[Dn];
    red[d] = c * c;
    __syncthreads();
    for (int o = Dn / 2; o > 0; o >>= 1) {
        if (d < o) red[d] += red[d + o];
        __syncthreads();
    }
    float nrm = fmaxf(sqrtf(red[0]), EPS_COS);
    if (isP) {
        g_centers[row * Dn + d] = c;
        g_ncT[(size_t)d * Pn + row] = c / nrm;
    } else {
        g_fcent[row * Dn + d] = c;
        g_nf[row * Dn + d] = c / nrm;
    }
}

// partial global_mean over B: 8 blocks, each sums 128 rows
__global__ void __launch_bounds__(Dn) gm_partial_kernel() {
    int i = blockIdx.x;
    int d = threadIdx.x;
    float s = 0.f;
    int b0 = i * (Bn / 8);
#pragma unroll 8
    for (int b = 0; b < Bn / 8; b++) s += g_fcent[(b0 + b) * Dn + d];
    g_gmp[i][d] = s;
}

// bias2[h] = dd_b1[h] + sum_d gm[d] * dd_w1[D + d][h]
__global__ void __launch_bounds__(512) bias2_kernel(const float* __restrict__ dd_w1,
                                                    const float* __restrict__ dd_b1) {
    int hx = threadIdx.x & 63;
    int dg = threadIdx.x >> 6;
    int h = blockIdx.x * 64 + hx;
    float s = 0.f;
#pragma unroll 8
    for (int j = 0; j < 32; j++) {
        int d = dg * 32 + j;
        float gm = 0.f;
#pragma unroll
        for (int q = 0; q < 8; q++) gm += g_gmp[q][d];
        gm *= (1.0f / Bn);
        s += gm * dd_w1[(size_t)(Dn + d) * Hn + h];
    }
    __shared__ float red[8][64];
    red[dg][hx] = s;
    __syncthreads();
    if (dg == 0) {
        float t = 0.f;
#pragma unroll
        for (int q = 0; q < 8; q++) t += red[q][hx];
        g_bias2[h] = dd_b1[h] + t;
    }
}

// ---------------- mma helpers -------------------------------------------------
__device__ __forceinline__ void mma_tf32(float* c,
                                         uint32_t a0, uint32_t a1, uint32_t a2, uint32_t a3,
                                         uint32_t b0, uint32_t b1) {
    asm volatile(
        "mma.sync.aligned.m16n8k8.row.col.f32.tf32.tf32.f32 "
        "{%0,%1,%2,%3}, {%4,%5,%6,%7}, {%8,%9}, {%0,%1,%2,%3};\n"
        : "+f"(c[0]), "+f"(c[1]), "+f"(c[2]), "+f"(c[3])
        : "r"(a0), "r"(a1), "r"(a2), "r"(a3), "r"(b0), "r"(b1));
}

__device__ __forceinline__ void cp16(void* smem, const void* gmem) {
    uint32_t sa = (uint32_t)__cvta_generic_to_shared(smem);
    asm volatile("cp.async.cg.shared.global [%0], [%1], 16;\n" :: "r"(sa), "l"(gmem));
}
__device__ __forceinline__ void cp_commit() {
    asm volatile("cp.async.commit_group;\n");
}
__device__ __forceinline__ void cp_wait1() {
    asm volatile("cp.async.wait_group 1;\n");
}

// ---- cp.async 3-stage pipelined tf32 GEMM: C[M,N] = act(A[M,K] @ W[K,N] + bias)
// ACT: 0 = bias, 1 = relu(bias), 2 = (1 - acc) no bias,
//      3 = centers + clip(STRENGTH*conf[m],MIN,MAX) * (acc + bias)   (fused newc)
// A raw fp32 is fed to mma.tf32 (hardware ignores low mantissa bits).
template<int BM, int BN, int WM, int WN, int ACT, int NT>
__global__ void __launch_bounds__(NT) gemm_ca(
    const float* __restrict__ A, const float* __restrict__ W,
    const float* __restrict__ bias, float* __restrict__ C,
    const float* __restrict__ conf, const float* __restrict__ centers,
    int M, int N, int K)
{
    constexpr int BK = 16;
    constexpr int S  = 3;                 // pipeline stages
    constexpr int PAA = 4;                // As row stride 20 floats (banks: 20g+tg all distinct)
    constexpr int PAB = 8;                // Bs row stride = 8 mod 32 (banks: 8tg+g all distinct)
    constexpr int WTM = BM / WM;
    constexpr int WTN = BN / WN;
    constexpr int MI = WTM / 16;
    constexpr int NI = WTN / 8;

    __shared__ __align__(16) float As[S][BM][BK + PAA];
    __shared__ __align__(16) float Bs[S][BK][BN + PAB];

    const int t = threadIdx.x;
    const int warp = t >> 5;
    const int lane = t & 31;
    const int g  = lane >> 2;
    const int tg = lane & 3;
    const int wm = warp / WN;
    const int wn = warp % WN;

    const int m0 = blockIdx.y * BM;
    const int n0 = blockIdx.x * BN;

    const float* Abase = A + (size_t)m0 * K;
    const float* Wbase = W + n0;

    // chunk mapping (16B each)
    constexpr int CA = (BM * BK / 4) / NT;        // A chunks per thread
    constexpr int CB = (BK * BN / 4) / NT;        // B chunks per thread
    const int KB = K / BK;

    auto issue = [&](int st, int kb) {
#pragma unroll
        for (int i = 0; i < CA; i++) {
            int c = t + i * NT;
            int row = c >> 2;
            int col = (c & 3) * 4;
            cp16(&As[st][row][col], Abase + (size_t)row * K + kb * BK + col);
        }
#pragma unroll
        for (int i = 0; i < CB; i++) {
            int c = t + i * NT;
            int row = c / (BN / 4);
            int col = (c % (BN / 4)) * 4;
            cp16(&Bs[st][row][col], Wbase + (size_t)(kb * BK + row) * N + col);
        }
    };

    float acc[MI][NI][4];
#pragma unroll
    for (int mi = 0; mi < MI; mi++)
#pragma unroll
        for (int ni = 0; ni < NI; ni++)
#pragma unroll
            for (int q = 0; q < 4; q++) acc[mi][ni][q] = 0.f;

    // prologue: stages 0..S-2
#pragma unroll
    for (int st = 0; st < S - 1; st++) { issue(st, st); cp_commit(); }

    for (int kb = 0; kb < KB; kb++) {
        cp_wait1();
        __syncthreads();
        int nl = kb + S - 1;
        if (nl < KB) issue(nl % S, nl);
        cp_commit();

        int cs = kb % S;
#pragma unroll
        for (int ks = 0; ks < BK; ks += 8) {
            uint32_t af[MI][4], bf[NI][2];
#pragma unroll
            for (int mi = 0; mi < MI; mi++) {
                int m = wm * WTM + mi * 16 + g;
                af[mi][0] = __float_as_uint(As[cs][m][ks + tg]);
                af[mi][1] = __float_as_uint(As[cs][m + 8][ks + tg]);
                af[mi][2] = __float_as_uint(As[cs][m][ks + tg + 4]);
                af[mi][3] = __float_as_uint(As[cs][m + 8][ks + tg + 4]);
            }
#pragma unroll
            for (int ni = 0; ni < NI; ni++) {
                int n = wn * WTN + ni * 8 + g;
                bf[ni][0] = __float_as_uint(Bs[cs][ks + tg][n]);
                bf[ni][1] = __float_as_uint(Bs[cs][ks + tg + 4][n]);
            }
#pragma unroll
            for (int mi = 0; mi < MI; mi++)
#pragma unroll
                for (int ni = 0; ni < NI; ni++)
                    mma_tf32(acc[mi][ni],
                             af[mi][0], af[mi][1], af[mi][2], af[mi][3],
                             bf[ni][0], bf[ni][1]);
        }
    }

    // epilogue
#pragma unroll
    for (int mi = 0; mi < MI; mi++) {
#pragma unroll
        for (int ni = 0; ni < NI; ni++) {
            int m = m0 + wm * WTM + mi * 16 + g;
            int n = n0 + wn * WTN + ni * 8 + tg * 2;
            float b0 = 0.f, b1 = 0.f;
            if (ACT != 2) { b0 = bias[n]; b1 = bias[n + 1]; }
            float2 v0, v1;
            if (ACT == 2) {
                v0.x = 1.0f - acc[mi][ni][0]; v0.y = 1.0f - acc[mi][ni][1];
                v1.x = 1.0f - acc[mi][ni][2]; v1.y = 1.0f - acc[mi][ni][3];
            } else if (ACT == 3) {
                float s0 = fminf(fmaxf(STRENGTH * conf[m], MIN_S), MAX_S);
                float s1 = fminf(fmaxf(STRENGTH * conf[m + 8], MIN_S), MAX_S);
                v0.x = centers[(size_t)m * N + n]           + s0 * (acc[mi][ni][0] + b0);
                v0.y = centers[(size_t)m * N + n + 1]       + s0 * (acc[mi][ni][1] + b1);
                v1.x = centers[(size_t)(m + 8) * N + n]     + s1 * (acc[mi][ni][2] + b0);
                v1.y = centers[(size_t)(m + 8) * N + n + 1] + s1 * (acc[mi][ni][3] + b1);
            } else {
                v0.x = acc[mi][ni][0] + b0;   v0.y = acc[mi][ni][1] + b1;
                v1.x = acc[mi][ni][2] + b0;   v1.y = acc[mi][ni][3] + b1;
                if (ACT == 1) {
                    v0.x = fmaxf(v0.x, 0.f); v0.y = fmaxf(v0.y, 0.f);
                    v1.x = fmaxf(v1.x, 0.f); v1.y = fmaxf(v1.y, 0.f);
                }
            }
            *(float2*)&C[(size_t)m * N + n]       = v0;
            *(float2*)&C[(size_t)(m + 8) * N + n] = v1;
        }
    }
}

// mean over B of drift column p -> flag. 64 blocks x (32 p, 8 b-slices)
__global__ void __launch_bounds__(256) colmean_kernel(const float* __restrict__ drift,
                                                      float* __restrict__ out_flag) {
    int tx = threadIdx.x & 31;
    int ty = threadIdx.x >> 5;
    int p = blockIdx.x * 32 + tx;
    float s = 0.f;
#pragma unroll 8
    for (int b = ty; b < Bn; b += 8)
        s += drift[(size_t)b * Pn + p];
    __shared__ float red[8][33];
    red[ty][tx] = s;
    __syncthreads();
    if (ty == 0) {
        float t = red[0][tx];
#pragma unroll
        for (int q = 1; q < 8; q++) t += red[q][tx];
        float fl = (t * (1.0f / Bn) > THRESHOLD) ? 1.0f : 0.0f;
        g_flag[p] = fl;
        if (out_flag) out_flag[p] = fl;
    }
}

// layernorm + relu over rows of width H=512
__global__ void __launch_bounds__(256) ln_relu_kernel(const float* __restrict__ z,
                                                      const float* __restrict__ g,
                                                      const float* __restrict__ be,
                                                      float* __restrict__ out) {
    int r = blockIdx.x;
    int d = threadIdx.x;
    const float* row = z + (size_t)r * Hn;
    float v0 = row[d], v1 = row[d + 256];

    __shared__ float red[256];
    red[d] = v0 + v1;
    __syncthreads();
    for (int o = 128; o > 0; o >>= 1) {
        if (d < o) red[d] += red[d + o];
        __syncthreads();
    }
    float mu = red[0] * (1.0f / Hn);
    __syncthreads();

    float d0 = v0 - mu, d1 = v1 - mu;
    red[d] = d0 * d0 + d1 * d1;
    __syncthreads();
    for (int o = 128; o > 0; o >>= 1) {
        if (d < o) red[d] += red[d + o];
        __syncthreads();
    }
    float var = red[0] * (1.0f / Hn);
    float rs = rsqrtf(var + EPS_LN);

    float* orow = out + (size_t)r * Hn;
    orow[d]       = fmaxf(d0 * rs * g[d] + be[d], 0.f);
    orow[d + 256] = fmaxf(d1 * rs * g[d + 256] + be[d + 256], 0.f);
}

// conf[p] = sigmoid(dot(h2[p], w3) + b3)
__global__ void __launch_bounds__(256) gemv_sig_kernel(const float* __restrict__ w3,
                                                       const float* __restrict__ b3) {
    int p = blockIdx.x;
    int d = threadIdx.x;
    float s = g_h2[(size_t)p * (Hn / 2) + d] * w3[d];
    __shared__ float red[256];
    red[d] = s;
    __syncthreads();
    for (int o = 128; o > 0; o >>= 1) {
        if (d < o) red[d] += red[d + o];
        __syncthreads();
    }
    if (d == 0) {
        float x = red[0] + b3[0];
        g_conf[p] = 1.0f / (1.0f + expf(-x));
    }
}

// calibrated[p][t][d] = flag[p] ? new_center[p][d] : prototype[p][t][d]
__global__ void __launch_bounds__(256) scatter_kernel(const float* __restrict__ proto,
                                                      float* __restrict__ out) {
    int i = blockIdx.x * 256 + threadIdx.x;
    int p = i >> 12;
    int r = i & 4095;
    int d4 = r & 63;
    float4 v;
    if (g_flag[p] > 0.5f) {
        v = ((const float4*)g_newc)[(p << 6) + d4];
    } else {
        v = ((const float4*)proto)[i];
    }
    ((float4*)out)[i] = v;
}

// ---------------- launch ------------------------------------------------------
extern "C" void kernel_launch(void* const* d_in, const int* in_sizes, int n_in,
                              void* d_out, int out_size) {
    (void)in_sizes; (void)n_in;
    const float* feat   = (const float*)d_in[0];
    const float* proto  = (const float*)d_in[1];
    const float* dd_w1  = (const float*)d_in[2];
    const float* dd_b1  = (const float*)d_in[3];
    const float* dd_g1  = (const float*)d_in[4];
    const float* dd_be1 = (const float*)d_in[5];
    const float* dd_w2  = (const float*)d_in[6];
    const float* dd_b2  = (const float*)d_in[7];
    const float* dd_w3  = (const float*)d_in[8];
    const float* dd_b3  = (const float*)d_in[9];
    const float* cal_w1 = (const float*)d_in[10];
    const float* cal_b1 = (const float*)d_in[11];
    const float* cal_g1 = (const float*)d_in[12];
    const float* cal_be1= (const float*)d_in[13];
    const float* cal_w2 = (const float*)d_in[14];
    const float* cal_b2 = (const float*)d_in[15];
    const float* cal_w3 = (const float*)d_in[16];
    const float* cal_b3 = (const float*)d_in[17];

    float* out = (float*)d_out;
    const long long PTD = (long long)Pn * Tn * Dn;
    const long long BP  = (long long)Bn * Pn;

    bool has_drift = (long long)out_size >= PTD + BP;
    bool has_flag  = (long long)out_size >= PTD + BP + Pn;

    float* drift_ptr = nullptr;
    if (has_drift) {
        drift_ptr = out + PTD;
    } else {
        cudaGetSymbolAddress((void**)&drift_ptr, g_drift);
    }
    float* flag_ptr = has_flag ? (out + PTD + BP) : nullptr;

    float *p_centers, *p_ncT, *p_nf, *p_bias2, *p_z1, *p_a1, *p_h2, *p_conf,
          *p_z2, *p_a2, *p_c2, *p_newc;
    cudaGetSymbolAddress((void**)&p_centers, g_centers);
    cudaGetSymbolAddress((void**)&p_ncT,     g_ncT);
    cudaGetSymbolAddress((void**)&p_nf,      g_nf);
    cudaGetSymbolAddress((void**)&p_bias2,   g_bias2);
    cudaGetSymbolAddress((void**)&p_z1,      g_z1);
    cudaGetSymbolAddress((void**)&p_a1,      g_a1);
    cudaGetSymbolAddress((void**)&p_h2,      g_h2);
    cudaGetSymbolAddress((void**)&p_conf,    g_conf);
    cudaGetSymbolAddress((void**)&p_z2,      g_z2);
    cudaGetSymbolAddress((void**)&p_a2,      g_a2);
    cudaGetSymbolAddress((void**)&p_c2,      g_c2);
    cudaGetSymbolAddress((void**)&p_newc,    g_newc);

    // 1: fused T-mean reductions
    reduce_centers_kernel<<<Pn + Bn, Dn>>>(proto, feat);
    // 2: partial global mean + fold gm @ dd_w1[D:2D] into bias2
    gm_partial_kernel<<<8, Dn>>>();
    bias2_kernel<<<8, 512>>>(dd_w1, dd_b1);

    // 3: drift score GEMM  [B,P] = 1 - nf @ ncT
    gemm_ca<64, 128, 1, 4, 2, 128><<<dim3(Pn / 128, Bn / 64), 128>>>(
        p_nf, p_ncT, nullptr, drift_ptr, nullptr, nullptr, Bn, Pn, Dn);
    // 4: column mean -> is_drifted
    colmean_kernel<<<Pn / 32, 256>>>(drift_ptr, flag_ptr);

    // 5-7: drift-detector MLP (gm half folded into bias2)
    gemm_ca<64, 128, 1, 4, 0, 128><<<dim3(Hn / 128, Pn / 64), 128>>>(
        p_centers, dd_w1, p_bias2, p_z1, nullptr, nullptr, Pn, Hn, Dn);
    ln_relu_kernel<<<Pn, 256>>>(p_z1, dd_g1, dd_be1, p_a1);
    gemm_ca<64, 64, 2, 2, 1, 128><<<dim3((Hn / 2) / 64, Pn / 64), 128>>>(
        p_a1, dd_w2, dd_b2, p_h2, nullptr, nullptr, Pn, Hn / 2, Hn);
    gemv_sig_kernel<<<Pn, 256>>>(dd_w3, dd_b3);

    // 8-11: calibration MLP; final GEMM fuses new_center epilogue
    gemm_ca<64, 128, 1, 4, 0, 128><<<dim3(Hn / 128, Pn / 64), 128>>>(
        p_centers, cal_w1, cal_b1, p_z2, nullptr, nullptr, Pn, Hn, Dn);
    ln_relu_kernel<<<Pn, 256>>>(p_z2, cal_g1, cal_be1, p_a2);
    gemm_ca<64, 128, 1, 4, 1, 128><<<dim3(Hn / 128, Pn / 64), 128>>>(
        p_a2, cal_w2, cal_b2, p_c2, nullptr, nullptr, Pn, Hn, Hn);
    gemm_ca<64, 64, 2, 2, 3, 128><<<dim3(Dn / 64, Pn / 64), 128>>>(
        p_c2, cal_w3, cal_b3, p_newc, p_conf, p_centers, Pn, Dn, Hn);

    // 12: scatter calibrated output
    scatter_kernel<<<(int)(PTD / 4 / 256), 256>>>(proto, out);
}

// round 10
// speedup vs baseline: 1.9057x; 1.0268x over previous
#include <cuda_runtime.h>
#include <math.h>
#include <stdint.h>

// Problem dims
#define Bn 1024
#define Tn 64
#define Dn 256
#define Pn 2048
#define Hn 512

#define THRESHOLD 0.3f
#define STRENGTH 0.1f
#define MIN_S 0.0f
#define MAX_S 0.5f
#define EPS_COS 1e-8f
#define EPS_LN 1e-5f

// ---------------- scratch (static device globals; no allocations) -------------
__device__ float g_centers[Pn * Dn];
__device__ float g_ncT[Dn * Pn];
__device__ float g_nf[Bn * Dn];
__device__ float g_fcent[Bn * Dn];
__device__ float g_gmp[8][Dn];
__device__ float g_bias2[Hn];
__device__ float g_drift[Bn * Pn];
__device__ float g_flag[Pn];
__device__ float g_z1[Pn * Hn];
__device__ float g_a1[Pn * Hn];
__device__ float g_h2[Pn * (Hn / 2)];
__device__ float g_conf[Pn];
__device__ float g_z2[Pn * Hn];
__device__ float g_a2[Pn * Hn];
__device__ float g_c2[Pn * Hn];
__device__ float g_newc[Pn * Dn];

// ---------------- fused T-mean reductions (proto + feat in one launch) --------
__global__ void __launch_bounds__(Dn) reduce_centers_kernel(
    const float* __restrict__ proto, const float* __restrict__ feat)
{
    int blk = blockIdx.x;
    int d = threadIdx.x;
    bool isP = blk < Pn;
    int row = isP ? blk : (blk - Pn);
    const float* base = (isP ? proto : feat) + (size_t)row * Tn * Dn + d;
    float s = 0.f;
#pragma unroll 16
    for (int t = 0; t < Tn; t++) s += base[t * Dn];
    float c = s * (1.0f / Tn);

    __shared__ float red[Dn];
    red[d] = c * c;
    __syncthreads();
    for (int o = Dn / 2; o > 0; o >>= 1) {
        if (d < o) red[d] += red[d + o];
        __syncthreads();
    }
    float nrm = fmaxf(sqrtf(red[0]), EPS_COS);
    if (isP) {
        g_centers[row * Dn + d] = c;
        g_ncT[(size_t)d * Pn + row] = c / nrm;
    } else {
        g_fcent[row * Dn + d] = c;
        g_nf[row * Dn + d] = c / nrm;
    }
}

// partial global_mean over B: 8 blocks, each sums 128 rows
__global__ void __launch_bounds__(Dn) gm_partial_kernel() {
    int i = blockIdx.x;
    int d = threadIdx.x;
    float s = 0.f;
    int b0 = i * (Bn / 8);
#pragma unroll 8
    for (int b = 0; b < Bn / 8; b++) s += g_fcent[(b0 + b) * Dn + d];
    g_gmp[i][d] = s;
}

// bias2[h] = dd_b1[h] + sum_d gm[d] * dd_w1[D + d][h]
__global__ void __launch_bounds__(512) bias2_kernel(const float* __restrict__ dd_w1,
                                                    const float* __restrict__ dd_b1) {
    int hx = threadIdx.x & 63;
    int dg = threadIdx.x >> 6;
    int h = blockIdx.x * 64 + hx;
    float s = 0.f;
#pragma unroll 8
    for (int j = 0; j < 32; j++) {
        int d = dg * 32 + j;
        float gm = 0.f;
#pragma unroll
        for (int q = 0; q < 8; q++) gm += g_gmp[q][d];
        gm *= (1.0f / Bn);
        s += gm * dd_w1[(size_t)(Dn + d) * Hn + h];
    }
    __shared__ float red[8][64];
    red[dg][hx] = s;
    __syncthreads();
    if (dg == 0) {
        float t = 0.f;
#pragma unroll
        for (int q = 0; q < 8; q++) t += red[q][hx];
        g_bias2[h] = dd_b1[h] + t;
    }
}

// ---------------- mma helpers -------------------------------------------------
__device__ __forceinline__ void mma_tf32(float* c,
                                         uint32_t a0, uint32_t a1, uint32_t a2, uint32_t a3,
                                         uint32_t b0, uint32_t b1) {
    asm volatile(
        "mma.sync.aligned.m16n8k8.row.col.f32.tf32.tf32.f32 "
        "{%0,%1,%2,%3}, {%4,%5,%6,%7}, {%8,%9}, {%0,%1,%2,%3};\n"
        : "+f"(c[0]), "+f"(c[1]), "+f"(c[2]), "+f"(c[3])
        : "r"(a0), "r"(a1), "r"(a2), "r"(a3), "r"(b0), "r"(b1));
}

__device__ __forceinline__ void cp16(void* smem, const void* gmem) {
    uint32_t sa = (uint32_t)__cvta_generic_to_shared(smem);
    asm volatile("cp.async.cg.shared.global [%0], [%1], 16;\n" :: "r"(sa), "l"(gmem));
}
__device__ __forceinline__ void cp_commit() {
    asm volatile("cp.async.commit_group;\n");
}
__device__ __forceinline__ void cp_wait1() {
    asm volatile("cp.async.wait_group 1;\n");
}

// per-z grouped GEMM descriptor
struct GB {
    const float* A[3];
    const float* W[3];
    const float* bias[3];
    float*       C[3];
    int          ldw[3];
    int          ldc[3];
};

// ---- grouped cp.async 3-stage pipelined tf32 GEMM.
// Per z-slice: C[M, ...] = act(A[M,K] @ W[K, Nslice] + bias), strides per z.
// ACT: 0 = bias, 1 = relu(bias), 2 = (1 - acc) no bias,
//      3 = centers + clip(STRENGTH*conf[m]) * (acc + bias)   (fused new_center)
template<int BM, int BN, int WM, int WN, int ACT, int NT>
__global__ void __launch_bounds__(NT) gemm_gb(
    GB gb, int K,
    const float* __restrict__ conf, const float* __restrict__ centers)
{
    constexpr int BK = 16;
    constexpr int S  = 3;
    constexpr int PAA = 4;                // As row stride 20 -> conflict-free frags
    constexpr int PAB = 8;                // Bs row stride %32 == 8 -> conflict-free
    constexpr int WTM = BM / WM;
    constexpr int WTN = BN / WN;
    constexpr int MI = WTM / 16;
    constexpr int NI = WTN / 8;

    __shared__ __align__(16) float As[S][BM][BK + PAA];
    __shared__ __align__(16) float Bs[S][BK][BN + PAB];

    const int t = threadIdx.x;
    const int warp = t >> 5;
    const int lane = t & 31;
    const int g  = lane >> 2;
    const int tg = lane & 3;
    const int wm = warp / WN;
    const int wn = warp % WN;

    const int z  = blockIdx.z;
    const int m0 = blockIdx.y * BM;
    const int n0 = blockIdx.x * BN;
    const int ldw = gb.ldw[z];
    const int ldc = gb.ldc[z];

    const float* Abase = gb.A[z] + (size_t)m0 * K;
    const float* Wbase = gb.W[z] + n0;

    constexpr int CA = (BM * BK / 4) / NT;
    constexpr int CB = (BK * BN / 4) / NT;
    const int KB = K / BK;

    auto issue = [&](int st, int kb) {
#pragma unroll
        for (int i = 0; i < CA; i++) {
            int c = t + i * NT;
            int row = c / (BK / 4);
            int col = (c % (BK / 4)) * 4;
            cp16(&As[st][row][col], Abase + (size_t)row * K + kb * BK + col);
        }
#pragma unroll
        for (int i = 0; i < CB; i++) {
            int c = t + i * NT;
            int row = c / (BN / 4);
            int col = (c % (BN / 4)) * 4;
            cp16(&Bs[st][row][col], Wbase + (size_t)(kb * BK + row) * ldw + col);
        }
    };

    float acc[MI][NI][4];
#pragma unroll
    for (int mi = 0; mi < MI; mi++)
#pragma unroll
        for (int ni = 0; ni < NI; ni++)
#pragma unroll
            for (int q = 0; q < 4; q++) acc[mi][ni][q] = 0.f;

#pragma unroll
    for (int st = 0; st < S - 1; st++) { issue(st, st); cp_commit(); }

    for (int kb = 0; kb < KB; kb++) {
        cp_wait1();
        __syncthreads();
        int nl = kb + S - 1;
        if (nl < KB) issue(nl % S, nl);
        cp_commit();

        int cs = kb % S;
#pragma unroll
        for (int ks = 0; ks < BK; ks += 8) {
            uint32_t af[MI][4], bf[NI][2];
#pragma unroll
            for (int mi = 0; mi < MI; mi++) {
                int m = wm * WTM + mi * 16 + g;
                af[mi][0] = __float_as_uint(As[cs][m][ks + tg]);
                af[mi][1] = __float_as_uint(As[cs][m + 8][ks + tg]);
                af[mi][2] = __float_as_uint(As[cs][m][ks + tg + 4]);
                af[mi][3] = __float_as_uint(As[cs][m + 8][ks + tg + 4]);
            }
#pragma unroll
            for (int ni = 0; ni < NI; ni++) {
                int n = wn * WTN + ni * 8 + g;
                bf[ni][0] = __float_as_uint(Bs[cs][ks + tg][n]);
                bf[ni][1] = __float_as_uint(Bs[cs][ks + tg + 4][n]);
            }
#pragma unroll
            for (int mi = 0; mi < MI; mi++)
#pragma unroll
                for (int ni = 0; ni < NI; ni++)
                    mma_tf32(acc[mi][ni],
                             af[mi][0], af[mi][1], af[mi][2], af[mi][3],
                             bf[ni][0], bf[ni][1]);
        }
    }

    const float* bias = gb.bias[z];
    float* C = gb.C[z];

#pragma unroll
    for (int mi = 0; mi < MI; mi++) {
#pragma unroll
        for (int ni = 0; ni < NI; ni++) {
            int m = m0 + wm * WTM + mi * 16 + g;
            int n = n0 + wn * WTN + ni * 8 + tg * 2;
            float b0 = 0.f, b1 = 0.f;
            if (ACT != 2) { b0 = bias[n]; b1 = bias[n + 1]; }
            float2 v0, v1;
            if (ACT == 2) {
                v0.x = 1.0f - acc[mi][ni][0]; v0.y = 1.0f - acc[mi][ni][1];
                v1.x = 1.0f - acc[mi][ni][2]; v1.y = 1.0f - acc[mi][ni][3];
            } else if (ACT == 3) {
                float s0 = fminf(fmaxf(STRENGTH * conf[m], MIN_S), MAX_S);
                float s1 = fminf(fmaxf(STRENGTH * conf[m + 8], MIN_S), MAX_S);
                v0.x = centers[(size_t)m * ldc + n]           + s0 * (acc[mi][ni][0] + b0);
                v0.y = centers[(size_t)m * ldc + n + 1]       + s0 * (acc[mi][ni][1] + b1);
                v1.x = centers[(size_t)(m + 8) * ldc + n]     + s1 * (acc[mi][ni][2] + b0);
                v1.y = centers[(size_t)(m + 8) * ldc + n + 1] + s1 * (acc[mi][ni][3] + b1);
            } else {
                v0.x = acc[mi][ni][0] + b0;   v0.y = acc[mi][ni][1] + b1;
                v1.x = acc[mi][ni][2] + b0;   v1.y = acc[mi][ni][3] + b1;
                if (ACT == 1) {
                    v0.x = fmaxf(v0.x, 0.f); v0.y = fmaxf(v0.y, 0.f);
                    v1.x = fmaxf(v1.x, 0.f); v1.y = fmaxf(v1.y, 0.f);
                }
            }
            *(float2*)&C[(size_t)m * ldc + n]       = v0;
            *(float2*)&C[(size_t)(m + 8) * ldc + n] = v1;
        }
    }
}

// mean over B of drift column p -> flag. 64 blocks x (32 p, 8 b-slices)
__global__ void __launch_bounds__(256) colmean_kernel(const float* __restrict__ drift,
                                                      float* __restrict__ out_flag) {
    int tx = threadIdx.x & 31;
    int ty = threadIdx.x >> 5;
    int p = blockIdx.x * 32 + tx;
    float s = 0.f;
#pragma unroll 8
    for (int b = ty; b < Bn; b += 8)
        s += drift[(size_t)b * Pn + p];
    __shared__ float red[8][33];
    red[ty][tx] = s;
    __syncthreads();
    if (ty == 0) {
        float t = red[0][tx];
#pragma unroll
        for (int q = 1; q < 8; q++) t += red[q][tx];
        float fl = (t * (1.0f / Bn) > THRESHOLD) ? 1.0f : 0.0f;
        g_flag[p] = fl;
        if (out_flag) out_flag[p] = fl;
    }
}

// batched layernorm+relu: blocks [0,Pn) -> z1/a1 (dd), [Pn,2Pn) -> z2/a2 (cal)
__global__ void __launch_bounds__(256) ln_relu2_kernel(
    const float* __restrict__ z1, const float* __restrict__ g1, const float* __restrict__ be1,
    float* __restrict__ o1,
    const float* __restrict__ z2, const float* __restrict__ g2, const float* __restrict__ be2,
    float* __restrict__ o2)
{
    int blk = blockIdx.x;
    bool first = blk < Pn;
    int r = first ? blk : blk - Pn;
    const float* z  = first ? z1 : z2;
    const float* g  = first ? g1 : g2;
    const float* be = first ? be1 : be2;
    float* out = first ? o1 : o2;

    int d = threadIdx.x;
    const float* row = z + (size_t)r * Hn;
    float v0 = row[d], v1 = row[d + 256];

    __shared__ float red[256];
    red[d] = v0 + v1;
    __syncthreads();
    for (int o = 128; o > 0; o >>= 1) {
        if (d < o) red[d] += red[d + o];
        __syncthreads();
    }
    float mu = red[0] * (1.0f / Hn);
    __syncthreads();

    float d0 = v0 - mu, d1 = v1 - mu;
    red[d] = d0 * d0 + d1 * d1;
    __syncthreads();
    for (int o = 128; o > 0; o >>= 1) {
        if (d < o) red[d] += red[d + o];
        __syncthreads();
    }
    float var = red[0] * (1.0f / Hn);
    float rs = rsqrtf(var + EPS_LN);

    float* orow = out + (size_t)r * Hn;
    orow[d]       = fmaxf(d0 * rs * g[d] + be[d], 0.f);
    orow[d + 256] = fmaxf(d1 * rs * g[d + 256] + be[d + 256], 0.f);
}

// conf[p] = sigmoid(dot(h2[p], w3) + b3)
__global__ void __launch_bounds__(256) gemv_sig_kernel(const float* __restrict__ w3,
                                                       const float* __restrict__ b3) {
    int p = blockIdx.x;
    int d = threadIdx.x;
    float s = g_h2[(size_t)p * (Hn / 2) + d] * w3[d];
    __shared__ float red[256];
    red[d] = s;
    __syncthreads();
    for (int o = 128; o > 0; o >>= 1) {
        if (d < o) red[d] += red[d + o];
        __syncthreads();
    }
    if (d == 0) {
        float x = red[0] + b3[0];
        g_conf[p] = 1.0f / (1.0f + expf(-x));
    }
}

// calibrated[p][t][d] = flag[p] ? new_center[p][d] : prototype[p][t][d]
__global__ void __launch_bounds__(256) scatter_kernel(const float* __restrict__ proto,
                                                      float* __restrict__ out) {
    int i = blockIdx.x * 256 + threadIdx.x;
    int p = i >> 12;
    int r = i & 4095;
    int d4 = r & 63;
    float4 v;
    if (g_flag[p] > 0.5f) {
        v = ((const float4*)g_newc)[(p << 6) + d4];
    } else {
        v = ((const float4*)proto)[i];
    }
    ((float4*)out)[i] = v;
}

// ---------------- launch ------------------------------------------------------
extern "C" void kernel_launch(void* const* d_in, const int* in_sizes, int n_in,
                              void* d_out, int out_size) {
    (void)in_sizes; (void)n_in;
    const float* feat   = (const float*)d_in[0];
    const float* proto  = (const float*)d_in[1];
    const float* dd_w1  = (const float*)d_in[2];
    const float* dd_b1  = (const float*)d_in[3];
    const float* dd_g1  = (const float*)d_in[4];
    const float* dd_be1 = (const float*)d_in[5];
    const float* dd_w2  = (const float*)d_in[6];
    const float* dd_b2  = (const float*)d_in[7];
    const float* dd_w3  = (const float*)d_in[8];
    const float* dd_b3  = (const float*)d_in[9];
    const float* cal_w1 = (const float*)d_in[10];
    const float* cal_b1 = (const float*)d_in[11];
    const float* cal_g1 = (const float*)d_in[12];
    const float* cal_be1= (const float*)d_in[13];
    const float* cal_w2 = (const float*)d_in[14];
    const float* cal_b2 = (const float*)d_in[15];
    const float* cal_w3 = (const float*)d_in[16];
    const float* cal_b3 = (const float*)d_in[17];

    float* out = (float*)d_out;
    const long long PTD = (long long)Pn * Tn * Dn;
    const long long BP  = (long long)Bn * Pn;

    bool has_drift = (long long)out_size >= PTD + BP;
    bool has_flag  = (long long)out_size >= PTD + BP + Pn;

    float* drift_ptr = nullptr;
    if (has_drift) {
        drift_ptr = out + PTD;
    } else {
        cudaGetSymbolAddress((void**)&drift_ptr, g_drift);
    }
    float* flag_ptr = has_flag ? (out + PTD + BP) : nullptr;

    float *p_centers, *p_ncT, *p_nf, *p_bias2, *p_z1, *p_a1, *p_h2, *p_conf,
          *p_z2, *p_a2, *p_c2, *p_newc;
    cudaGetSymbolAddress((void**)&p_centers, g_centers);
    cudaGetSymbolAddress((void**)&p_ncT,     g_ncT);
    cudaGetSymbolAddress((void**)&p_nf,      g_nf);
    cudaGetSymbolAddress((void**)&p_bias2,   g_bias2);
    cudaGetSymbolAddress((void**)&p_z1,      g_z1);
    cudaGetSymbolAddress((void**)&p_a1,      g_a1);
    cudaGetSymbolAddress((void**)&p_h2,      g_h2);
    cudaGetSymbolAddress((void**)&p_conf,    g_conf);
    cudaGetSymbolAddress((void**)&p_z2,      g_z2);
    cudaGetSymbolAddress((void**)&p_a2,      g_a2);
    cudaGetSymbolAddress((void**)&p_c2,      g_c2);
    cudaGetSymbolAddress((void**)&p_newc,    g_newc);

    // 1: fused T-mean reductions
    reduce_centers_kernel<<<Pn + Bn, Dn>>>(proto, feat);
    // 2: partial global mean + fold gm @ dd_w1[D:2D] into bias2
    gm_partial_kernel<<<8, Dn>>>();
    bias2_kernel<<<8, 512>>>(dd_w1, dd_b1);

    // 3: drift score GEMM  [B,P] = 1 - nf @ ncT   (512 blocks)
    {
        GB gb = {};
        gb.A[0] = p_nf; gb.W[0] = p_ncT; gb.bias[0] = nullptr;
        gb.C[0] = drift_ptr; gb.ldw[0] = Pn; gb.ldc[0] = Pn;
        gemm_gb<64, 64, 2, 2, 2, 128><<<dim3(Pn / 64, Bn / 64, 1), 128>>>(
            gb, Dn, nullptr, nullptr);
    }
    // 4: column mean -> is_drifted
    colmean_kernel<<<Pn / 32, 256>>>(drift_ptr, flag_ptr);

    // 5: batched layer-1 GEMMs (dd_w1 with folded bias2, cal_w1) -> z1, z2
    {
        GB gb = {};
        gb.A[0] = p_centers; gb.W[0] = dd_w1;  gb.bias[0] = p_bias2;
        gb.C[0] = p_z1; gb.ldw[0] = Hn; gb.ldc[0] = Hn;
        gb.A[1] = p_centers; gb.W[1] = cal_w1; gb.bias[1] = cal_b1;
        gb.C[1] = p_z2; gb.ldw[1] = Hn; gb.ldc[1] = Hn;
        gemm_gb<64, 64, 2, 2, 0, 128><<<dim3(Hn / 64, Pn / 64, 2), 128>>>(
            gb, Dn, nullptr, nullptr);
    }
    // 6: batched layernorm+relu (z1->a1, z2->a2)
    ln_relu2_kernel<<<2 * Pn, 256>>>(p_z1, dd_g1, dd_be1, p_a1,
                                     p_z2, cal_g1, cal_be1, p_a2);
    // 7: batched layer-2 GEMMs: dd_w2 (N=256) + cal_w2 split into two N=256 halves
    {
        GB gb = {};
        gb.A[0] = p_a1; gb.W[0] = dd_w2;        gb.bias[0] = dd_b2;
        gb.C[0] = p_h2;       gb.ldw[0] = Hn / 2; gb.ldc[0] = Hn / 2;
        gb.A[1] = p_a2; gb.W[1] = cal_w2;       gb.bias[1] = cal_b2;
        gb.C[1] = p_c2;       gb.ldw[1] = Hn;     gb.ldc[1] = Hn;
        gb.A[2] = p_a2; gb.W[2] = cal_w2 + 256; gb.bias[2] = cal_b2 + 256;
        gb.C[2] = p_c2 + 256; gb.ldw[2] = Hn;     gb.ldc[2] = Hn;
        gemm_gb<64, 64, 2, 2, 1, 128><<<dim3(256 / 64, Pn / 64, 3), 128>>>(
            gb, Hn, nullptr, nullptr);
    }
    // 8: drift confidence
    gemv_sig_kernel<<<Pn, 256>>>(dd_w3, dd_b3);
    // 9: final cal GEMM with fused new_center epilogue
    {
        GB gb = {};
        gb.A[0] = p_c2; gb.W[0] = cal_w3; gb.bias[0] = cal_b3;
        gb.C[0] = p_newc; gb.ldw[0] = Dn; gb.ldc[0] = Dn;
        gemm_gb<64, 64, 2, 2, 3, 128><<<dim3(Dn / 64, Pn / 64, 1), 128>>>(
            gb, Hn, p_conf, p_centers);
    }
    // 10: scatter calibrated output
    scatter_kernel<<<(int)(PTD / 4 / 256), 256>>>(proto, out);
}

// round 13
// speedup vs baseline: 2.0163x; 1.0580x over previous
#include <cuda_runtime.h>
#include <math.h>
#include <stdint.h>

// Problem dims
#define Bn 1024
#define Tn 64
#define Dn 256
#define Pn 2048
#define Hn 512

#define THRESHOLD 0.3f
#define STRENGTH 0.1f
#define MIN_S 0.0f
#define MAX_S 0.5f
#define EPS_COS 1e-8f
#define EPS_LN 1e-5f

// ---------------- scratch (static device globals; no allocations) -------------
__device__ float g_centers[Pn * Dn];
__device__ float g_ncT[Dn * Pn];
__device__ float g_nf[Bn * Dn];
__device__ float g_fcent[Bn * Dn];
__device__ float g_gmp[8][Dn];
__device__ float g_bias2[Hn];
__device__ float g_drift[Bn * Pn];
__device__ float g_flag[Pn];
__device__ float g_z1[Pn * Hn];
__device__ float g_a1[Pn * Hn];
__device__ float g_h2[Pn * (Hn / 2)];
__device__ float g_z2[Pn * Hn];
__device__ float g_a2[Pn * Hn];
__device__ float g_c2[Pn * Hn];
__device__ float g_newc[Pn * Dn];

// ---------------- fused T-mean reductions, float4 loads -----------------------
__global__ void __launch_bounds__(256) reduce_centers_kernel(
    const float* __restrict__ proto, const float* __restrict__ feat)
{
    int blk = blockIdx.x;
    bool isP = blk < Pn;
    int row = isP ? blk : (blk - Pn);
    const float4* base = (const float4*)((isP ? proto : feat) + (size_t)row * Tn * Dn);

    int dq = threadIdx.x & 63;     // which float4 of the 64 in D
    int tq = threadIdx.x >> 6;     // 0..3 t-slices

    float4 a = make_float4(0.f, 0.f, 0.f, 0.f);
#pragma unroll 16
    for (int tt = tq; tt < Tn; tt += 4) {
        float4 v = base[tt * (Dn / 4) + dq];
        a.x += v.x; a.y += v.y; a.z += v.z; a.w += v.w;
    }

    __shared__ float4 sred[4][64];
    __shared__ float ss[64];
    __shared__ float s_inv;
    sred[tq][dq] = a;
    __syncthreads();

    if (tq == 0) {
        float4 b0 = sred[0][dq], b1 = sred[1][dq], b2 = sred[2][dq], b3 = sred[3][dq];
        float4 c;
        c.x = (b0.x + b1.x + b2.x + b3.x) * (1.0f / Tn);
        c.y = (b0.y + b1.y + b2.y + b3.y) * (1.0f / Tn);
        c.z = (b0.z + b1.z + b2.z + b3.z) * (1.0f / Tn);
        c.w = (b0.w + b1.w + b2.w + b3.w) * (1.0f / Tn);
        sred[0][dq] = c;
        ss[dq] = c.x * c.x + c.y * c.y + c.z * c.z + c.w * c.w;
    }
    __syncthreads();
    if (threadIdx.x < 32) {
        float s = ss[threadIdx.x] + ss[threadIdx.x + 32];
#pragma unroll
        for (int o = 16; o > 0; o >>= 1) s += __shfl_xor_sync(0xffffffffu, s, o);
        if (threadIdx.x == 0) s_inv = 1.0f / fmaxf(sqrtf(s), EPS_COS);
    }
    __syncthreads();

    if (tq == 0) {
        float4 c = sred[0][dq];
        float inv = s_inv;
        if (isP) {
            ((float4*)g_centers)[row * (Dn / 4) + dq] = c;
            int d = dq * 4;
            g_ncT[(size_t)(d + 0) * Pn + row] = c.x * inv;
            g_ncT[(size_t)(d + 1) * Pn + row] = c.y * inv;
            g_ncT[(size_t)(d + 2) * Pn + row] = c.z * inv;
            g_ncT[(size_t)(d + 3) * Pn + row] = c.w * inv;
        } else {
            ((float4*)g_fcent)[row * (Dn / 4) + dq] = c;
            ((float4*)g_nf)[row * (Dn / 4) + dq] =
                make_float4(c.x * inv, c.y * inv, c.z * inv, c.w * inv);
        }
    }
}

// partial global_mean over B: 8 blocks, each sums 128 rows
__global__ void __launch_bounds__(Dn) gm_partial_kernel() {
    int i = blockIdx.x;
    int d = threadIdx.x;
    float s = 0.f;
    int b0 = i * (Bn / 8);
#pragma unroll 8
    for (int b = 0; b < Bn / 8; b++) s += g_fcent[(b0 + b) * Dn + d];
    g_gmp[i][d] = s;
}

// bias2[h] = dd_b1[h] + sum_d gm[d] * dd_w1[D + d][h]
__global__ void __launch_bounds__(512) bias2_kernel(const float* __restrict__ dd_w1,
                                                    const float* __restrict__ dd_b1) {
    int hx = threadIdx.x & 63;
    int dg = threadIdx.x >> 6;
    int h = blockIdx.x * 64 + hx;
    float s = 0.f;
#pragma unroll 8
    for (int j = 0; j < 32; j++) {
        int d = dg * 32 + j;
        float gm = 0.f;
#pragma unroll
        for (int q = 0; q < 8; q++) gm += g_gmp[q][d];
        gm *= (1.0f / Bn);
        s += gm * dd_w1[(size_t)(Dn + d) * Hn + h];
    }
    __shared__ float red[8][64];
    red[dg][hx] = s;
    __syncthreads();
    if (dg == 0) {
        float t = 0.f;
#pragma unroll
        for (int q = 0; q < 8; q++) t += red[q][hx];
        g_bias2[h] = dd_b1[h] + t;
    }
}

// ---------------- mma helpers -------------------------------------------------
__device__ __forceinline__ void mma_tf32(float* c,
                                         uint32_t a0, uint32_t a1, uint32_t a2, uint32_t a3,
                                         uint32_t b0, uint32_t b1) {
    asm volatile(
        "mma.sync.aligned.m16n8k8.row.col.f32.tf32.tf32.f32 "
        "{%0,%1,%2,%3}, {%4,%5,%6,%7}, {%8,%9}, {%0,%1,%2,%3};\n"
        : "+f"(c[0]), "+f"(c[1]), "+f"(c[2]), "+f"(c[3])
        : "r"(a0), "r"(a1), "r"(a2), "r"(a3), "r"(b0), "r"(b1));
}

__device__ __forceinline__ void cp16(void* smem, const void* gmem) {
    uint32_t sa = (uint32_t)__cvta_generic_to_shared(smem);
    asm volatile("cp.async.cg.shared.global [%0], [%1], 16;\n" :: "r"(sa), "l"(gmem));
}
__device__ __forceinline__ void cp_commit() {
    asm volatile("cp.async.commit_group;\n");
}
__device__ __forceinline__ void cp_wait1() {
    asm volatile("cp.async.wait_group 1;\n");
}

// flat-grouped GEMM descriptor: up to 3 slices packed into one 1-D grid
struct GB {
    const float* A[3];
    const float* W[3];
    const float* bias[3];
    float*       C[3];
    int          ldw[3];
    int          ldc[3];
    int          act[3];    // 0=bias, 1=relu(bias), 2=(1-acc) no bias
    int          nx[3];     // blocks along N for this slice
    int          start1, start2;  // block-id prefix boundaries
};

// ---- flat-grouped cp.async 3-stage pipelined tf32 GEMM (uniform K across z)
template<int BM, int BN, int WM, int WN, int NT>
__global__ void __launch_bounds__(NT) gemm_fg(GB gb, int K)
{
    constexpr int BK = 16;
    constexpr int S  = 3;
    constexpr int PAA = 4;
    constexpr int PAB = 8;
    constexpr int WTM = BM / WM;
    constexpr int WTN = BN / WN;
    constexpr int MI = WTM / 16;
    constexpr int NI = WTN / 8;

    __shared__ __align__(16) float As[S][BM][BK + PAA];
    __shared__ __align__(16) float Bs[S][BK][BN + PAB];

    const int bx = blockIdx.x;
    const int z = (bx >= gb.start1) + (bx >= gb.start2);
    const int local = bx - (z == 0 ? 0 : (z == 1 ? gb.start1 : gb.start2));
    const int nx = gb.nx[z];
    const int m0 = (local / nx) * BM;
    const int n0 = (local % nx) * BN;
    const int ldw = gb.ldw[z];
    const int ldc = gb.ldc[z];
    const int act = gb.act[z];

    const int t = threadIdx.x;
    const int warp = t >> 5;
    const int lane = t & 31;
    const int g  = lane >> 2;
    const int tg = lane & 3;
    const int wm = warp / WN;
    const int wn = warp % WN;

    const float* Abase = gb.A[z] + (size_t)m0 * K;
    const float* Wbase = gb.W[z] + n0;

    constexpr int CA = (BM * BK / 4) / NT;
    constexpr int CB = (BK * BN / 4) / NT;
    const int KB = K / BK;

    auto issue = [&](int st, int kb) {
#pragma unroll
        for (int i = 0; i < CA; i++) {
            int c = t + i * NT;
            int row = c / (BK / 4);
            int col = (c % (BK / 4)) * 4;
            cp16(&As[st][row][col], Abase + (size_t)row * K + kb * BK + col);
        }
#pragma unroll
        for (int i = 0; i < CB; i++) {
            int c = t + i * NT;
            int row = c / (BN / 4);
            int col = (c % (BN / 4)) * 4;
            cp16(&Bs[st][row][col], Wbase + (size_t)(kb * BK + row) * ldw + col);
        }
    };

    float acc[MI][NI][4];
#pragma unroll
    for (int mi = 0; mi < MI; mi++)
#pragma unroll
        for (int ni = 0; ni < NI; ni++)
#pragma unroll
            for (int q = 0; q < 4; q++) acc[mi][ni][q] = 0.f;

#pragma unroll
    for (int st = 0; st < S - 1; st++) { issue(st, st); cp_commit(); }

    for (int kb = 0; kb < KB; kb++) {
        cp_wait1();
        __syncthreads();
        int nl = kb + S - 1;
        if (nl < KB) issue(nl % S, nl);
        cp_commit();

        int cs = kb % S;
#pragma unroll
        for (int ks = 0; ks < BK; ks += 8) {
            uint32_t af[MI][4], bf[NI][2];
#pragma unroll
            for (int mi = 0; mi < MI; mi++) {
                int m = wm * WTM + mi * 16 + g;
                af[mi][0] = __float_as_uint(As[cs][m][ks + tg]);
                af[mi][1] = __float_as_uint(As[cs][m + 8][ks + tg]);
                af[mi][2] = __float_as_uint(As[cs][m][ks + tg + 4]);
                af[mi][3] = __float_as_uint(As[cs][m + 8][ks + tg + 4]);
            }
#pragma unroll
            for (int ni = 0; ni < NI; ni++) {
                int n = wn * WTN + ni * 8 + g;
                bf[ni][0] = __float_as_uint(Bs[cs][ks + tg][n]);
                bf[ni][1] = __float_as_uint(Bs[cs][ks + tg + 4][n]);
            }
#pragma unroll
            for (int mi = 0; mi < MI; mi++)
#pragma unroll
                for (int ni = 0; ni < NI; ni++)
                    mma_tf32(acc[mi][ni],
                             af[mi][0], af[mi][1], af[mi][2], af[mi][3],
                             bf[ni][0], bf[ni][1]);
        }
    }

    const float* bias = gb.bias[z];
    float* C = gb.C[z];

#pragma unroll
    for (int mi = 0; mi < MI; mi++) {
#pragma unroll
        for (int ni = 0; ni < NI; ni++) {
            int m = m0 + wm * WTM + mi * 16 + g;
            int n = n0 + wn * WTN + ni * 8 + tg * 2;
            float2 v0, v1;
            if (act == 2) {
                v0.x = 1.0f - acc[mi][ni][0]; v0.y = 1.0f - acc[mi][ni][1];
                v1.x = 1.0f - acc[mi][ni][2]; v1.y = 1.0f - acc[mi][ni][3];
            } else {
                float b0 = bias[n], b1 = bias[n + 1];
                v0.x = acc[mi][ni][0] + b0;   v0.y = acc[mi][ni][1] + b1;
                v1.x = acc[mi][ni][2] + b0;   v1.y = acc[mi][ni][3] + b1;
                if (act == 1) {
                    v0.x = fmaxf(v0.x, 0.f); v0.y = fmaxf(v0.y, 0.f);
                    v1.x = fmaxf(v1.x, 0.f); v1.y = fmaxf(v1.y, 0.f);
                }
            }
            *(float2*)&C[(size_t)m * ldc + n]       = v0;
            *(float2*)&C[(size_t)(m + 8) * ldc + n] = v1;
        }
    }
}

// ---- final GEMM: newc = centers + clip(STRENGTH*conf)*(c2 @ cal_w3 + b3)
// conf computed inline per block from h2 rows (replaces gemv_sig launch).
template<int BM, int BN, int WM, int WN, int NT>
__global__ void __launch_bounds__(NT) gemm_final(
    const float* __restrict__ A, const float* __restrict__ W,
    const float* __restrict__ bias, float* __restrict__ C,
    const float* __restrict__ h2, const float* __restrict__ w3,
    const float* __restrict__ b3, const float* __restrict__ centers,
    int N, int K)
{
    constexpr int BK = 16;
    constexpr int S  = 3;
    constexpr int PAA = 4;
    constexpr int PAB = 8;
    constexpr int WTM = BM / WM;
    constexpr int WTN = BN / WN;
    constexpr int MI = WTM / 16;
    constexpr int NI = WTN / 8;

    __shared__ __align__(16) float As[S][BM][BK + PAA];
    __shared__ __align__(16) float Bs[S][BK][BN + PAB];
    __shared__ float cred[BM][2];
    __shared__ float conf_s[BM];

    const int t = threadIdx.x;
    const int warp = t >> 5;
    const int lane = t & 31;
    const int g  = lane >> 2;
    const int tg = lane & 3;
    const int wm = warp / WN;
    const int wn = warp % WN;

    const int m0 = blockIdx.y * BM;
    const int n0 = blockIdx.x * BN;

    const float* Abase = A + (size_t)m0 * K;
    const float* Wbase = W + n0;

    constexpr int CA = (BM * BK / 4) / NT;
    constexpr int CB = (BK * BN / 4) / NT;
    const int KB = K / BK;

    auto issue = [&](int st, int kb) {
#pragma unroll
        for (int i = 0; i < CA; i++) {
            int c = t + i * NT;
            int row = c / (BK / 4);
            int col = (c % (BK / 4)) * 4;
            cp16(&As[st][row][col], Abase + (size_t)row * K + kb * BK + col);
        }
#pragma unroll
        for (int i = 0; i < CB; i++) {
            int c = t + i * NT;
            int row = c / (BN / 4);
            int col = (c % (BN / 4)) * 4;
            cp16(&Bs[st][row][col], Wbase + (size_t)(kb * BK + row) * N + col);
        }
    };

    float acc[MI][NI][4];
#pragma unroll
    for (int mi = 0; mi < MI; mi++)
#pragma unroll
        for (int ni = 0; ni < NI; ni++)
#pragma unroll
            for (int q = 0; q < 4; q++) acc[mi][ni][q] = 0.f;

#pragma unroll
    for (int st = 0; st < S - 1; st++) { issue(st, st); cp_commit(); }

    // inline conf: 2 threads per row, 128 cols each over h2 row (Hn/2 = 256)
    {
        int r = t >> 1;
        int half = t & 1;
        const float* hrow = h2 + (size_t)(m0 + r) * (Hn / 2) + half * 128;
        const float* wrow = w3 + half * 128;
        float s = 0.f;
#pragma unroll 16
        for (int j = 0; j < 128; j++) s += hrow[j] * wrow[j];
        cred[r][half] = s;
    }
    __syncthreads();
    if (t < BM) {
        float x = cred[t][0] + cred[t][1] + b3[0];
        conf_s[t] = 1.0f / (1.0f + expf(-x));
    }

    for (int kb = 0; kb < KB; kb++) {
        cp_wait1();
        __syncthreads();
        int nl = kb + S - 1;
        if (nl < KB) issue(nl % S, nl);
        cp_commit();

        int cs = kb % S;
#pragma unroll
        for (int ks = 0; ks < BK; ks += 8) {
            uint32_t af[MI][4], bf[NI][2];
#pragma unroll
            for (int mi = 0; mi < MI; mi++) {
                int m = wm * WTM + mi * 16 + g;
                af[mi][0] = __float_as_uint(As[cs][m][ks + tg]);
                af[mi][1] = __float_as_uint(As[cs][m + 8][ks + tg]);
                af[mi][2] = __float_as_uint(As[cs][m][ks + tg + 4]);
                af[mi][3] = __float_as_uint(As[cs][m + 8][ks + tg + 4]);
            }
#pragma unroll
            for (int ni = 0; ni < NI; ni++) {
                int n = wn * WTN + ni * 8 + g;
                bf[ni][0] = __float_as_uint(Bs[cs][ks + tg][n]);
                bf[ni][1] = __float_as_uint(Bs[cs][ks + tg + 4][n]);
            }
#pragma unroll
            for (int mi = 0; mi < MI; mi++)
#pragma unroll
                for (int ni = 0; ni < NI; ni++)
                    mma_tf32(acc[mi][ni],
                             af[mi][0], af[mi][1], af[mi][2], af[mi][3],
                             bf[ni][0], bf[ni][1]);
        }
    }

#pragma unroll
    for (int mi = 0; mi < MI; mi++) {
#pragma unroll
        for (int ni = 0; ni < NI; ni++) {
            int lm = wm * WTM + mi * 16 + g;
            int m = m0 + lm;
            int n = n0 + wn * WTN + ni * 8 + tg * 2;
            float b0 = bias[n], b1 = bias[n + 1];
            float s0 = fminf(fmaxf(STRENGTH * conf_s[lm], MIN_S), MAX_S);
            float s1 = fminf(fmaxf(STRENGTH * conf_s[lm + 8], MIN_S), MAX_S);
            float2 v0, v1;
            v0.x = centers[(size_t)m * N + n]           + s0 * (acc[mi][ni][0] + b0);
            v0.y = centers[(size_t)m * N + n + 1]       + s0 * (acc[mi][ni][1] + b1);
            v1.x = centers[(size_t)(m + 8) * N + n]     + s1 * (acc[mi][ni][2] + b0);
            v1.y = centers[(size_t)(m + 8) * N + n + 1] + s1 * (acc[mi][ni][3] + b1);
            *(float2*)&C[(size_t)m * N + n]       = v0;
            *(float2*)&C[(size_t)(m + 8) * N + n] = v1;
        }
    }
}

// merged: blocks [0, 2Pn) -> layernorm+relu rows; [2Pn, 2Pn+64) -> colmean
__global__ void __launch_bounds__(256) ln_cm_kernel(
    const float* __restrict__ z1, const float* __restrict__ g1, const float* __restrict__ be1,
    float* __restrict__ o1,
    const float* __restrict__ z2, const float* __restrict__ g2, const float* __restrict__ be2,
    float* __restrict__ o2,
    const float* __restrict__ drift, float* __restrict__ out_flag)
{
    int blk = blockIdx.x;
    if (blk >= 2 * Pn) {
        // colmean over B for 32 prototypes per block
        int cb = blk - 2 * Pn;
        int tx = threadIdx.x & 31;
        int ty = threadIdx.x >> 5;
        int p = cb * 32 + tx;
        float s = 0.f;
#pragma unroll 8
        for (int b = ty; b < Bn; b += 8)
            s += drift[(size_t)b * Pn + p];
        __shared__ float redc[8][33];
        redc[ty][tx] = s;
        __syncthreads();
        if (ty == 0) {
            float t = redc[0][tx];
#pragma unroll
            for (int q = 1; q < 8; q++) t += redc[q][tx];
            float fl = (t * (1.0f / Bn) > THRESHOLD) ? 1.0f : 0.0f;
            g_flag[p] = fl;
            if (out_flag) out_flag[p] = fl;
        }
        return;
    }

    bool first = blk < Pn;
    int r = first ? blk : blk - Pn;
    const float* z  = first ? z1 : z2;
    const float* g  = first ? g1 : g2;
    const float* be = first ? be1 : be2;
    float* out = first ? o1 : o2;

    int d = threadIdx.x;
    const float* row = z + (size_t)r * Hn;
    float v0 = row[d], v1 = row[d + 256];

    __shared__ float red[256];
    red[d] = v0 + v1;
    __syncthreads();
    for (int o = 128; o > 0; o >>= 1) {
        if (d < o) red[d] += red[d + o];
        __syncthreads();
    }
    float mu = red[0] * (1.0f / Hn);
    __syncthreads();

    float d0 = v0 - mu, d1 = v1 - mu;
    red[d] = d0 * d0 + d1 * d1;
    __syncthreads();
    for (int o = 128; o > 0; o >>= 1) {
        if (d < o) red[d] += red[d + o];
        __syncthreads();
    }
    float var = red[0] * (1.0f / Hn);
    float rs = rsqrtf(var + EPS_LN);

    float* orow = out + (size_t)r * Hn;
    orow[d]       = fmaxf(d0 * rs * g[d] + be[d], 0.f);
    orow[d + 256] = fmaxf(d1 * rs * g[d + 256] + be[d + 256], 0.f);
}

// calibrated[p][t][d] = flag[p] ? new_center[p][d] : prototype[p][t][d]
__global__ void __launch_bounds__(256) scatter_kernel(const float* __restrict__ proto,
                                                      float* __restrict__ out) {
    int i = blockIdx.x * 256 + threadIdx.x;
    int p = i >> 12;
    int r = i & 4095;
    int d4 = r & 63;
    float4 v;
    if (g_flag[p] > 0.5f) {
        v = ((const float4*)g_newc)[(p << 6) + d4];
    } else {
        v = ((const float4*)proto)[i];
    }
    ((float4*)out)[i] = v;
}

// ---------------- launch ------------------------------------------------------
extern "C" void kernel_launch(void* const* d_in, const int* in_sizes, int n_in,
                              void* d_out, int out_size) {
    (void)in_sizes; (void)n_in;
    const float* feat   = (const float*)d_in[0];
    const float* proto  = (const float*)d_in[1];
    const float* dd_w1  = (const float*)d_in[2];
    const float* dd_b1  = (const float*)d_in[3];
    const float* dd_g1  = (const float*)d_in[4];
    const float* dd_be1 = (const float*)d_in[5];
    const float* dd_w2  = (const float*)d_in[6];
    const float* dd_b2  = (const float*)d_in[7];
    const float* dd_w3  = (const float*)d_in[8];
    const float* dd_b3  = (const float*)d_in[9];
    const float* cal_w1 = (const float*)d_in[10];
    const float* cal_b1 = (const float*)d_in[11];
    const float* cal_g1 = (const float*)d_in[12];
    const float* cal_be1= (const float*)d_in[13];
    const float* cal_w2 = (const float*)d_in[14];
    const float* cal_b2 = (const float*)d_in[15];
    const float* cal_w3 = (const float*)d_in[16];
    const float* cal_b3 = (const float*)d_in[17];

    float* out = (float*)d_out;
    const long long PTD = (long long)Pn * Tn * Dn;
    const long long BP  = (long long)Bn * Pn;

    bool has_drift = (long long)out_size >= PTD + BP;
    bool has_flag  = (long long)out_size >= PTD + BP + Pn;

    float* drift_ptr = nullptr;
    if (has_drift) {
        drift_ptr = out + PTD;
    } else {
        cudaGetSymbolAddress((void**)&drift_ptr, g_drift);
    }
    float* flag_ptr = has_flag ? (out + PTD + BP) : nullptr;

    float *p_centers, *p_ncT, *p_nf, *p_bias2, *p_z1, *p_a1, *p_h2,
          *p_z2, *p_a2, *p_c2, *p_newc;
    cudaGetSymbolAddress((void**)&p_centers, g_centers);
    cudaGetSymbolAddress((void**)&p_ncT,     g_ncT);
    cudaGetSymbolAddress((void**)&p_nf,      g_nf);
    cudaGetSymbolAddress((void**)&p_bias2,   g_bias2);
    cudaGetSymbolAddress((void**)&p_z1,      g_z1);
    cudaGetSymbolAddress((void**)&p_a1,      g_a1);
    cudaGetSymbolAddress((void**)&p_h2,      g_h2);
    cudaGetSymbolAddress((void**)&p_z2,      g_z2);
    cudaGetSymbolAddress((void**)&p_a2,      g_a2);
    cudaGetSymbolAddress((void**)&p_c2,      g_c2);
    cudaGetSymbolAddress((void**)&p_newc,    g_newc);

    // 1: fused T-mean reductions (float4)
    reduce_centers_kernel<<<Pn + Bn, 256>>>(proto, feat);
    // 2-3: partial global mean, fold gm @ dd_w1[D:2D] into bias2
    gm_partial_kernel<<<8, Dn>>>();
    bias2_kernel<<<8, 512>>>(dd_w1, dd_b1);

    // 4: MEGA phase 1 — sim GEMM + both layer-1 GEMMs (all K=256), 512 blocks
    {
        GB gb = {};
        // z0: drift = 1 - nf @ ncT  [1024 x 2048]
        gb.A[0] = p_nf;      gb.W[0] = p_ncT;  gb.bias[0] = nullptr;
        gb.C[0] = drift_ptr; gb.ldw[0] = Pn;   gb.ldc[0] = Pn;
        gb.act[0] = 2;       gb.nx[0] = Pn / 128;            // 16 x 16 = 256 blocks
        // z1: z1 = centers @ dd_w1[0:D] + bias2  [2048 x 512]
        gb.A[1] = p_centers; gb.W[1] = dd_w1;  gb.bias[1] = p_bias2;
        gb.C[1] = p_z1;      gb.ldw[1] = Hn;   gb.ldc[1] = Hn;
        gb.act[1] = 0;       gb.nx[1] = Hn / 128;            // 4 x 32 = 128 blocks
        // z2: z2 = centers @ cal_w1 + cal_b1  [2048 x 512]
        gb.A[2] = p_centers; gb.W[2] = cal_w1; gb.bias[2] = cal_b1;
        gb.C[2] = p_z2;      gb.ldw[2] = Hn;   gb.ldc[2] = Hn;
        gb.act[2] = 0;       gb.nx[2] = Hn / 128;            // 128 blocks
        gb.start1 = 256; gb.start2 = 384;
        gemm_fg<64, 128, 1, 4, 128><<<512, 128>>>(gb, Dn);
    }

    // 5: merged layernorm+relu (z1->a1, z2->a2) + colmean -> flag
    ln_cm_kernel<<<2 * Pn + Pn / 32, 256>>>(p_z1, dd_g1, dd_be1, p_a1,
                                            p_z2, cal_g1, cal_be1, p_a2,
                                            drift_ptr, flag_ptr);

    // 6: MEGA phase 2 — dd layer-2 + cal layer-2 (two 256-col halves), K=512
    {
        GB gb = {};
        gb.A[0] = p_a1; gb.W[0] = dd_w2;        gb.bias[0] = dd_b2;
        gb.C[0] = p_h2;       gb.ldw[0] = Hn / 2; gb.ldc[0] = Hn / 2;
        gb.act[0] = 1;        gb.nx[0] = 2;                  // 2 x 32 = 64
        gb.A[1] = p_a2; gb.W[1] = cal_w2;       gb.bias[1] = cal_b2;
        gb.C[1] = p_c2;       gb.ldw[1] = Hn;     gb.ldc[1] = Hn;
        gb.act[1] = 1;        gb.nx[1] = 2;                  // 64
        gb.A[2] = p_a2; gb.W[2] = cal_w2 + 256; gb.bias[2] = cal_b2 + 256;
        gb.C[2] = p_c2 + 256; gb.ldw[2] = Hn;     gb.ldc[2] = Hn;
        gb.act[2] = 1;        gb.nx[2] = 2;                  // 64
        gb.start1 = 64; gb.start2 = 128;
        gemm_fg<64, 128, 1, 4, 128><<<192, 128>>>(gb, Hn);
    }

    // 7: final GEMM with inline conf (sigmoid gemv) + fused new_center epilogue
    gemm_final<64, 64, 2, 2, 128><<<dim3(Dn / 64, Pn / 64), 128>>>(
        p_c2, cal_w3, cal_b3, p_newc, p_h2, dd_w3, dd_b3, p_centers, Dn, Hn);

    // 8: scatter calibrated output
    scatter_kernel<<<(int)(PTD / 4 / 256), 256>>>(proto, out);
}

// round 14
// speedup vs baseline: 2.0955x; 1.0392x over previous
#include <cuda_runtime.h>
#include <math.h>
#include <stdint.h>

// Problem dims
#define Bn 1024
#define Tn 64
#define Dn 256
#define Pn 2048
#define Hn 512

#define THRESHOLD 0.3f
#define STRENGTH 0.1f
#define MIN_S 0.0f
#define MAX_S 0.5f
#define EPS_COS 1e-8f
#define EPS_LN 1e-5f

// ---------------- scratch (static device globals; no allocations) -------------
__device__ float g_centers[Pn * Dn];
__device__ float g_ncT[Dn * Pn];
__device__ float g_nf[Bn * Dn];
__device__ float g_fcent[Bn * Dn];
__device__ float g_gmp[8][Dn];
__device__ float g_bias2[Hn];
__device__ float g_drift[Bn * Pn];
__device__ float g_flag[Pn];
__device__ float g_z1[Pn * Hn];
__device__ float g_a1[Pn * Hn];
__device__ float g_h2[Pn * (Hn / 2)];
__device__ float g_z2[Pn * Hn];
__device__ float g_a2[Pn * Hn];
__device__ float g_c2[Pn * Hn];
__device__ float g_newc[Pn * Dn];

// ---------------- fused T-mean reductions, float4 loads -----------------------
__global__ void __launch_bounds__(256) reduce_centers_kernel(
    const float* __restrict__ proto, const float* __restrict__ feat)
{
    int blk = blockIdx.x;
    bool isP = blk < Pn;
    int row = isP ? blk : (blk - Pn);
    const float4* base = (const float4*)((isP ? proto : feat) + (size_t)row * Tn * Dn);

    int dq = threadIdx.x & 63;
    int tq = threadIdx.x >> 6;

    float4 a = make_float4(0.f, 0.f, 0.f, 0.f);
#pragma unroll 16
    for (int tt = tq; tt < Tn; tt += 4) {
        float4 v = base[tt * (Dn / 4) + dq];
        a.x += v.x; a.y += v.y; a.z += v.z; a.w += v.w;
    }

    __shared__ float4 sred[4][64];
    __shared__ float ss[64];
    __shared__ float s_inv;
    sred[tq][dq] = a;
    __syncthreads();

    if (tq == 0) {
        float4 b0 = sred[0][dq], b1 = sred[1][dq], b2 = sred[2][dq], b3 = sred[3][dq];
        float4 c;
        c.x = (b0.x + b1.x + b2.x + b3.x) * (1.0f / Tn);
        c.y = (b0.y + b1.y + b2.y + b3.y) * (1.0f / Tn);
        c.z = (b0.z + b1.z + b2.z + b3.z) * (1.0f / Tn);
        c.w = (b0.w + b1.w + b2.w + b3.w) * (1.0f / Tn);
        sred[0][dq] = c;
        ss[dq] = c.x * c.x + c.y * c.y + c.z * c.z + c.w * c.w;
    }
    __syncthreads();
    if (threadIdx.x < 32) {
        float s = ss[threadIdx.x] + ss[threadIdx.x + 32];
#pragma unroll
        for (int o = 16; o > 0; o >>= 1) s += __shfl_xor_sync(0xffffffffu, s, o);
        if (threadIdx.x == 0) s_inv = 1.0f / fmaxf(sqrtf(s), EPS_COS);
    }
    __syncthreads();

    if (tq == 0) {
        float4 c = sred[0][dq];
        float inv = s_inv;
        if (isP) {
            ((float4*)g_centers)[row * (Dn / 4) + dq] = c;
            int d = dq * 4;
            g_ncT[(size_t)(d + 0) * Pn + row] = c.x * inv;
            g_ncT[(size_t)(d + 1) * Pn + row] = c.y * inv;
            g_ncT[(size_t)(d + 2) * Pn + row] = c.z * inv;
            g_ncT[(size_t)(d + 3) * Pn + row] = c.w * inv;
        } else {
            ((float4*)g_fcent)[row * (Dn / 4) + dq] = c;
            ((float4*)g_nf)[row * (Dn / 4) + dq] =
                make_float4(c.x * inv, c.y * inv, c.z * inv, c.w * inv);
        }
    }
}

// partial global_mean over B: 8 blocks, each sums 128 rows
__global__ void __launch_bounds__(Dn) gm_partial_kernel() {
    int i = blockIdx.x;
    int d = threadIdx.x;
    float s = 0.f;
    int b0 = i * (Bn / 8);
#pragma unroll 8
    for (int b = 0; b < Bn / 8; b++) s += g_fcent[(b0 + b) * Dn + d];
    g_gmp[i][d] = s;
}

// bias2[h] = dd_b1[h] + sum_d gm[d] * dd_w1[D + d][h]
__global__ void __launch_bounds__(512) bias2_kernel(const float* __restrict__ dd_w1,
                                                    const float* __restrict__ dd_b1) {
    int hx = threadIdx.x & 63;
    int dg = threadIdx.x >> 6;
    int h = blockIdx.x * 64 + hx;
    float s = 0.f;
#pragma unroll 8
    for (int j = 0; j < 32; j++) {
        int d = dg * 32 + j;
        float gm = 0.f;
#pragma unroll
        for (int q = 0; q < 8; q++) gm += g_gmp[q][d];
        gm *= (1.0f / Bn);
        s += gm * dd_w1[(size_t)(Dn + d) * Hn + h];
    }
    __shared__ float red[8][64];
    red[dg][hx] = s;
    __syncthreads();
    if (dg == 0) {
        float t = 0.f;
#pragma unroll
        for (int q = 0; q < 8; q++) t += red[q][hx];
        g_bias2[h] = dd_b1[h] + t;
    }
}

// ---------------- mma / copy helpers ------------------------------------------
__device__ __forceinline__ void mma_tf32(float* c,
                                         uint32_t a0, uint32_t a1, uint32_t a2, uint32_t a3,
                                         uint32_t b0, uint32_t b1) {
    asm volatile(
        "mma.sync.aligned.m16n8k8.row.col.f32.tf32.tf32.f32 "
        "{%0,%1,%2,%3}, {%4,%5,%6,%7}, {%8,%9}, {%0,%1,%2,%3};\n"
        : "+f"(c[0]), "+f"(c[1]), "+f"(c[2]), "+f"(c[3])
        : "r"(a0), "r"(a1), "r"(a2), "r"(a3), "r"(b0), "r"(b1));
}

__device__ __forceinline__ void ldsm4(uint32_t& r0, uint32_t& r1, uint32_t& r2, uint32_t& r3,
                                      uint32_t addr) {
    asm volatile("ldmatrix.sync.aligned.m8n8.x4.shared.b16 {%0,%1,%2,%3}, [%4];"
                 : "=r"(r0), "=r"(r1), "=r"(r2), "=r"(r3) : "r"(addr));
}

__device__ __forceinline__ void cp16(void* smem, const void* gmem) {
    uint32_t sa = (uint32_t)__cvta_generic_to_shared(smem);
    asm volatile("cp.async.cg.shared.global [%0], [%1], 16;\n" :: "r"(sa), "l"(gmem));
}
__device__ __forceinline__ void cp_commit() {
    asm volatile("cp.async.commit_group;\n");
}
__device__ __forceinline__ void cp_wait0() {
    asm volatile("cp.async.wait_group 0;\n");
}
__device__ __forceinline__ void cp_wait1() {
    asm volatile("cp.async.wait_group 1;\n");
}

// flat-grouped GEMM descriptor
struct GB {
    const float* A[3];
    const float* W[3];
    const float* bias[3];
    float*       C[3];
    int          ldw[3];
    int          ldc[3];
    int          act[3];    // 0=bias, 1=relu(bias), 2=(1-acc) no bias
    int          nx[3];
    int          start1, start2;
};

// ---- flat-grouped cp.async double-buffered tf32 GEMM, BK=32, ldmatrix A frags
template<int BM, int BN, int WM, int WN, int NT>
__global__ void __launch_bounds__(NT) gemm_fg(GB gb, int K)
{
    constexpr int BK = 32;
    constexpr int PAA = 4;                 // As stride 36 floats = 144B (16B-aligned, bank-free)
    constexpr int PAB = 8;                 // Bs stride %32 == 8 -> scalar frags bank-free
    constexpr int WTM = BM / WM;
    constexpr int WTN = BN / WN;
    constexpr int MI = WTM / 16;
    constexpr int NI = WTN / 8;

    __shared__ __align__(16) float As[2][BM][BK + PAA];
    __shared__ __align__(16) float Bs[2][BK][BN + PAB];

    const int bx = blockIdx.x;
    const int z = (bx >= gb.start1) + (bx >= gb.start2);
    const int local = bx - (z == 0 ? 0 : (z == 1 ? gb.start1 : gb.start2));
    const int nx = gb.nx[z];
    const int m0 = (local / nx) * BM;
    const int n0 = (local % nx) * BN;
    const int ldw = gb.ldw[z];
    const int ldc = gb.ldc[z];
    const int act = gb.act[z];

    const int t = threadIdx.x;
    const int warp = t >> 5;
    const int lane = t & 31;
    const int g  = lane >> 2;
    const int tg = lane & 3;
    const int wm = warp / WN;
    const int wn = warp % WN;

    const float* Abase = gb.A[z] + (size_t)m0 * K;
    const float* Wbase = gb.W[z] + n0;

    constexpr int CA = (BM * BK / 4) / NT;
    constexpr int CB = (BK * BN / 4) / NT;
    const int KB = K / BK;

    auto issue = [&](int st, int kb) {
#pragma unroll
        for (int i = 0; i < CA; i++) {
            int c = t + i * NT;
            int row = c / (BK / 4);
            int col = (c % (BK / 4)) * 4;
            cp16(&As[st][row][col], Abase + (size_t)row * K + kb * BK + col);
        }
#pragma unroll
        for (int i = 0; i < CB; i++) {
            int c = t + i * NT;
            int row = c / (BN / 4);
            int col = (c % (BN / 4)) * 4;
            cp16(&Bs[st][row][col], Wbase + (size_t)(kb * BK + row) * ldw + col);
        }
    };

    // ldmatrix source address: row = warp M origin + (lane&15), col = ((lane>>4)*4)
    uint32_t aAddr[2];
#pragma unroll
    for (int st = 0; st < 2; st++)
        aAddr[st] = (uint32_t)__cvta_generic_to_shared(
            &As[st][wm * WTM + (lane & 15)][(lane >> 4) << 2]);

    float acc[MI][NI][4];
#pragma unroll
    for (int mi = 0; mi < MI; mi++)
#pragma unroll
        for (int ni = 0; ni < NI; ni++)
#pragma unroll
            for (int q = 0; q < 4; q++) acc[mi][ni][q] = 0.f;

    issue(0, 0); cp_commit();

    for (int kb = 0; kb < KB; kb++) {
        if (kb + 1 < KB) {
            issue((kb + 1) & 1, kb + 1);
            cp_commit();
            cp_wait1();
        } else {
            cp_wait0();
        }
        __syncthreads();

        int cs = kb & 1;
#pragma unroll
        for (int ks = 0; ks < BK; ks += 8) {
            uint32_t af[MI][4], bf[NI][2];
#pragma unroll
            for (int mi = 0; mi < MI; mi++)
                ldsm4(af[mi][0], af[mi][1], af[mi][2], af[mi][3],
                      aAddr[cs] + (uint32_t)((mi * 16 * (BK + PAA) + ks) * 4));
#pragma unroll
            for (int ni = 0; ni < NI; ni++) {
                int n = wn * WTN + ni * 8 + g;
                bf[ni][0] = __float_as_uint(Bs[cs][ks + tg][n]);
                bf[ni][1] = __float_as_uint(Bs[cs][ks + tg + 4][n]);
            }
#pragma unroll
            for (int mi = 0; mi < MI; mi++)
#pragma unroll
                for (int ni = 0; ni < NI; ni++)
                    mma_tf32(acc[mi][ni],
                             af[mi][0], af[mi][1], af[mi][2], af[mi][3],
                             bf[ni][0], bf[ni][1]);
        }
        __syncthreads();
    }

    const float* bias = gb.bias[z];
    float* C = gb.C[z];

#pragma unroll
    for (int mi = 0; mi < MI; mi++) {
#pragma unroll
        for (int ni = 0; ni < NI; ni++) {
            int m = m0 + wm * WTM + mi * 16 + g;
            int n = n0 + wn * WTN + ni * 8 + tg * 2;
            float2 v0, v1;
            if (act == 2) {
                v0.x = 1.0f - acc[mi][ni][0]; v0.y = 1.0f - acc[mi][ni][1];
                v1.x = 1.0f - acc[mi][ni][2]; v1.y = 1.0f - acc[mi][ni][3];
            } else {
                float b0 = bias[n], b1 = bias[n + 1];
                v0.x = acc[mi][ni][0] + b0;   v0.y = acc[mi][ni][1] + b1;
                v1.x = acc[mi][ni][2] + b0;   v1.y = acc[mi][ni][3] + b1;
                if (act == 1) {
                    v0.x = fmaxf(v0.x, 0.f); v0.y = fmaxf(v0.y, 0.f);
                    v1.x = fmaxf(v1.x, 0.f); v1.y = fmaxf(v1.y, 0.f);
                }
            }
            *(float2*)&C[(size_t)m * ldc + n]       = v0;
            *(float2*)&C[(size_t)(m + 8) * ldc + n] = v1;
        }
    }
}

// ---- final GEMM: newc = centers + clip(STRENGTH*conf)*(c2 @ cal_w3 + b3)
template<int BM, int BN, int WM, int WN, int NT>
__global__ void __launch_bounds__(NT) gemm_final(
    const float* __restrict__ A, const float* __restrict__ W,
    const float* __restrict__ bias, float* __restrict__ C,
    const float* __restrict__ h2, const float* __restrict__ w3,
    const float* __restrict__ b3, const float* __restrict__ centers,
    int N, int K)
{
    constexpr int BK = 32;
    constexpr int PAA = 4;
    constexpr int PAB = 8;
    constexpr int WTM = BM / WM;
    constexpr int WTN = BN / WN;
    constexpr int MI = WTM / 16;
    constexpr int NI = WTN / 8;

    __shared__ __align__(16) float As[2][BM][BK + PAA];
    __shared__ __align__(16) float Bs[2][BK][BN + PAB];
    __shared__ float cred[BM][2];
    __shared__ float conf_s[BM];

    const int t = threadIdx.x;
    const int warp = t >> 5;
    const int lane = t & 31;
    const int g  = lane >> 2;
    const int tg = lane & 3;
    const int wm = warp / WN;
    const int wn = warp % WN;

    const int m0 = blockIdx.y * BM;
    const int n0 = blockIdx.x * BN;

    const float* Abase = A + (size_t)m0 * K;
    const float* Wbase = W + n0;

    constexpr int CA = (BM * BK / 4) / NT;
    constexpr int CB = (BK * BN / 4) / NT;
    const int KB = K / BK;

    auto issue = [&](int st, int kb) {
#pragma unroll
        for (int i = 0; i < CA; i++) {
            int c = t + i * NT;
            int row = c / (BK / 4);
            int col = (c % (BK / 4)) * 4;
            cp16(&As[st][row][col], Abase + (size_t)row * K + kb * BK + col);
        }
#pragma unroll
        for (int i = 0; i < CB; i++) {
            int c = t + i * NT;
            int row = c / (BN / 4);
            int col = (c % (BN / 4)) * 4;
            cp16(&Bs[st][row][col], Wbase + (size_t)(kb * BK + row) * N + col);
        }
    };

    uint32_t aAddr[2];
#pragma unroll
    for (int st = 0; st < 2; st++)
        aAddr[st] = (uint32_t)__cvta_generic_to_shared(
            &As[st][wm * WTM + (lane & 15)][(lane >> 4) << 2]);

    float acc[MI][NI][4];
#pragma unroll
    for (int mi = 0; mi < MI; mi++)
#pragma unroll
        for (int ni = 0; ni < NI; ni++)
#pragma unroll
            for (int q = 0; q < 4; q++) acc[mi][ni][q] = 0.f;

    issue(0, 0); cp_commit();

    // inline conf: 2 threads per row, halves of h2 row (Hn/2 = 256 cols)
    {
        int r = t >> 1;
        int half = t & 1;
        const float* hrow = h2 + (size_t)(m0 + r) * (Hn / 2) + half * 128;
        const float* wrow = w3 + half * 128;
        float s = 0.f;
#pragma unroll 16
        for (int j = 0; j < 128; j++) s += hrow[j] * wrow[j];
        cred[r][half] = s;
    }
    __syncthreads();
    if (t < BM) {
        float x = cred[t][0] + cred[t][1] + b3[0];
        conf_s[t] = 1.0f / (1.0f + expf(-x));
    }

    for (int kb = 0; kb < KB; kb++) {
        if (kb + 1 < KB) {
            issue((kb + 1) & 1, kb + 1);
            cp_commit();
            cp_wait1();
        } else {
            cp_wait0();
        }
        __syncthreads();

        int cs = kb & 1;
#pragma unroll
        for (int ks = 0; ks < BK; ks += 8) {
            uint32_t af[MI][4], bf[NI][2];
#pragma unroll
            for (int mi = 0; mi < MI; mi++)
                ldsm4(af[mi][0], af[mi][1], af[mi][2], af[mi][3],
                      aAddr[cs] + (uint32_t)((mi * 16 * (BK + PAA) + ks) * 4));
#pragma unroll
            for (int ni = 0; ni < NI; ni++) {
                int n = wn * WTN + ni * 8 + g;
                bf[ni][0] = __float_as_uint(Bs[cs][ks + tg][n]);
                bf[ni][1] = __float_as_uint(Bs[cs][ks + tg + 4][n]);
            }
#pragma unroll
            for (int mi = 0; mi < MI; mi++)
#pragma unroll
                for (int ni = 0; ni < NI; ni++)
                    mma_tf32(acc[mi][ni],
                             af[mi][0], af[mi][1], af[mi][2], af[mi][3],
                             bf[ni][0], bf[ni][1]);
        }
        __syncthreads();
    }

#pragma unroll
    for (int mi = 0; mi < MI; mi++) {
#pragma unroll
        for (int ni = 0; ni < NI; ni++) {
            int lm = wm * WTM + mi * 16 + g;
            int m = m0 + lm;
            int n = n0 + wn * WTN + ni * 8 + tg * 2;
            float b0 = bias[n], b1 = bias[n + 1];
            float s0 = fminf(fmaxf(STRENGTH * conf_s[lm], MIN_S), MAX_S);
            float s1 = fminf(fmaxf(STRENGTH * conf_s[lm + 8], MIN_S), MAX_S);
            float2 v0, v1;
            v0.x = centers[(size_t)m * N + n]           + s0 * (acc[mi][ni][0] + b0);
            v0.y = centers[(size_t)m * N + n + 1]       + s0 * (acc[mi][ni][1] + b1);
            v1.x = centers[(size_t)(m + 8) * N + n]     + s1 * (acc[mi][ni][2] + b0);
            v1.y = centers[(size_t)(m + 8) * N + n + 1] + s1 * (acc[mi][ni][3] + b1);
            *(float2*)&C[(size_t)m * N + n]       = v0;
            *(float2*)&C[(size_t)(m + 8) * N + n] = v1;
        }
    }
}

// merged: blocks [0, 2Pn) -> layernorm+relu rows; [2Pn, 2Pn+64) -> colmean
__global__ void __launch_bounds__(256) ln_cm_kernel(
    const float* __restrict__ z1, const float* __restrict__ g1, const float* __restrict__ be1,
    float* __restrict__ o1,
    const float* __restrict__ z2, const float* __restrict__ g2, const float* __restrict__ be2,
    float* __restrict__ o2,
    const float* __restrict__ drift, float* __restrict__ out_flag)
{
    int blk = blockIdx.x;
    if (blk >= 2 * Pn) {
        int cb = blk - 2 * Pn;
        int tx = threadIdx.x & 31;
        int ty = threadIdx.x >> 5;
        int p = cb * 32 + tx;
        float s = 0.f;
#pragma unroll 8
        for (int b = ty; b < Bn; b += 8)
            s += drift[(size_t)b * Pn + p];
        __shared__ float redc[8][33];
        redc[ty][tx] = s;
        __syncthreads();
        if (ty == 0) {
            float t = redc[0][tx];
#pragma unroll
            for (int q = 1; q < 8; q++) t += redc[q][tx];
            float fl = (t * (1.0f / Bn) > THRESHOLD) ? 1.0f : 0.0f;
            g_flag[p] = fl;
            if (out_flag) out_flag[p] = fl;
        }
        return;
    }

    bool first = blk < Pn;
    int r = first ? blk : blk - Pn;
    const float* z  = first ? z1 : z2;
    const float* g  = first ? g1 : g2;
    const float* be = first ? be1 : be2;
    float* out = first ? o1 : o2;

    int d = threadIdx.x;
    const float* row = z + (size_t)r * Hn;
    float v0 = row[d], v1 = row[d + 256];

    __shared__ float red[256];
    red[d] = v0 + v1;
    __syncthreads();
    for (int o = 128; o > 0; o >>= 1) {
        if (d < o) red[d] += red[d + o];
        __syncthreads();
    }
    float mu = red[0] * (1.0f / Hn);
    __syncthreads();

    float d0 = v0 - mu, d1 = v1 - mu;
    red[d] = d0 * d0 + d1 * d1;
    __syncthreads();
    for (int o = 128; o > 0; o >>= 1) {
        if (d < o) red[d] += red[d + o];
        __syncthreads();
    }
    float var = red[0] * (1.0f / Hn);
    float rs = rsqrtf(var + EPS_LN);

    float* orow = out + (size_t)r * Hn;
    orow[d]       = fmaxf(d0 * rs * g[d] + be[d], 0.f);
    orow[d + 256] = fmaxf(d1 * rs * g[d + 256] + be[d + 256], 0.f);
}

// calibrated[p][t][d] = flag[p] ? new_center[p][d] : prototype[p][t][d]
__global__ void __launch_bounds__(256) scatter_kernel(const float* __restrict__ proto,
                                                      float* __restrict__ out) {
    int i = blockIdx.x * 256 + threadIdx.x;
    int p = i >> 12;
    int r = i & 4095;
    int d4 = r & 63;
    float4 v;
    if (g_flag[p] > 0.5f) {
        v = ((const float4*)g_newc)[(p << 6) + d4];
    } else {
        v = ((const float4*)proto)[i];
    }
    ((float4*)out)[i] = v;
}

// ---------------- launch ------------------------------------------------------
extern "C" void kernel_launch(void* const* d_in, const int* in_sizes, int n_in,
                              void* d_out, int out_size) {
    (void)in_sizes; (void)n_in;
    const float* feat   = (const float*)d_in[0];
    const float* proto  = (const float*)d_in[1];
    const float* dd_w1  = (const float*)d_in[2];
    const float* dd_b1  = (const float*)d_in[3];
    const float* dd_g1  = (const float*)d_in[4];
    const float* dd_be1 = (const float*)d_in[5];
    const float* dd_w2  = (const float*)d_in[6];
    const float* dd_b2  = (const float*)d_in[7];
    const float* dd_w3  = (const float*)d_in[8];
    const float* dd_b3  = (const float*)d_in[9];
    const float* cal_w1 = (const float*)d_in[10];
    const float* cal_b1 = (const float*)d_in[11];
    const float* cal_g1 = (const float*)d_in[12];
    const float* cal_be1= (const float*)d_in[13];
    const float* cal_w2 = (const float*)d_in[14];
    const float* cal_b2 = (const float*)d_in[15];
    const float* cal_w3 = (const float*)d_in[16];
    const float* cal_b3 = (const float*)d_in[17];

    float* out = (float*)d_out;
    const long long PTD = (long long)Pn * Tn * Dn;
    const long long BP  = (long long)Bn * Pn;

    bool has_drift = (long long)out_size >= PTD + BP;
    bool has_flag  = (long long)out_size >= PTD + BP + Pn;

    float* drift_ptr = nullptr;
    if (has_drift) {
        drift_ptr = out + PTD;
    } else {
        cudaGetSymbolAddress((void**)&drift_ptr, g_drift);
    }
    float* flag_ptr = has_flag ? (out + PTD + BP) : nullptr;

    float *p_centers, *p_ncT, *p_nf, *p_bias2, *p_z1, *p_a1, *p_h2,
          *p_z2, *p_a2, *p_c2, *p_newc;
    cudaGetSymbolAddress((void**)&p_centers, g_centers);
    cudaGetSymbolAddress((void**)&p_ncT,     g_ncT);
    cudaGetSymbolAddress((void**)&p_nf,      g_nf);
    cudaGetSymbolAddress((void**)&p_bias2,   g_bias2);
    cudaGetSymbolAddress((void**)&p_z1,      g_z1);
    cudaGetSymbolAddress((void**)&p_a1,      g_a1);
    cudaGetSymbolAddress((void**)&p_h2,      g_h2);
    cudaGetSymbolAddress((void**)&p_z2,      g_z2);
    cudaGetSymbolAddress((void**)&p_a2,      g_a2);
    cudaGetSymbolAddress((void**)&p_c2,      g_c2);
    cudaGetSymbolAddress((void**)&p_newc,    g_newc);

    // 1: fused T-mean reductions (float4)
    reduce_centers_kernel<<<Pn + Bn, 256>>>(proto, feat);
    // 2-3: partial global mean, fold gm @ dd_w1[D:2D] into bias2
    gm_partial_kernel<<<8, Dn>>>();
    bias2_kernel<<<8, 512>>>(dd_w1, dd_b1);

    // 4: MEGA phase 1 — sim GEMM + both layer-1 GEMMs (all K=256), 512 blocks
    {
        GB gb = {};
        gb.A[0] = p_nf;      gb.W[0] = p_ncT;  gb.bias[0] = nullptr;
        gb.C[0] = drift_ptr; gb.ldw[0] = Pn;   gb.ldc[0] = Pn;
        gb.act[0] = 2;       gb.nx[0] = Pn / 128;
        gb.A[1] = p_centers; gb.W[1] = dd_w1;  gb.bias[1] = p_bias2;
        gb.C[1] = p_z1;      gb.ldw[1] = Hn;   gb.ldc[1] = Hn;
        gb.act[1] = 0;       gb.nx[1] = Hn / 128;
        gb.A[2] = p_centers; gb.W[2] = cal_w1; gb.bias[2] = cal_b1;
        gb.C[2] = p_z2;      gb.ldw[2] = Hn;   gb.ldc[2] = Hn;
        gb.act[2] = 0;       gb.nx[2] = Hn / 128;
        gb.start1 = 256; gb.start2 = 384;
        gemm_fg<64, 128, 1, 4, 128><<<512, 128>>>(gb, Dn);
    }

    // 5: merged layernorm+relu (z1->a1, z2->a2) + colmean -> flag
    ln_cm_kernel<<<2 * Pn + Pn / 32, 256>>>(p_z1, dd_g1, dd_be1, p_a1,
                                            p_z2, cal_g1, cal_be1, p_a2,
                                            drift_ptr, flag_ptr);

    // 6: MEGA phase 2 — dd layer-2 + cal layer-2 (two 256-col halves), K=512
    {
        GB gb = {};
        gb.A[0] = p_a1; gb.W[0] = dd_w2;        gb.bias[0] = dd_b2;
        gb.C[0] = p_h2;       gb.ldw[0] = Hn / 2; gb.ldc[0] = Hn / 2;
        gb.act[0] = 1;        gb.nx[0] = 2;
        gb.A[1] = p_a2; gb.W[1] = cal_w2;       gb.bias[1] = cal_b2;
        gb.C[1] = p_c2;       gb.ldw[1] = Hn;     gb.ldc[1] = Hn;
        gb.act[1] = 1;        gb.nx[1] = 2;
        gb.A[2] = p_a2; gb.W[2] = cal_w2 + 256; gb.bias[2] = cal_b2 + 256;
        gb.C[2] = p_c2 + 256; gb.ldw[2] = Hn;     gb.ldc[2] = Hn;
        gb.act[2] = 1;        gb.nx[2] = 2;
        gb.start1 = 64; gb.start2 = 128;
        gemm_fg<64, 128, 1, 4, 128><<<192, 128>>>(gb, Hn);
    }

    // 7: final GEMM with inline conf + fused new_center epilogue
    gemm_final<64, 64, 2, 2, 128><<<dim3(Dn / 64, Pn / 64), 128>>>(
        p_c2, cal_w3, cal_b3, p_newc, p_h2, dd_w3, dd_b3, p_centers, Dn, Hn);

    // 8: scatter calibrated output
    scatter_kernel<<<(int)(PTD / 4 / 256), 256>>>(proto, out);
}

// round 17
// speedup vs baseline: 2.2258x; 1.0622x over previous
#include <cuda_runtime.h>
#include <math.h>
#include <stdint.h>

// Problem dims
#define Bn 1024
#define Tn 64
#define Dn 256
#define Pn 2048
#define Hn 512

#define THRESHOLD 0.3f
#define STRENGTH 0.1f
#define MIN_S 0.0f
#define MAX_S 0.5f
#define EPS_COS 1e-8f
#define EPS_LN 1e-5f

// ---------------- scratch (static device globals; no allocations) -------------
__device__ float g_centers[Pn * Dn];
__device__ float g_nc[Pn * Dn];            // normalized centers, row-major (sim B operand)
__device__ float g_nf[Bn * Dn];
__device__ float g_fcent[Bn * Dn];
__device__ float g_gmp[8][Dn];
__device__ float g_bias2[Hn];
__device__ float g_drift[Bn * Pn];
__device__ float g_flag[Pn];
__device__ float g_z1[Pn * Hn];
__device__ float g_a1[Pn * Hn];
__device__ float g_h2[Pn * (Hn / 2)];
__device__ float g_z2[Pn * Hn];
__device__ float g_a2[Pn * Hn];
__device__ float g_c2[Pn * Hn];
// n-major (transposed) weight copies
__device__ float g_w1dT[Hn * Dn];          // [512][256]
__device__ float g_calw1T[Hn * Dn];        // [512][256]
__device__ float g_ddw2T[(Hn / 2) * Hn];   // [256][512]
__device__ float g_calw2T[Hn * Hn];        // [512][512]
__device__ float g_calw3T[Dn * Hn];        // [256][512]

// ---------------- weight transpose: src [K][N] -> dst [N][K] -------------------
__global__ void __launch_bounds__(256) transpose_w_kernel(
    const float* __restrict__ dd_w1, const float* __restrict__ cal_w1,
    const float* __restrict__ dd_w2, const float* __restrict__ cal_w2,
    const float* __restrict__ cal_w3)
{
    __shared__ float s[32][33];
    int tile = blockIdx.x;
    const float* src; float* dst; int K, N;
    if (tile < 128)      { src = dd_w1;  dst = g_w1dT;   K = 256; N = 512; }
    else if (tile < 256) { src = cal_w1; dst = g_calw1T; K = 256; N = 512; tile -= 128; }
    else if (tile < 384) { src = dd_w2;  dst = g_ddw2T;  K = 512; N = 256; tile -= 256; }
    else if (tile < 640) { src = cal_w2; dst = g_calw2T; K = 512; N = 512; tile -= 384; }
    else                 { src = cal_w3; dst = g_calw3T; K = 512; N = 256; tile -= 640; }
    int ntiles = N >> 5;
    int kt = tile / ntiles, nt = tile % ntiles;
    int tx = threadIdx.x & 31, ty = threadIdx.x >> 5;
#pragma unroll
    for (int i = 0; i < 4; i++)
        s[ty + 8 * i][tx] = src[(size_t)(kt * 32 + ty + 8 * i) * N + nt * 32 + tx];
    __syncthreads();
#pragma unroll
    for (int i = 0; i < 4; i++)
        dst[(size_t)(nt * 32 + ty + 8 * i) * K + kt * 32 + tx] = s[tx][ty + 8 * i];
}

// ---------------- fused T-mean reductions, float4 loads -----------------------
__global__ void __launch_bounds__(256) reduce_centers_kernel(
    const float* __restrict__ proto, const float* __restrict__ feat)
{
    int blk = blockIdx.x;
    bool isP = blk < Pn;
    int row = isP ? blk : (blk - Pn);
    const float4* base = (const float4*)((isP ? proto : feat) + (size_t)row * Tn * Dn);

    int dq = threadIdx.x & 63;
    int tq = threadIdx.x >> 6;

    float4 a = make_float4(0.f, 0.f, 0.f, 0.f);
#pragma unroll 16
    for (int tt = tq; tt < Tn; tt += 4) {
        float4 v = base[tt * (Dn / 4) + dq];
        a.x += v.x; a.y += v.y; a.z += v.z; a.w += v.w;
    }

    __shared__ float4 sred[4][64];
    __shared__ float ss[64];
    __shared__ float s_inv;
    sred[tq][dq] = a;
    __syncthreads();

    if (tq == 0) {
        float4 b0 = sred[0][dq], b1 = sred[1][dq], b2 = sred[2][dq], b3 = sred[3][dq];
        float4 c;
        c.x = (b0.x + b1.x + b2.x + b3.x) * (1.0f / Tn);
        c.y = (b0.y + b1.y + b2.y + b3.y) * (1.0f / Tn);
        c.z = (b0.z + b1.z + b2.z + b3.z) * (1.0f / Tn);
        c.w = (b0.w + b1.w + b2.w + b3.w) * (1.0f / Tn);
        sred[0][dq] = c;
        ss[dq] = c.x * c.x + c.y * c.y + c.z * c.z + c.w * c.w;
    }
    __syncthreads();
    if (threadIdx.x < 32) {
        float s = ss[threadIdx.x] + ss[threadIdx.x + 32];
#pragma unroll
        for (int o = 16; o > 0; o >>= 1) s += __shfl_xor_sync(0xffffffffu, s, o);
        if (threadIdx.x == 0) s_inv = 1.0f / fmaxf(sqrtf(s), EPS_COS);
    }
    __syncthreads();

    if (tq == 0) {
        float4 c = sred[0][dq];
        float inv = s_inv;
        float4 cn = make_float4(c.x * inv, c.y * inv, c.z * inv, c.w * inv);
        if (isP) {
            ((float4*)g_centers)[row * (Dn / 4) + dq] = c;
            ((float4*)g_nc)[row * (Dn / 4) + dq] = cn;
        } else {
            ((float4*)g_fcent)[row * (Dn / 4) + dq] = c;
            ((float4*)g_nf)[row * (Dn / 4) + dq] = cn;
        }
    }
}

// partial global_mean over B: 8 blocks, each sums 128 rows
__global__ void __launch_bounds__(Dn) gm_partial_kernel() {
    int i = blockIdx.x;
    int d = threadIdx.x;
    float s = 0.f;
    int b0 = i * (Bn / 8);
#pragma unroll 8
    for (int b = 0; b < Bn / 8; b++) s += g_fcent[(b0 + b) * Dn + d];
    g_gmp[i][d] = s;
}

// bias2[h] = dd_b1[h] + sum_d gm[d] * dd_w1[D + d][h]
__global__ void __launch_bounds__(512) bias2_kernel(const float* __restrict__ dd_w1,
                                                    const float* __restrict__ dd_b1) {
    int hx = threadIdx.x & 63;
    int dg = threadIdx.x >> 6;
    int h = blockIdx.x * 64 + hx;
    float s = 0.f;
#pragma unroll 8
    for (int j = 0; j < 32; j++) {
        int d = dg * 32 + j;
        float gm = 0.f;
#pragma unroll
        for (int q = 0; q < 8; q++) gm += g_gmp[q][d];
        gm *= (1.0f / Bn);
        s += gm * dd_w1[(size_t)(Dn + d) * Hn + h];
    }
    __shared__ float red[8][64];
    red[dg][hx] = s;
    __syncthreads();
    if (dg == 0) {
        float t = 0.f;
#pragma unroll
        for (int q = 0; q < 8; q++) t += red[q][hx];
        g_bias2[h] = dd_b1[h] + t;
    }
}

// ---------------- mma / copy helpers ------------------------------------------
__device__ __forceinline__ void mma_tf32(float* c,
                                         uint32_t a0, uint32_t a1, uint32_t a2, uint32_t a3,
                                         uint32_t b0, uint32_t b1) {
    asm volatile(
        "mma.sync.aligned.m16n8k8.row.col.f32.tf32.tf32.f32 "
        "{%0,%1,%2,%3}, {%4,%5,%6,%7}, {%8,%9}, {%0,%1,%2,%3};\n"
        : "+f"(c[0]), "+f"(c[1]), "+f"(c[2]), "+f"(c[3])
        : "r"(a0), "r"(a1), "r"(a2), "r"(a3), "r"(b0), "r"(b1));
}

__device__ __forceinline__ void ldsm4(uint32_t& r0, uint32_t& r1, uint32_t& r2, uint32_t& r3,
                                      uint32_t addr) {
    asm volatile("ldmatrix.sync.aligned.m8n8.x4.shared.b16 {%0,%1,%2,%3}, [%4];"
                 : "=r"(r0), "=r"(r1), "=r"(r2), "=r"(r3) : "r"(addr));
}

__device__ __forceinline__ void cp16(void* smem, const void* gmem) {
    uint32_t sa = (uint32_t)__cvta_generic_to_shared(smem);
    asm volatile("cp.async.cg.shared.global [%0], [%1], 16;\n" :: "r"(sa), "l"(gmem));
}
__device__ __forceinline__ void cp_commit() {
    asm volatile("cp.async.commit_group;\n");
}
__device__ __forceinline__ void cp_wait0() {
    asm volatile("cp.async.wait_group 0;\n");
}
__device__ __forceinline__ void cp_wait1() {
    asm volatile("cp.async.wait_group 1;\n");
}

// flat-grouped GEMM descriptor (W operands are n-major [N][K], row stride = K)
struct GB {
    const float* A[3];
    const float* W[3];
    const float* bias[3];
    float*       C[3];
    int          ldc[3];
    int          act[3];    // 0=bias, 1=relu(bias), 2=(1-acc) no bias
    int          nx[3];
    int          start1, start2;
};

// ---- flat-grouped cp.async double-buffered tf32 GEMM, BK=32,
//      ldmatrix for BOTH A (row-major) and B (n-major) fragments.
template<int BM, int BN, int WM, int WN, int NT>
__global__ void __launch_bounds__(NT) gemm_fg(GB gb, int K)
{
    constexpr int BK = 32;
    constexpr int PAD = 4;                 // stride 36 floats = 144B: 16B-aligned, bank-free
    constexpr int WTM = BM / WM;
    constexpr int WTN = BN / WN;
    constexpr int MI = WTM / 16;
    constexpr int NI = WTN / 8;

    __shared__ __align__(16) float As[2][BM][BK + PAD];
    __shared__ __align__(16) float Bs[2][BN][BK + PAD];   // n-major!

    const int bx = blockIdx.x;
    const int z = (bx >= gb.start1) + (bx >= gb.start2);
    const int local = bx - (z == 0 ? 0 : (z == 1 ? gb.start1 : gb.start2));
    const int nx = gb.nx[z];
    const int m0 = (local / nx) * BM;
    const int n0 = (local % nx) * BN;
    const int ldc = gb.ldc[z];
    const int act = gb.act[z];

    const int t = threadIdx.x;
    const int warp = t >> 5;
    const int lane = t & 31;
    const int g  = lane >> 2;
    const int tg = lane & 3;
    const int wm = warp / WN;
    const int wn = warp % WN;

    const float* Abase = gb.A[z] + (size_t)m0 * K;
    const float* Wbase = gb.W[z] + (size_t)n0 * K;   // n-major rows

    constexpr int CA = (BM * BK / 4) / NT;
    constexpr int CB = (BN * BK / 4) / NT;
    const int KB = K / BK;

    auto issue = [&](int st, int kb) {
#pragma unroll
        for (int i = 0; i < CA; i++) {
            int c = t + i * NT;
            int row = c >> 3;              // 8 chunks per 32-float row
            int col = (c & 7) << 2;
            cp16(&As[st][row][col], Abase + (size_t)row * K + kb * BK + col);
        }
#pragma unroll
        for (int i = 0; i < CB; i++) {
            int c = t + i * NT;
            int row = c >> 3;
            int col = (c & 7) << 2;
            cp16(&Bs[st][row][col], Wbase + (size_t)row * K + kb * BK + col);
        }
    };

    // ldmatrix base addresses
    uint32_t aAddr[2], bAddr[2];
#pragma unroll
    for (int st = 0; st < 2; st++) {
        aAddr[st] = (uint32_t)__cvta_generic_to_shared(
            &As[st][wm * WTM + (lane & 15)][(lane >> 4) << 2]);
        bAddr[st] = (uint32_t)__cvta_generic_to_shared(
            &Bs[st][wn * WTN + ((lane >> 4) << 3) + (lane & 7)][((lane >> 3) & 1) << 2]);
    }

    float acc[MI][NI][4];
#pragma unroll
    for (int mi = 0; mi < MI; mi++)
#pragma unroll
        for (int ni = 0; ni < NI; ni++)
#pragma unroll
            for (int q = 0; q < 4; q++) acc[mi][ni][q] = 0.f;

    issue(0, 0); cp_commit();

    for (int kb = 0; kb < KB; kb++) {
        if (kb + 1 < KB) {
            issue((kb + 1) & 1, kb + 1);
            cp_commit();
            cp_wait1();
        } else {
            cp_wait0();
        }
        __syncthreads();

        int cs = kb & 1;
#pragma unroll
        for (int ks = 0; ks < BK; ks += 8) {
            uint32_t af[MI][4], bf[NI][2];
#pragma unroll
            for (int mi = 0; mi < MI; mi++)
                ldsm4(af[mi][0], af[mi][1], af[mi][2], af[mi][3],
                      aAddr[cs] + (uint32_t)((mi * 16 * (BK + PAD) + ks) * 4));
#pragma unroll
            for (int n2 = 0; n2 < NI / 2; n2++) {
                uint32_t r0, r1, r2, r3;
                ldsm4(r0, r1, r2, r3,
                      bAddr[cs] + (uint32_t)((n2 * 16 * (BK + PAD) + ks) * 4));
                bf[n2 * 2][0] = r0; bf[n2 * 2][1] = r1;
                bf[n2 * 2 + 1][0] = r2; bf[n2 * 2 + 1][1] = r3;
            }
#pragma unroll
            for (int mi = 0; mi < MI; mi++)
#pragma unroll
                for (int ni = 0; ni < NI; ni++)
                    mma_tf32(acc[mi][ni],
                             af[mi][0], af[mi][1], af[mi][2], af[mi][3],
                             bf[ni][0], bf[ni][1]);
        }
        __syncthreads();
    }

    const float* bias = gb.bias[z];
    float* C = gb.C[z];

#pragma unroll
    for (int mi = 0; mi < MI; mi++) {
#pragma unroll
        for (int ni = 0; ni < NI; ni++) {
            int m = m0 + wm * WTM + mi * 16 + g;
            int n = n0 + wn * WTN + ni * 8 + tg * 2;
            float2 v0, v1;
            if (act == 2) {
                v0.x = 1.0f - acc[mi][ni][0]; v0.y = 1.0f - acc[mi][ni][1];
                v1.x = 1.0f - acc[mi][ni][2]; v1.y = 1.0f - acc[mi][ni][3];
            } else {
                float b0 = bias[n], b1 = bias[n + 1];
                v0.x = acc[mi][ni][0] + b0;   v0.y = acc[mi][ni][1] + b1;
                v1.x = acc[mi][ni][2] + b0;   v1.y = acc[mi][ni][3] + b1;
                if (act == 1) {
                    v0.x = fmaxf(v0.x, 0.f); v0.y = fmaxf(v0.y, 0.f);
                    v1.x = fmaxf(v1.x, 0.f); v1.y = fmaxf(v1.y, 0.f);
                }
            }
            *(float2*)&C[(size_t)m * ldc + n]       = v0;
            *(float2*)&C[(size_t)(m + 8) * ldc + n] = v1;
        }
    }
}

// ---- final GEMM + fused scatter:
// newc(tile) = centers + clip(STRENGTH*conf)*(c2 @ cal_w3 + b3)  (conf inline),
// then write calibrated[p][t][d0..d0+63] for all t (newc if flagged else proto).
// BM=32, BN=64, WM=2, WN=2, NT=128 -> grid (Dn/64, Pn/32) = 256 blocks.
__global__ void __launch_bounds__(128) gemm_final_scatter(
    const float* __restrict__ A,        // c2 [P][512]
    const float* __restrict__ Wn,       // calw3T [256][512] n-major
    const float* __restrict__ bias,     // cal_b3 [256]
    const float* __restrict__ h2, const float* __restrict__ w3,
    const float* __restrict__ b3, const float* __restrict__ centers,
    const float* __restrict__ proto, float* __restrict__ outp)
{
    constexpr int BM = 32, BN = 64, BK = 32, PAD = 4, NT = 128;
    constexpr int WTM = 16, WTN = 32;
    constexpr int MI = 1, NI = 4;
    const int K = Hn, N = Dn;

    __shared__ __align__(16) float As[2][BM][BK + PAD];
    __shared__ __align__(16) float Bs[2][BN][BK + PAD];
    __shared__ __align__(16) float newcs[BM][BN + 4];
    __shared__ float cred[BM][4];
    __shared__ float conf_s[BM];
    __shared__ float flags[BM];

    const int t = threadIdx.x;
    const int warp = t >> 5;
    const int lane = t & 31;
    const int g  = lane >> 2;
    const int tg = lane & 3;
    const int wm = warp >> 1;
    const int wn = warp & 1;

    const int m0 = blockIdx.y * BM;
    const int n0 = blockIdx.x * BN;

    const float* Abase = A + (size_t)m0 * K;
    const float* Wbase = Wn + (size_t)n0 * K;

    constexpr int CA = (BM * BK / 4) / NT;   // 2
    constexpr int CB = (BN * BK / 4) / NT;   // 4
    const int KB = K / BK;                    // 16

    auto issue = [&](int st, int kb) {
#pragma unroll
        for (int i = 0; i < CA; i++) {
            int c = t + i * NT;
            int row = c >> 3;
            int col = (c & 7) << 2;
            cp16(&As[st][row][col], Abase + (size_t)row * K + kb * BK + col);
        }
#pragma unroll
        for (int i = 0; i < CB; i++) {
            int c = t + i * NT;
            int row = c >> 3;
            int col = (c & 7) << 2;
            cp16(&Bs[st][row][col], Wbase + (size_t)row * K + kb * BK + col);
        }
    };

    uint32_t aAddr[2], bAddr[2];
#pragma unroll
    for (int st = 0; st < 2; st++) {
        aAddr[st] = (uint32_t)__cvta_generic_to_shared(
            &As[st][wm * WTM + (lane & 15)][(lane >> 4) << 2]);
        bAddr[st] = (uint32_t)__cvta_generic_to_shared(
            &Bs[st][wn * WTN + ((lane >> 4) << 3) + (lane & 7)][((lane >> 3) & 1) << 2]);
    }

    float acc[MI][NI][4];
#pragma unroll
    for (int mi = 0; mi < MI; mi++)
#pragma unroll
        for (int ni = 0; ni < NI; ni++)
#pragma unroll
            for (int q = 0; q < 4; q++) acc[mi][ni][q] = 0.f;

    issue(0, 0); cp_commit();

    // inline conf: 4 threads per row, 64 h2-cols each (Hn/2 = 256)
    {
        int r = t >> 2;
        int q = t & 3;
        const float* hrow = h2 + (size_t)(m0 + r) * (Hn / 2) + q * 64;
        const float* wrow = w3 + q * 64;
        float s = 0.f;
#pragma unroll 16
        for (int j = 0; j < 64; j++) s += hrow[j] * wrow[j];
        cred[r][q] = s;
    }
    if (t < BM) flags[t] = g_flag[m0 + t];
    __syncthreads();
    if (t < BM) {
        float x = cred[t][0] + cred[t][1] + cred[t][2] + cred[t][3] + b3[0];
        conf_s[t] = 1.0f / (1.0f + expf(-x));
    }

    for (int kb = 0; kb < KB; kb++) {
        if (kb + 1 < KB) {
            issue((kb + 1) & 1, kb + 1);
            cp_commit();
            cp_wait1();
        } else {
            cp_wait0();
        }
        __syncthreads();

        int cs = kb & 1;
#pragma unroll
        for (int ks = 0; ks < BK; ks += 8) {
            uint32_t af[MI][4], bf[NI][2];
#pragma unroll
            for (int mi = 0; mi < MI; mi++)
                ldsm4(af[mi][0], af[mi][1], af[mi][2], af[mi][3],
                      aAddr[cs] + (uint32_t)((mi * 16 * (BK + PAD) + ks) * 4));
#pragma unroll
            for (int n2 = 0; n2 < NI / 2; n2++) {
                uint32_t r0, r1, r2, r3;
                ldsm4(r0, r1, r2, r3,
                      bAddr[cs] + (uint32_t)((n2 * 16 * (BK + PAD) + ks) * 4));
                bf[n2 * 2][0] = r0; bf[n2 * 2][1] = r1;
                bf[n2 * 2 + 1][0] = r2; bf[n2 * 2 + 1][1] = r3;
            }
#pragma unroll
            for (int mi = 0; mi < MI; mi++)
#pragma unroll
                for (int ni = 0; ni < NI; ni++)
                    mma_tf32(acc[mi][ni],
                             af[mi][0], af[mi][1], af[mi][2], af[mi][3],
                             bf[ni][0], bf[ni][1]);
        }
        __syncthreads();
    }

    // epilogue: newc values into smem tile
#pragma unroll
    for (int ni = 0; ni < NI; ni++) {
        int lm = wm * WTM + g;
        int ln = wn * WTN + ni * 8 + tg * 2;
        int m = m0 + lm;
        int n = n0 + ln;
        float b0 = bias[n], b1 = bias[n + 1];
        float s0 = fminf(fmaxf(STRENGTH * conf_s[lm], MIN_S), MAX_S);
        float s1 = fminf(fmaxf(STRENGTH * conf_s[lm + 8], MIN_S), MAX_S);
        newcs[lm][ln]         = centers[(size_t)m * N + n]           + s0 * (acc[0][ni][0] + b0);
        newcs[lm][ln + 1]     = centers[(size_t)m * N + n + 1]       + s0 * (acc[0][ni][1] + b1);
        newcs[lm + 8][ln]     = centers[(size_t)(m + 8) * N + n]     + s1 * (acc[0][ni][2] + b0);
        newcs[lm + 8][ln + 1] = centers[(size_t)(m + 8) * N + n + 1] + s1 * (acc[0][ni][3] + b1);
    }
    __syncthreads();

    // scatter: 32 p x 64 t x 16 float4 = 32768 float4 per block
    const float4* proto4 = (const float4*)proto;
    float4* out4 = (float4*)outp;
    int d4base = n0 >> 2;
#pragma unroll 4
    for (int i = 0; i < 256; i++) {
        int idx = t + i * 128;
        int d4 = idx & 15;
        int tt = (idx >> 4) & 63;
        int pr = idx >> 10;
        size_t f4 = ((size_t)(m0 + pr) * 64 + tt) * 64 + d4base + d4;
        float4 v;
        if (flags[pr] > 0.5f) {
            v = *(const float4*)&newcs[pr][d4 << 2];
        } else {
            v = proto4[f4];
        }
        out4[f4] = v;
    }
}

// merged: blocks [0, 2Pn) -> layernorm+relu rows; [2Pn, 2Pn+64) -> colmean
__global__ void __launch_bounds__(256) ln_cm_kernel(
    const float* __restrict__ z1, const float* __restrict__ g1, const float* __restrict__ be1,
    float* __restrict__ o1,
    const float* __restrict__ z2, const float* __restrict__ g2, const float* __restrict__ be2,
    float* __restrict__ o2,
    const float* __restrict__ drift, float* __restrict__ out_flag)
{
    int blk = blockIdx.x;
    if (blk >= 2 * Pn) {
        int cb = blk - 2 * Pn;
        int tx = threadIdx.x & 31;
        int ty = threadIdx.x >> 5;
        int p = cb * 32 + tx;
        float s = 0.f;
#pragma unroll 8
        for (int b = ty; b < Bn; b += 8)
            s += drift[(size_t)b * Pn + p];
        __shared__ float redc[8][33];
        redc[ty][tx] = s;
        __syncthreads();
        if (ty == 0) {
            float t = redc[0][tx];
#pragma unroll
            for (int q = 1; q < 8; q++) t += redc[q][tx];
            float fl = (t * (1.0f / Bn) > THRESHOLD) ? 1.0f : 0.0f;
            g_flag[p] = fl;
            if (out_flag) out_flag[p] = fl;
        }
        return;
    }

    bool first = blk < Pn;
    int r = first ? blk : blk - Pn;
    const float* z  = first ? z1 : z2;
    const float* g  = first ? g1 : g2;
    const float* be = first ? be1 : be2;
    float* out = first ? o1 : o2;

    int d = threadIdx.x;
    const float* row = z + (size_t)r * Hn;
    float v0 = row[d], v1 = row[d + 256];

    __shared__ float red[256];
    red[d] = v0 + v1;
    __syncthreads();
    for (int o = 128; o > 0; o >>= 1) {
        if (d < o) red[d] += red[d + o];
        __syncthreads();
    }
    float mu = red[0] * (1.0f / Hn);
    __syncthreads();

    float d0 = v0 - mu, d1 = v1 - mu;
    red[d] = d0 * d0 + d1 * d1;
    __syncthreads();
    for (int o = 128; o > 0; o >>= 1) {
        if (d < o) red[d] += red[d + o];
        __syncthreads();
    }
    float var = red[0] * (1.0f / Hn);
    float rs = rsqrtf(var + EPS_LN);

    float* orow = out + (size_t)r * Hn;
    orow[d]       = fmaxf(d0 * rs * g[d] + be[d], 0.f);
    orow[d + 256] = fmaxf(d1 * rs * g[d + 256] + be[d + 256], 0.f);
}

// ---------------- launch ------------------------------------------------------
extern "C" void kernel_launch(void* const* d_in, const int* in_sizes, int n_in,
                              void* d_out, int out_size) {
    (void)in_sizes; (void)n_in;
    const float* feat   = (const float*)d_in[0];
    const float* proto  = (const float*)d_in[1];
    const float* dd_w1  = (const float*)d_in[2];
    const float* dd_b1  = (const float*)d_in[3];
    const float* dd_g1  = (const float*)d_in[4];
    const float* dd_be1 = (const float*)d_in[5];
    const float* dd_w2  = (const float*)d_in[6];
    const float* dd_b2  = (const float*)d_in[7];
    const float* dd_w3  = (const float*)d_in[8];
    const float* dd_b3  = (const float*)d_in[9];
    const float* cal_w1 = (const float*)d_in[10];
    const float* cal_b1 = (const float*)d_in[11];
    const float* cal_g1 = (const float*)d_in[12];
    const float* cal_be1= (const float*)d_in[13];
    const float* cal_w2 = (const float*)d_in[14];
    const float* cal_b2 = (const float*)d_in[15];
    const float* cal_w3 = (const float*)d_in[16];
    const float* cal_b3 = (const float*)d_in[17];

    float* out = (float*)d_out;
    const long long PTD = (long long)Pn * Tn * Dn;
    const long long BP  = (long long)Bn * Pn;

    bool has_drift = (long long)out_size >= PTD + BP;
    bool has_flag  = (long long)out_size >= PTD + BP + Pn;

    float* drift_ptr = nullptr;
    if (has_drift) {
        drift_ptr = out + PTD;
    } else {
        cudaGetSymbolAddress((void**)&drift_ptr, g_drift);
    }
    float* flag_ptr = has_flag ? (out + PTD + BP) : nullptr;

    float *p_centers, *p_nc, *p_nf, *p_bias2, *p_z1, *p_a1, *p_h2,
          *p_z2, *p_a2, *p_c2, *p_w1dT, *p_calw1T, *p_ddw2T, *p_calw2T, *p_calw3T;
    cudaGetSymbolAddress((void**)&p_centers, g_centers);
    cudaGetSymbolAddress((void**)&p_nc,      g_nc);
    cudaGetSymbolAddress((void**)&p_nf,      g_nf);
    cudaGetSymbolAddress((void**)&p_bias2,   g_bias2);
    cudaGetSymbolAddress((void**)&p_z1,      g_z1);
    cudaGetSymbolAddress((void**)&p_a1,      g_a1);
    cudaGetSymbolAddress((void**)&p_h2,      g_h2);
    cudaGetSymbolAddress((void**)&p_z2,      g_z2);
    cudaGetSymbolAddress((void**)&p_a2,      g_a2);
    cudaGetSymbolAddress((void**)&p_c2,      g_c2);
    cudaGetSymbolAddress((void**)&p_w1dT,    g_w1dT);
    cudaGetSymbolAddress((void**)&p_calw1T,  g_calw1T);
    cudaGetSymbolAddress((void**)&p_ddw2T,   g_ddw2T);
    cudaGetSymbolAddress((void**)&p_calw2T,  g_calw2T);
    cudaGetSymbolAddress((void**)&p_calw3T,  g_calw3T);

    // 0: weight transposes (independent)
    transpose_w_kernel<<<768, 256>>>(dd_w1, cal_w1, dd_w2, cal_w2, cal_w3);
    // 1: fused T-mean reductions
    reduce_centers_kernel<<<Pn + Bn, 256>>>(proto, feat);
    // 2-3: partial global mean, fold gm @ dd_w1[D:2D] into bias2
    gm_partial_kernel<<<8, Dn>>>();
    bias2_kernel<<<8, 512>>>(dd_w1, dd_b1);

    // 4: MEGA phase 1 — sim GEMM + both layer-1 GEMMs (all K=256), 512 blocks
    {
        GB gb = {};
        gb.A[0] = p_nf;      gb.W[0] = p_nc;      gb.bias[0] = nullptr;
        gb.C[0] = drift_ptr; gb.ldc[0] = Pn;      gb.act[0] = 2; gb.nx[0] = Pn / 128;
        gb.A[1] = p_centers; gb.W[1] = p_w1dT;    gb.bias[1] = p_bias2;
        gb.C[1] = p_z1;      gb.ldc[1] = Hn;      gb.act[1] = 0; gb.nx[1] = Hn / 128;
        gb.A[2] = p_centers; gb.W[2] = p_calw1T;  gb.bias[2] = cal_b1;
        gb.C[2] = p_z2;      gb.ldc[2] = Hn;      gb.act[2] = 0; gb.nx[2] = Hn / 128;
        gb.start1 = 256; gb.start2 = 384;
        gemm_fg<64, 128, 1, 4, 128><<<512, 128>>>(gb, Dn);
    }

    // 5: merged layernorm+relu (z1->a1, z2->a2) + colmean -> flag
    ln_cm_kernel<<<2 * Pn + Pn / 32, 256>>>(p_z1, dd_g1, dd_be1, p_a1,
                                            p_z2, cal_g1, cal_be1, p_a2,
                                            drift_ptr, flag_ptr);

    // 6: MEGA phase 2 — dd layer-2 + cal layer-2 (two 256-col halves), K=512
    {
        GB gb = {};
        gb.A[0] = p_a1; gb.W[0] = p_ddw2T;              gb.bias[0] = dd_b2;
        gb.C[0] = p_h2;       gb.ldc[0] = Hn / 2; gb.act[0] = 1; gb.nx[0] = 2;
        gb.A[1] = p_a2; gb.W[1] = p_calw2T;             gb.bias[1] = cal_b2;
        gb.C[1] = p_c2;       gb.ldc[1] = Hn;     gb.act[1] = 1; gb.nx[1] = 2;
        gb.A[2] = p_a2; gb.W[2] = p_calw2T + 256 * Hn;  gb.bias[2] = cal_b2 + 256;
        gb.C[2] = p_c2 + 256; gb.ldc[2] = Hn;     gb.act[2] = 1; gb.nx[2] = 2;
        gb.start1 = 64; gb.start2 = 128;
        gemm_fg<64, 128, 1, 4, 128><<<192, 128>>>(gb, Hn);
    }

    // 7: final GEMM + inline conf + fused new_center + scatter
    gemm_final_scatter<<<dim3(Dn / 64, Pn / 32), 128>>>(
        p_c2, p_calw3T, cal_b3, p_h2, dd_w3, dd_b3, p_centers, proto, out);
}